// round 1
// baseline (speedup 1.0000x reference)
#include <cuda_runtime.h>
#include <math.h>

// ---------------- problem constants ----------------
#define BB   8
#define NN   2049
#define CC   768
#define HH   12
#define NBB  4
#define HD   64
#define SPB  512
#define MROWS (BB*NN)      // 16392
#define SCALE 0.125f
#define LNEPS 1e-6f

// ---------------- scratch (static device globals; no runtime alloc) -------------
__device__ float g_h1 [(size_t)MROWS * CC];        // LN1 output
__device__ float g_qkv[(size_t)MROWS * 3 * CC];    // qkv of h1
__device__ float g_qkvc[BB * 3 * CC];              // qkv of cls token
__device__ float g_y  [(size_t)MROWS * CC];        // attention output (pre-proj)
__device__ float g_x2 [(size_t)MROWS * CC];        // x + attn
__device__ float g_h2 [(size_t)MROWS * CC];        // LN2 output
__device__ float g_fc1[(size_t)MROWS * 4 * CC];    // gelu(fc1) output

// ---------------- LayerNorm: one block per row, 256 threads ----------------
__global__ void __launch_bounds__(256) ln_kernel(const float* __restrict__ x,
                                                 const float* __restrict__ w,
                                                 const float* __restrict__ b,
                                                 float* __restrict__ out)
{
    __shared__ float red[256];
    int row = blockIdx.x;
    int tid = threadIdx.x;
    const float* xr = x + (size_t)row * CC;

    float v0 = xr[tid], v1 = xr[tid + 256], v2 = xr[tid + 512];
    float s = v0 + v1 + v2;
    red[tid] = s; __syncthreads();
    for (int off = 128; off; off >>= 1) {
        if (tid < off) red[tid] += red[tid + off];
        __syncthreads();
    }
    float mu = red[0] * (1.0f / CC);
    __syncthreads();

    float d0 = v0 - mu, d1 = v1 - mu, d2 = v2 - mu;
    red[tid] = d0*d0 + d1*d1 + d2*d2; __syncthreads();
    for (int off = 128; off; off >>= 1) {
        if (tid < off) red[tid] += red[tid + off];
        __syncthreads();
    }
    float var = red[0] * (1.0f / CC);
    float rs = rsqrtf(var + LNEPS);

    float* orow = out + (size_t)row * CC;
    orow[tid      ] = d0 * rs * w[tid      ] + b[tid      ];
    orow[tid + 256] = d1 * rs * w[tid + 256] + b[tid + 256];
    orow[tid + 512] = d2 * rs * w[tid + 512] + b[tid + 512];
}

// ---------------- SGEMM: C[m][n] = sum_k A[m][k]*W[n][k] (+epilogue) -------------
// BM=BN=128, BK=8, 256 threads, 8x8 per thread.
// EPI: 0 = none, 1 = bias + residual, 2 = bias + exact gelu
template <int EPI>
__global__ void __launch_bounds__(256) sgemm_nt(const float* __restrict__ A,
                                                const float* __restrict__ W,
                                                const float* __restrict__ bias,
                                                const float* __restrict__ res,
                                                float* __restrict__ C,
                                                int M, int N, int K)
{
    __shared__ float As[8][128];
    __shared__ float Bs[8][128];

    int tid = threadIdx.x;
    int tx = tid & 15;      // 0..15 (n)
    int ty = tid >> 4;      // 0..15 (m)
    int bm = blockIdx.y * 128;
    int bn = blockIdx.x * 128;

    int lr = tid >> 1;            // 0..127 row within tile
    int lk = (tid & 1) * 4;       // 0 or 4

    const float* Aptr = A + (size_t)(bm + lr) * K + lk;
    const float* Wptr = W + (size_t)(bn + lr) * K + lk;
    bool arow_ok = (bm + lr) < M;

    float acc[8][8];
    #pragma unroll
    for (int i = 0; i < 8; i++)
        #pragma unroll
        for (int j = 0; j < 8; j++) acc[i][j] = 0.0f;

    for (int k0 = 0; k0 < K; k0 += 8) {
        float4 av = arow_ok ? *(const float4*)(Aptr + k0) : make_float4(0.f,0.f,0.f,0.f);
        float4 wv = *(const float4*)(Wptr + k0);
        As[lk+0][lr] = av.x; As[lk+1][lr] = av.y; As[lk+2][lr] = av.z; As[lk+3][lr] = av.w;
        Bs[lk+0][lr] = wv.x; Bs[lk+1][lr] = wv.y; Bs[lk+2][lr] = wv.z; Bs[lk+3][lr] = wv.w;
        __syncthreads();

        #pragma unroll
        for (int kk = 0; kk < 8; kk++) {
            float4 a0 = *(const float4*)&As[kk][ty*4];
            float4 a1 = *(const float4*)&As[kk][64 + ty*4];
            float4 b0 = *(const float4*)&Bs[kk][tx*4];
            float4 b1 = *(const float4*)&Bs[kk][64 + tx*4];
            float a[8] = {a0.x,a0.y,a0.z,a0.w,a1.x,a1.y,a1.z,a1.w};
            float bb[8] = {b0.x,b0.y,b0.z,b0.w,b1.x,b1.y,b1.z,b1.w};
            #pragma unroll
            for (int i = 0; i < 8; i++)
                #pragma unroll
                for (int j = 0; j < 8; j++)
                    acc[i][j] = fmaf(a[i], bb[j], acc[i][j]);
        }
        __syncthreads();
    }

    #pragma unroll
    for (int i = 0; i < 8; i++) {
        int mrow = bm + ((i < 4) ? (ty*4 + i) : (64 + ty*4 + i - 4));
        if (mrow >= M) continue;
        #pragma unroll
        for (int j = 0; j < 8; j++) {
            int ncol = bn + ((j < 4) ? (tx*4 + j) : (64 + tx*4 + j - 4));
            float v = acc[i][j];
            if (EPI != 0) v += bias[ncol];
            if (EPI == 1) v += res[(size_t)mrow * N + ncol];
            if (EPI == 2) v = 0.5f * v * (1.0f + erff(v * 0.7071067811865476f));
            C[(size_t)mrow * N + ncol] = v;
        }
    }
}

// ---------------- cls global attention: 1 block per (b,h) ----------------
// out cls[b][h*64+d] = softmax(q0 . K / sqrt(d)) @ V  + h1[b,0,h*64+d]  -> g_y row 0
__global__ void __launch_bounds__(256) cls_attn_kernel(const float* __restrict__ qkv,
                                                       const float* __restrict__ h1,
                                                       float* __restrict__ y)
{
    __shared__ float sq[64];
    __shared__ float sc[NN];
    __shared__ float red[256];
    __shared__ float so[4][64];

    int bh = blockIdx.x;
    int b = bh / HH, h = bh % HH;
    int tid = threadIdx.x;

    const float* qbase = qkv + (size_t)(b * NN) * (3*CC) + h * HD;
    if (tid < 64) sq[tid] = qbase[tid];
    __syncthreads();

    float lmax = -1e30f;
    for (int i = tid; i < NN; i += 256) {
        const float* kr = qkv + (size_t)(b * NN + i) * (3*CC) + CC + h * HD;
        float s = 0.0f;
        #pragma unroll 16
        for (int d = 0; d < 64; d++) s = fmaf(sq[d], kr[d], s);
        s *= SCALE;
        sc[i] = s;
        lmax = fmaxf(lmax, s);
    }
    red[tid] = lmax; __syncthreads();
    for (int off = 128; off; off >>= 1) {
        if (tid < off) red[tid] = fmaxf(red[tid], red[tid + off]);
        __syncthreads();
    }
    float m = red[0];
    __syncthreads();

    float lsum = 0.0f;
    for (int i = tid; i < NN; i += 256) {
        float e = expf(sc[i] - m);
        sc[i] = e;
        lsum += e;
    }
    red[tid] = lsum; __syncthreads();
    for (int off = 128; off; off >>= 1) {
        if (tid < off) red[tid] += red[tid + off];
        __syncthreads();
    }
    float l = red[0];
    __syncthreads();

    int d = tid & 63, part = tid >> 6;   // 4 parts
    float o = 0.0f;
    for (int i = part; i < NN; i += 4)
        o = fmaf(sc[i], qkv[(size_t)(b * NN + i) * (3*CC) + 2*CC + h * HD + d], o);
    so[part][d] = o;
    __syncthreads();

    if (tid < 64) {
        float val = (so[0][tid] + so[1][tid] + so[2][tid] + so[3][tid]) / l;
        size_t off0 = (size_t)(b * NN) * CC + h * HD + tid;
        y[off0] = val + h1[off0];
    }
}

// ---------------- cls qkv: qkvc[b][j] = cls[b] . qkv_w[j] (warp per output) ------
__global__ void __launch_bounds__(256) cls_qkv_kernel(const float* __restrict__ y,
                                                      const float* __restrict__ qkv_w,
                                                      float* __restrict__ qkvc)
{
    int j = blockIdx.x;                 // 0..2303
    int w = threadIdx.x >> 5;           // warp = batch b (0..7)
    int lane = threadIdx.x & 31;
    const float* cls = y + (size_t)w * NN * CC;   // row 0 of batch w
    const float* wr = qkv_w + (size_t)j * CC;
    float s = 0.0f;
    for (int k = lane; k < CC; k += 32) s = fmaf(cls[k], wr[k], s);
    #pragma unroll
    for (int off = 16; off; off >>= 1) s += __shfl_xor_sync(0xffffffffu, s, off);
    if (lane == 0) qkvc[w * (3*CC) + j] = s;
}

// ---------------- branch attention ----------------
// grid (qtile=8, nb=4, b*H=96), 256 threads. 64 queries x 513 keys x 64 dim.
// Flash-style online softmax, register-resident stats, shared-tiled GEMMs.
#define AS 68   // padded stride (floats) for 64-wide shared rows

__global__ void __launch_bounds__(256) branch_attn_kernel(const float* __restrict__ qkv,
                                                          const float* __restrict__ qkvc,
                                                          float* __restrict__ y)
{
    extern __shared__ float smem[];
    float* Qs = smem;             // [d][q]  64 x AS
    float* Ks = Qs + 64 * AS;     // [d][key]
    float* Vs = Ks + 64 * AS;     // [key][d]
    float* Ps = Vs + 64 * AS;     // [key][q]

    int tid = threadIdx.x;
    int tx = tid & 15;   // key / dim frag
    int ty = tid >> 4;   // query frag
    int qt = blockIdx.x;             // 0..7
    int nb = blockIdx.y;             // 0..3
    int b = blockIdx.z / HH, h = blockIdx.z % HH;

    // ---- load Q tile, transposed to [d][q] ----
    {
        int q  = tid >> 2;           // 0..63
        int dg = (tid & 3) * 16;     // 0,16,32,48
        int token = 1 + nb * SPB + qt * 64 + q;
        const float* src = qkv + (size_t)(b * NN + token) * (3*CC) + h * HD + dg;
        #pragma unroll
        for (int ii = 0; ii < 4; ii++) {
            float4 v = *(const float4*)(src + ii * 4);
            int d = dg + ii * 4;
            Qs[(d+0)*AS + q] = v.x; Qs[(d+1)*AS + q] = v.y;
            Qs[(d+2)*AS + q] = v.z; Qs[(d+3)*AS + q] = v.w;
        }
    }

    float m[4], l[4], o[4][4];
    #pragma unroll
    for (int i = 0; i < 4; i++) {
        m[i] = -1e30f; l[i] = 0.0f;
        #pragma unroll
        for (int j = 0; j < 4; j++) o[i][j] = 0.0f;
    }

    for (int kt = 0; kt < 9; kt++) {     // 9 key tiles of 64 -> 513 keys
        // ---- load K (transposed) and V (natural) tiles ----
        {
            int key = tid >> 2;
            int dg  = (tid & 3) * 16;
            int jg  = kt * 64 + key;
            bool valid = jg < (SPB + 1);
            const float *ksrc = nullptr, *vsrc = nullptr;
            if (valid) {
                if (jg == 0) {
                    ksrc = qkvc + b * (3*CC) + CC   + h * HD + dg;
                    vsrc = qkvc + b * (3*CC) + 2*CC + h * HD + dg;
                } else {
                    int token = nb * SPB + jg;    // = 1 + nb*SPB + (jg-1)
                    size_t roff = (size_t)(b * NN + token) * (3*CC) + h * HD + dg;
                    ksrc = qkv + roff + CC;
                    vsrc = qkv + roff + 2*CC;
                }
            }
            #pragma unroll
            for (int ii = 0; ii < 4; ii++) {
                float4 kv = valid ? *(const float4*)(ksrc + ii*4) : make_float4(0.f,0.f,0.f,0.f);
                float4 vv = valid ? *(const float4*)(vsrc + ii*4) : make_float4(0.f,0.f,0.f,0.f);
                int d = dg + ii * 4;
                Ks[(d+0)*AS + key] = kv.x; Ks[(d+1)*AS + key] = kv.y;
                Ks[(d+2)*AS + key] = kv.z; Ks[(d+3)*AS + key] = kv.w;
                *(float4*)&Vs[key * AS + d] = vv;
            }
        }
        __syncthreads();

        // ---- S = Q @ K^T  (outer product over d) ----
        float s[4][4];
        #pragma unroll
        for (int i = 0; i < 4; i++)
            #pragma unroll
            for (int j = 0; j < 4; j++) s[i][j] = 0.0f;

        #pragma unroll 16
        for (int d = 0; d < 64; d++) {
            float4 aq = *(const float4*)&Qs[d*AS + ty*4];
            float4 bk = *(const float4*)&Ks[d*AS + tx*4];
            float a[4] = {aq.x, aq.y, aq.z, aq.w};
            float bb[4] = {bk.x, bk.y, bk.z, bk.w};
            #pragma unroll
            for (int i = 0; i < 4; i++)
                #pragma unroll
                for (int j = 0; j < 4; j++)
                    s[i][j] = fmaf(a[i], bb[j], s[i][j]);
        }

        // scale + mask out-of-range keys
        #pragma unroll
        for (int i = 0; i < 4; i++)
            #pragma unroll
            for (int j = 0; j < 4; j++) {
                s[i][j] *= SCALE;
                if (kt * 64 + tx * 4 + j >= (SPB + 1)) s[i][j] = -1e30f;
            }

        // ---- online softmax (row = 16 lanes sharing ty) ----
        #pragma unroll
        for (int i = 0; i < 4; i++) {
            float mt = fmaxf(fmaxf(s[i][0], s[i][1]), fmaxf(s[i][2], s[i][3]));
            #pragma unroll
            for (int off = 8; off; off >>= 1)
                mt = fmaxf(mt, __shfl_xor_sync(0xffffffffu, mt, off));
            float mnew = fmaxf(m[i], mt);
            float alpha = expf(m[i] - mnew);
            m[i] = mnew;
            float rs = 0.0f;
            #pragma unroll
            for (int j = 0; j < 4; j++) {
                s[i][j] = expf(s[i][j] - mnew);
                rs += s[i][j];
            }
            #pragma unroll
            for (int off = 8; off; off >>= 1)
                rs += __shfl_xor_sync(0xffffffffu, rs, off);
            l[i] = l[i] * alpha + rs;
            #pragma unroll
            for (int j = 0; j < 4; j++) {
                o[i][j] *= alpha;
                Ps[(tx*4 + j)*AS + ty*4 + i] = s[i][j];   // P transposed [k][q]
            }
        }
        __syncthreads();

        // ---- O += P @ V (outer product over k) ----
        #pragma unroll 16
        for (int k = 0; k < 64; k++) {
            float4 ap = *(const float4*)&Ps[k*AS + ty*4];
            float4 bv = *(const float4*)&Vs[k*AS + tx*4];
            float a[4] = {ap.x, ap.y, ap.z, ap.w};
            float bb[4] = {bv.x, bv.y, bv.z, bv.w};
            #pragma unroll
            for (int i = 0; i < 4; i++)
                #pragma unroll
                for (int j = 0; j < 4; j++)
                    o[i][j] = fmaf(a[i], bb[j], o[i][j]);
        }
        __syncthreads();
    }

    // ---- write output with the reference's scrambled head/seq reshape ----
    #pragma unroll
    for (int i = 0; i < 4; i++) {
        int sp = qt * 64 + ty * 4 + i;       // seq within block (0..511)
        float inv_l = 1.0f / l[i];
        #pragma unroll
        for (int j = 0; j < 4; j++) {
            int dp = tx * 4 + j;             // head dim (0..63)
            int linear = h * (SPB * HD) + sp * HD + dp;   // flat over [H,SPB,HD]
            int s_ = linear / CC;
            int c  = linear - s_ * CC;
            int token = 1 + nb * SPB + s_;
            y[(size_t)(b * NN + token) * CC + c] = o[i][j] * inv_l;
        }
    }
}

// ---------------- launch ----------------
extern "C" void kernel_launch(void* const* d_in, const int* in_sizes, int n_in,
                              void* d_out, int out_size)
{
    const float* x      = (const float*)d_in[0];
    const float* ln1_w  = (const float*)d_in[1];
    const float* ln1_b  = (const float*)d_in[2];
    const float* qkv_w  = (const float*)d_in[3];
    const float* proj_w = (const float*)d_in[4];
    const float* proj_b = (const float*)d_in[5];
    const float* ln2_w  = (const float*)d_in[6];
    const float* ln2_b  = (const float*)d_in[7];
    const float* fc1_w  = (const float*)d_in[8];
    const float* fc1_b  = (const float*)d_in[9];
    const float* fc2_w  = (const float*)d_in[10];
    const float* fc2_b  = (const float*)d_in[11];
    float* out = (float*)d_out;

    float *h1, *qkv, *qkvc, *y, *x2, *h2, *fc1;
    cudaGetSymbolAddress((void**)&h1,   g_h1);
    cudaGetSymbolAddress((void**)&qkv,  g_qkv);
    cudaGetSymbolAddress((void**)&qkvc, g_qkvc);
    cudaGetSymbolAddress((void**)&y,    g_y);
    cudaGetSymbolAddress((void**)&x2,   g_x2);
    cudaGetSymbolAddress((void**)&h2,   g_h2);
    cudaGetSymbolAddress((void**)&fc1,  g_fc1);

    const int M = MROWS;

    // 1. LN1
    ln_kernel<<<M, 256>>>(x, ln1_w, ln1_b, h1);

    // 2. qkv = h1 @ qkv_w^T   [M, 2304]
    {
        dim3 grid((3*CC)/128, (M + 127)/128);
        sgemm_nt<0><<<grid, 256>>>(h1, qkv_w, nullptr, nullptr, qkv, M, 3*CC, CC);
    }

    // 3. cls global attention -> g_y row 0 per batch
    cls_attn_kernel<<<BB*HH, 256>>>(qkv, h1, y);

    // 4. cls qkv
    cls_qkv_kernel<<<3*CC, 256>>>(y, qkv_w, qkvc);

    // 5. branch attention -> g_y rows 1..2048 (scrambled reshape)
    {
        static int smem_set = 0;
        size_t smem = 4 * 64 * AS * sizeof(float);  // 69632 bytes
        cudaFuncSetAttribute(branch_attn_kernel,
                             cudaFuncAttributeMaxDynamicSharedMemorySize, (int)smem);
        dim3 grid(8, NBB, BB*HH);
        branch_attn_kernel<<<grid, 256, smem>>>(qkv, qkvc, y);
        (void)smem_set;
    }

    // 6. x2 = x + y @ proj_w^T + proj_b
    {
        dim3 grid(CC/128, (M + 127)/128);
        sgemm_nt<1><<<grid, 256>>>(y, proj_w, proj_b, x, x2, M, CC, CC);
    }

    // 7. LN2
    ln_kernel<<<M, 256>>>(x2, ln2_w, ln2_b, h2);

    // 8. fc1 + gelu
    {
        dim3 grid((4*CC)/128, (M + 127)/128);
        sgemm_nt<2><<<grid, 256>>>(h2, fc1_w, fc1_b, nullptr, fc1, M, 4*CC, CC);
    }

    // 9. out = x2 + fc1g @ fc2_w^T + fc2_b
    {
        dim3 grid(CC/128, (M + 127)/128);
        sgemm_nt<1><<<grid, 256>>>(fc1, fc2_w, fc2_b, x2, out, M, CC, 4*CC);
    }
}

// round 2
// speedup vs baseline: 1.2549x; 1.2549x over previous
#include <cuda_runtime.h>
#include <cuda_bf16.h>
#include <math.h>

// ---------------- problem constants ----------------
#define BB   8
#define NN   2049
#define CC   768
#define HH   12
#define NBB  4
#define HD   64
#define SPB  512
#define MROWS (BB*NN)      // 16392
#define MPAD  16512        // 129 * 128
#define SCALE 0.125f
#define LNEPS 1e-6f

// ---------------- scratch (static device globals; zero-initialized) -------------
__device__ float g_h1f [(size_t)MROWS * CC];
__device__ __nv_bfloat16 g_h1h[(size_t)MPAD * CC];
__device__ __nv_bfloat16 g_h1l[(size_t)MPAD * CC];
__device__ float g_qkv [(size_t)MROWS * 3 * CC];
__device__ float g_qkvc[BB * 3 * CC];
__device__ float g_cls [BB * CC];
__device__ __nv_bfloat16 g_yh [(size_t)MPAD * CC];
__device__ __nv_bfloat16 g_yl [(size_t)MPAD * CC];
__device__ float g_x2  [(size_t)MROWS * CC];
__device__ __nv_bfloat16 g_h2h[(size_t)MPAD * CC];
__device__ __nv_bfloat16 g_h2l[(size_t)MPAD * CC];
__device__ __nv_bfloat16 g_f1h[(size_t)MPAD * 4 * CC];
__device__ __nv_bfloat16 g_f1l[(size_t)MPAD * 4 * CC];
// weight splits
__device__ __nv_bfloat16 g_wqh[3*CC*CC], g_wql[3*CC*CC];
__device__ __nv_bfloat16 g_wph[CC*CC],   g_wpl[CC*CC];
__device__ __nv_bfloat16 g_w1h[4*CC*CC], g_w1l[4*CC*CC];
__device__ __nv_bfloat16 g_w2h[4*CC*CC], g_w2l[4*CC*CC];

// ---------------- helpers ----------------
__device__ __forceinline__ void split2(float v, __nv_bfloat16& h, __nv_bfloat16& l) {
    h = __float2bfloat16(v);
    l = __float2bfloat16(v - __bfloat162float(h));
}

__global__ void __launch_bounds__(256) split_kernel(const float* __restrict__ in,
                                                    __nv_bfloat16* __restrict__ oh,
                                                    __nv_bfloat16* __restrict__ ol, int n)
{
    int i = blockIdx.x * 256 + threadIdx.x;
    if (i < n) {
        __nv_bfloat16 h, l;
        split2(in[i], h, l);
        oh[i] = h; ol[i] = l;
    }
}

// ---------------- LayerNorm: one block per row ----------------
__global__ void __launch_bounds__(256) ln_kernel(const float* __restrict__ x,
                                                 const float* __restrict__ w,
                                                 const float* __restrict__ b,
                                                 float* __restrict__ outf,
                                                 __nv_bfloat16* __restrict__ oh,
                                                 __nv_bfloat16* __restrict__ ol)
{
    __shared__ float red[256];
    int row = blockIdx.x;
    int tid = threadIdx.x;
    const float* xr = x + (size_t)row * CC;

    float v0 = xr[tid], v1 = xr[tid + 256], v2 = xr[tid + 512];
    float s = v0 + v1 + v2;
    red[tid] = s; __syncthreads();
    for (int off = 128; off; off >>= 1) {
        if (tid < off) red[tid] += red[tid + off];
        __syncthreads();
    }
    float mu = red[0] * (1.0f / CC);
    __syncthreads();

    float d0 = v0 - mu, d1 = v1 - mu, d2 = v2 - mu;
    red[tid] = d0*d0 + d1*d1 + d2*d2; __syncthreads();
    for (int off = 128; off; off >>= 1) {
        if (tid < off) red[tid] += red[tid + off];
        __syncthreads();
    }
    float var = red[0] * (1.0f / CC);
    float rs = rsqrtf(var + LNEPS);

    float o0 = d0 * rs * w[tid      ] + b[tid      ];
    float o1 = d1 * rs * w[tid + 256] + b[tid + 256];
    float o2 = d2 * rs * w[tid + 512] + b[tid + 512];
    size_t base = (size_t)row * CC;
    if (outf) { outf[base+tid] = o0; outf[base+tid+256] = o1; outf[base+tid+512] = o2; }
    __nv_bfloat16 h, l;
    split2(o0, h, l); oh[base+tid    ] = h; ol[base+tid    ] = l;
    split2(o1, h, l); oh[base+tid+256] = h; ol[base+tid+256] = l;
    split2(o2, h, l); oh[base+tid+512] = h; ol[base+tid+512] = l;
}

// ---------------- bf16x3 tensor-core GEMM ----------------
// C[m][n] = sum_k A[m][k] * W[n][k], A/W given as (hi,lo) bf16 splits.
// BM=BN=128, BK=32, 256 threads (8 warps in 2x4), warp tile 64x32, m16n8k16.
// EPI: 0 none, 1 bias+residual, 2 bias+exact gelu. SPLIT: write bf16 hi/lo.
#define GLDA 40   // smem row stride in halves (80B, conflict-free)

__device__ __forceinline__ void cp8(__nv_bfloat16* s, const __nv_bfloat16* g) {
    unsigned sa = (unsigned)__cvta_generic_to_shared(s);
    asm volatile("cp.async.ca.shared.global [%0], [%1], 8;\n" :: "r"(sa), "l"(g));
}
__device__ __forceinline__ void cp_commit() { asm volatile("cp.async.commit_group;\n"); }
template<int NW> __device__ __forceinline__ void cp_wait() {
    asm volatile("cp.async.wait_group %0;\n" :: "n"(NW));
}
__device__ __forceinline__ void mma16816(float* c, const unsigned* a, const unsigned* b) {
    asm volatile("mma.sync.aligned.m16n8k16.row.col.f32.bf16.bf16.f32 "
        "{%0,%1,%2,%3}, {%4,%5,%6,%7}, {%8,%9}, {%0,%1,%2,%3};"
        : "+f"(c[0]), "+f"(c[1]), "+f"(c[2]), "+f"(c[3])
        : "r"(a[0]), "r"(a[1]), "r"(a[2]), "r"(a[3]), "r"(b[0]), "r"(b[1]));
}

template<int EPI, bool SPLIT>
__global__ void __launch_bounds__(256) gemm_bf16x3(
    const __nv_bfloat16* __restrict__ Ah, const __nv_bfloat16* __restrict__ Al,
    const __nv_bfloat16* __restrict__ Wh, const __nv_bfloat16* __restrict__ Wl,
    const float* __restrict__ bias, const float* __restrict__ res,
    float* __restrict__ Cf, __nv_bfloat16* __restrict__ Ch, __nv_bfloat16* __restrict__ Cl,
    int M, int N, int K)
{
    extern __shared__ __nv_bfloat16 sm[];
    const int SA = 128 * GLDA;      // halves per array
    const int SSTAGE = 4 * SA;

    int tid = threadIdx.x;
    int bm = blockIdx.y * 128, bn = blockIdx.x * 128;

    int lrow = tid >> 1;            // 0..127
    int loff = (tid & 1) * 16;      // half offset 0/16

    float acc[4][4][4];
    #pragma unroll
    for (int i = 0; i < 4; i++)
        #pragma unroll
        for (int j = 0; j < 4; j++)
            #pragma unroll
            for (int t = 0; t < 4; t++) acc[i][j][t] = 0.0f;

    int lane = tid & 31, wid = tid >> 5;
    int wm = (wid & 1) * 64, wn = (wid >> 1) * 32;
    int r = lane >> 2, c2 = (lane & 3) * 2;

    const int nt = K / 32;

    // stage loader
    auto load_stage = [&](int kt, int stg) {
        __nv_bfloat16* base = sm + stg * SSTAGE;
        const __nv_bfloat16* gAh = Ah + (size_t)(bm + lrow) * K + kt*32 + loff;
        const __nv_bfloat16* gAl = Al + (size_t)(bm + lrow) * K + kt*32 + loff;
        const __nv_bfloat16* gWh = Wh + (size_t)(bn + lrow) * K + kt*32 + loff;
        const __nv_bfloat16* gWl = Wl + (size_t)(bn + lrow) * K + kt*32 + loff;
        __nv_bfloat16* s0 = base + lrow * GLDA + loff;
        #pragma unroll
        for (int j = 0; j < 4; j++) {
            cp8(s0 +        j*4, gAh + j*4);
            cp8(s0 + SA   + j*4, gAl + j*4);
            cp8(s0 + 2*SA + j*4, gWh + j*4);
            cp8(s0 + 3*SA + j*4, gWl + j*4);
        }
    };

    load_stage(0, 0);
    cp_commit();

    for (int kt = 0; kt < nt; kt++) {
        if (kt + 1 < nt) load_stage(kt + 1, (kt + 1) & 1);
        cp_commit();
        cp_wait<1>();
        __syncthreads();

        const __nv_bfloat16* base = sm + (kt & 1) * SSTAGE;
        const __nv_bfloat16* sAh = base;
        const __nv_bfloat16* sAl = base + SA;
        const __nv_bfloat16* sBh = base + 2*SA;
        const __nv_bfloat16* sBl = base + 3*SA;

        #pragma unroll
        for (int kk = 0; kk < 2; kk++) {
            int kb = kk * 16;
            unsigned bh[4][2], bl[4][2];
            #pragma unroll
            for (int ni = 0; ni < 4; ni++) {
                int n0 = wn + ni*8 + r;
                bh[ni][0] = *(const unsigned*)&sBh[n0*GLDA + kb + c2];
                bh[ni][1] = *(const unsigned*)&sBh[n0*GLDA + kb + 8 + c2];
                bl[ni][0] = *(const unsigned*)&sBl[n0*GLDA + kb + c2];
                bl[ni][1] = *(const unsigned*)&sBl[n0*GLDA + kb + 8 + c2];
            }
            #pragma unroll
            for (int mi = 0; mi < 4; mi++) {
                int m0 = wm + mi*16 + r;
                unsigned ah[4], al[4];
                ah[0] = *(const unsigned*)&sAh[ m0    *GLDA + kb + c2];
                ah[1] = *(const unsigned*)&sAh[(m0+8)*GLDA + kb + c2];
                ah[2] = *(const unsigned*)&sAh[ m0    *GLDA + kb + 8 + c2];
                ah[3] = *(const unsigned*)&sAh[(m0+8)*GLDA + kb + 8 + c2];
                al[0] = *(const unsigned*)&sAl[ m0    *GLDA + kb + c2];
                al[1] = *(const unsigned*)&sAl[(m0+8)*GLDA + kb + c2];
                al[2] = *(const unsigned*)&sAl[ m0    *GLDA + kb + 8 + c2];
                al[3] = *(const unsigned*)&sAl[(m0+8)*GLDA + kb + 8 + c2];
                #pragma unroll
                for (int ni = 0; ni < 4; ni++) {
                    mma16816(acc[mi][ni], ah, bh[ni]);
                    mma16816(acc[mi][ni], ah, bl[ni]);
                    mma16816(acc[mi][ni], al, bh[ni]);
                }
            }
        }
        __syncthreads();
    }

    // epilogue
    #pragma unroll
    for (int mi = 0; mi < 4; mi++) {
        #pragma unroll
        for (int hh = 0; hh < 2; hh++) {
            int m = bm + wm + mi*16 + r + hh*8;
            if (m >= M) continue;
            #pragma unroll
            for (int ni = 0; ni < 4; ni++) {
                int n0 = bn + wn + ni*8 + c2;
                #pragma unroll
                for (int t = 0; t < 2; t++) {
                    int n = n0 + t;
                    float v = acc[mi][ni][hh*2 + t];
                    if (EPI != 0) v += bias[n];
                    if (EPI == 1) v += res[(size_t)m * N + n];
                    if (EPI == 2) v = 0.5f * v * (1.0f + erff(v * 0.7071067811865476f));
                    size_t idx = (size_t)m * N + n;
                    if (SPLIT) {
                        __nv_bfloat16 h, l;
                        split2(v, h, l);
                        Ch[idx] = h; Cl[idx] = l;
                    } else {
                        Cf[idx] = v;
                    }
                }
            }
        }
    }
}

// ---------------- cls global attention: 1 block per (b,h) ----------------
__global__ void __launch_bounds__(256) cls_attn_kernel(const float* __restrict__ qkv,
                                                       const float* __restrict__ h1,
                                                       float* __restrict__ cls,
                                                       __nv_bfloat16* __restrict__ yh,
                                                       __nv_bfloat16* __restrict__ yl)
{
    __shared__ float sq[64];
    __shared__ float sc[NN];
    __shared__ float red[256];
    __shared__ float so[4][64];

    int bh = blockIdx.x;
    int b = bh / HH, h = bh % HH;
    int tid = threadIdx.x;

    const float* qbase = qkv + (size_t)(b * NN) * (3*CC) + h * HD;
    if (tid < 64) sq[tid] = qbase[tid];
    __syncthreads();

    float lmax = -1e30f;
    for (int i = tid; i < NN; i += 256) {
        const float* kr = qkv + (size_t)(b * NN + i) * (3*CC) + CC + h * HD;
        float s = 0.0f;
        #pragma unroll 16
        for (int d = 0; d < 64; d++) s = fmaf(sq[d], kr[d], s);
        s *= SCALE;
        sc[i] = s;
        lmax = fmaxf(lmax, s);
    }
    red[tid] = lmax; __syncthreads();
    for (int off = 128; off; off >>= 1) {
        if (tid < off) red[tid] = fmaxf(red[tid], red[tid + off]);
        __syncthreads();
    }
    float m = red[0];
    __syncthreads();

    float lsum = 0.0f;
    for (int i = tid; i < NN; i += 256) {
        float e = expf(sc[i] - m);
        sc[i] = e;
        lsum += e;
    }
    red[tid] = lsum; __syncthreads();
    for (int off = 128; off; off >>= 1) {
        if (tid < off) red[tid] += red[tid + off];
        __syncthreads();
    }
    float l = red[0];
    __syncthreads();

    int d = tid & 63, part = tid >> 6;
    float o = 0.0f;
    for (int i = part; i < NN; i += 4)
        o = fmaf(sc[i], qkv[(size_t)(b * NN + i) * (3*CC) + 2*CC + h * HD + d], o);
    so[part][d] = o;
    __syncthreads();

    if (tid < 64) {
        float val = (so[0][tid] + so[1][tid] + so[2][tid] + so[3][tid]) / l;
        size_t off0 = (size_t)(b * NN) * CC + h * HD + tid;
        float v = val + h1[off0];
        cls[b * CC + h * HD + tid] = v;
        __nv_bfloat16 hi, lo;
        split2(v, hi, lo);
        yh[off0] = hi; yl[off0] = lo;
    }
}

// ---------------- cls qkv ----------------
__global__ void __launch_bounds__(256) cls_qkv_kernel(const float* __restrict__ cls,
                                                      const float* __restrict__ qkv_w,
                                                      float* __restrict__ qkvc)
{
    int j = blockIdx.x;
    int w = threadIdx.x >> 5;
    int lane = threadIdx.x & 31;
    const float* cr = cls + (size_t)w * CC;
    const float* wr = qkv_w + (size_t)j * CC;
    float s = 0.0f;
    for (int k = lane; k < CC; k += 32) s = fmaf(cr[k], wr[k], s);
    #pragma unroll
    for (int off = 16; off; off >>= 1) s += __shfl_xor_sync(0xffffffffu, s, off);
    if (lane == 0) qkvc[w * (3*CC) + j] = s;
}

// ---------------- branch attention ----------------
#define AS 68

__global__ void __launch_bounds__(256) branch_attn_kernel(const float* __restrict__ qkv,
                                                          const float* __restrict__ qkvc,
                                                          __nv_bfloat16* __restrict__ yh,
                                                          __nv_bfloat16* __restrict__ yl)
{
    extern __shared__ float smem[];
    float* Qs = smem;
    float* Ks = Qs + 64 * AS;
    float* Vs = Ks + 64 * AS;
    float* Ps = Vs + 64 * AS;

    int tid = threadIdx.x;
    int tx = tid & 15;
    int ty = tid >> 4;
    int qt = blockIdx.x;
    int nb = blockIdx.y;
    int b = blockIdx.z / HH, h = blockIdx.z % HH;

    {
        int q  = tid >> 2;
        int dg = (tid & 3) * 16;
        int token = 1 + nb * SPB + qt * 64 + q;
        const float* src = qkv + (size_t)(b * NN + token) * (3*CC) + h * HD + dg;
        #pragma unroll
        for (int ii = 0; ii < 4; ii++) {
            float4 v = *(const float4*)(src + ii * 4);
            int d = dg + ii * 4;
            Qs[(d+0)*AS + q] = v.x; Qs[(d+1)*AS + q] = v.y;
            Qs[(d+2)*AS + q] = v.z; Qs[(d+3)*AS + q] = v.w;
        }
    }

    float m[4], l[4], o[4][4];
    #pragma unroll
    for (int i = 0; i < 4; i++) {
        m[i] = -1e30f; l[i] = 0.0f;
        #pragma unroll
        for (int j = 0; j < 4; j++) o[i][j] = 0.0f;
    }

    for (int kt = 0; kt < 9; kt++) {
        {
            int key = tid >> 2;
            int dg  = (tid & 3) * 16;
            int jg  = kt * 64 + key;
            bool valid = jg < (SPB + 1);
            const float *ksrc = nullptr, *vsrc = nullptr;
            if (valid) {
                if (jg == 0) {
                    ksrc = qkvc + b * (3*CC) + CC   + h * HD + dg;
                    vsrc = qkvc + b * (3*CC) + 2*CC + h * HD + dg;
                } else {
                    int token = nb * SPB + jg;
                    size_t roff = (size_t)(b * NN + token) * (3*CC) + h * HD + dg;
                    ksrc = qkv + roff + CC;
                    vsrc = qkv + roff + 2*CC;
                }
            }
            #pragma unroll
            for (int ii = 0; ii < 4; ii++) {
                float4 kv = valid ? *(const float4*)(ksrc + ii*4) : make_float4(0.f,0.f,0.f,0.f);
                float4 vv = valid ? *(const float4*)(vsrc + ii*4) : make_float4(0.f,0.f,0.f,0.f);
                int d = dg + ii * 4;
                Ks[(d+0)*AS + key] = kv.x; Ks[(d+1)*AS + key] = kv.y;
                Ks[(d+2)*AS + key] = kv.z; Ks[(d+3)*AS + key] = kv.w;
                *(float4*)&Vs[key * AS + d] = vv;
            }
        }
        __syncthreads();

        float s[4][4];
        #pragma unroll
        for (int i = 0; i < 4; i++)
            #pragma unroll
            for (int j = 0; j < 4; j++) s[i][j] = 0.0f;

        #pragma unroll 16
        for (int d = 0; d < 64; d++) {
            float4 aq = *(const float4*)&Qs[d*AS + ty*4];
            float4 bk = *(const float4*)&Ks[d*AS + tx*4];
            float a[4] = {aq.x, aq.y, aq.z, aq.w};
            float bb[4] = {bk.x, bk.y, bk.z, bk.w};
            #pragma unroll
            for (int i = 0; i < 4; i++)
                #pragma unroll
                for (int j = 0; j < 4; j++)
                    s[i][j] = fmaf(a[i], bb[j], s[i][j]);
        }

        #pragma unroll
        for (int i = 0; i < 4; i++)
            #pragma unroll
            for (int j = 0; j < 4; j++) {
                s[i][j] *= SCALE;
                if (kt * 64 + tx * 4 + j >= (SPB + 1)) s[i][j] = -1e30f;
            }

        #pragma unroll
        for (int i = 0; i < 4; i++) {
            float mt = fmaxf(fmaxf(s[i][0], s[i][1]), fmaxf(s[i][2], s[i][3]));
            #pragma unroll
            for (int off = 8; off; off >>= 1)
                mt = fmaxf(mt, __shfl_xor_sync(0xffffffffu, mt, off));
            float mnew = fmaxf(m[i], mt);
            float alpha = expf(m[i] - mnew);
            m[i] = mnew;
            float rs = 0.0f;
            #pragma unroll
            for (int j = 0; j < 4; j++) {
                s[i][j] = expf(s[i][j] - mnew);
                rs += s[i][j];
            }
            #pragma unroll
            for (int off = 8; off; off >>= 1)
                rs += __shfl_xor_sync(0xffffffffu, rs, off);
            l[i] = l[i] * alpha + rs;
            #pragma unroll
            for (int j = 0; j < 4; j++) {
                o[i][j] *= alpha;
                Ps[(tx*4 + j)*AS + ty*4 + i] = s[i][j];
            }
        }
        __syncthreads();

        #pragma unroll 16
        for (int k = 0; k < 64; k++) {
            float4 ap = *(const float4*)&Ps[k*AS + ty*4];
            float4 bv = *(const float4*)&Vs[k*AS + tx*4];
            float a[4] = {ap.x, ap.y, ap.z, ap.w};
            float bb[4] = {bv.x, bv.y, bv.z, bv.w};
            #pragma unroll
            for (int i = 0; i < 4; i++)
                #pragma unroll
                for (int j = 0; j < 4; j++)
                    o[i][j] = fmaf(a[i], bb[j], o[i][j]);
        }
        __syncthreads();
    }

    #pragma unroll
    for (int i = 0; i < 4; i++) {
        int sp = qt * 64 + ty * 4 + i;
        float inv_l = 1.0f / l[i];
        #pragma unroll
        for (int j = 0; j < 4; j++) {
            int dp = tx * 4 + j;
            int linear = h * (SPB * HD) + sp * HD + dp;
            int s_ = linear / CC;
            int c  = linear - s_ * CC;
            int token = 1 + nb * SPB + s_;
            float v = o[i][j] * inv_l;
            __nv_bfloat16 hi, lo;
            split2(v, hi, lo);
            size_t idx = (size_t)(b * NN + token) * CC + c;
            yh[idx] = hi; yl[idx] = lo;
        }
    }
}

// ---------------- launch ----------------
extern "C" void kernel_launch(void* const* d_in, const int* in_sizes, int n_in,
                              void* d_out, int out_size)
{
    const float* x      = (const float*)d_in[0];
    const float* ln1_w  = (const float*)d_in[1];
    const float* ln1_b  = (const float*)d_in[2];
    const float* qkv_w  = (const float*)d_in[3];
    const float* proj_w = (const float*)d_in[4];
    const float* proj_b = (const float*)d_in[5];
    const float* ln2_w  = (const float*)d_in[6];
    const float* ln2_b  = (const float*)d_in[7];
    const float* fc1_w  = (const float*)d_in[8];
    const float* fc1_b  = (const float*)d_in[9];
    const float* fc2_w  = (const float*)d_in[10];
    const float* fc2_b  = (const float*)d_in[11];
    float* out = (float*)d_out;

    float *h1f, *qkv, *qkvc, *cls, *x2;
    __nv_bfloat16 *h1h, *h1l, *yh, *yl, *h2h, *h2l, *f1h, *f1l;
    __nv_bfloat16 *wqh, *wql, *wph, *wpl, *w1h, *w1l, *w2h, *w2l;
    cudaGetSymbolAddress((void**)&h1f,  g_h1f);
    cudaGetSymbolAddress((void**)&h1h,  g_h1h);
    cudaGetSymbolAddress((void**)&h1l,  g_h1l);
    cudaGetSymbolAddress((void**)&qkv,  g_qkv);
    cudaGetSymbolAddress((void**)&qkvc, g_qkvc);
    cudaGetSymbolAddress((void**)&cls,  g_cls);
    cudaGetSymbolAddress((void**)&yh,   g_yh);
    cudaGetSymbolAddress((void**)&yl,   g_yl);
    cudaGetSymbolAddress((void**)&x2,   g_x2);
    cudaGetSymbolAddress((void**)&h2h,  g_h2h);
    cudaGetSymbolAddress((void**)&h2l,  g_h2l);
    cudaGetSymbolAddress((void**)&f1h,  g_f1h);
    cudaGetSymbolAddress((void**)&f1l,  g_f1l);
    cudaGetSymbolAddress((void**)&wqh,  g_wqh);
    cudaGetSymbolAddress((void**)&wql,  g_wql);
    cudaGetSymbolAddress((void**)&wph,  g_wph);
    cudaGetSymbolAddress((void**)&wpl,  g_wpl);
    cudaGetSymbolAddress((void**)&w1h,  g_w1h);
    cudaGetSymbolAddress((void**)&w1l,  g_w1l);
    cudaGetSymbolAddress((void**)&w2h,  g_w2h);
    cudaGetSymbolAddress((void**)&w2l,  g_w2l);

    const int M = MROWS;
    const size_t gemm_smem = 2 * 4 * 128 * GLDA * sizeof(__nv_bfloat16); // 81920
    cudaFuncSetAttribute(gemm_bf16x3<0,false>, cudaFuncAttributeMaxDynamicSharedMemorySize, (int)gemm_smem);
    cudaFuncSetAttribute(gemm_bf16x3<1,false>, cudaFuncAttributeMaxDynamicSharedMemorySize, (int)gemm_smem);
    cudaFuncSetAttribute(gemm_bf16x3<2,true >, cudaFuncAttributeMaxDynamicSharedMemorySize, (int)gemm_smem);

    // 0. split weights
    split_kernel<<<(3*CC*CC + 255)/256, 256>>>(qkv_w,  wqh, wql, 3*CC*CC);
    split_kernel<<<(CC*CC   + 255)/256, 256>>>(proj_w, wph, wpl, CC*CC);
    split_kernel<<<(4*CC*CC + 255)/256, 256>>>(fc1_w,  w1h, w1l, 4*CC*CC);
    split_kernel<<<(4*CC*CC + 255)/256, 256>>>(fc2_w,  w2h, w2l, 4*CC*CC);

    // 1. LN1 -> h1 (fp32 + split)
    ln_kernel<<<M, 256>>>(x, ln1_w, ln1_b, h1f, h1h, h1l);

    // 2. qkv = h1 @ qkv_w^T  (fp32 out)
    {
        dim3 grid((3*CC)/128, MPAD/128);
        gemm_bf16x3<0,false><<<grid, 256, gemm_smem>>>(h1h, h1l, wqh, wql,
            nullptr, nullptr, qkv, nullptr, nullptr, M, 3*CC, CC);
    }

    // 3. cls global attention
    cls_attn_kernel<<<BB*HH, 256>>>(qkv, h1f, cls, yh, yl);

    // 4. cls qkv
    cls_qkv_kernel<<<3*CC, 256>>>(cls, qkv_w, qkvc);

    // 5. branch attention
    {
        size_t smem = 4 * 64 * AS * sizeof(float);
        cudaFuncSetAttribute(branch_attn_kernel,
                             cudaFuncAttributeMaxDynamicSharedMemorySize, (int)smem);
        dim3 grid(8, NBB, BB*HH);
        branch_attn_kernel<<<grid, 256, smem>>>(qkv, qkvc, yh, yl);
    }

    // 6. x2 = x + y @ proj_w^T + proj_b
    {
        dim3 grid(CC/128, MPAD/128);
        gemm_bf16x3<1,false><<<grid, 256, gemm_smem>>>(yh, yl, wph, wpl,
            proj_b, x, x2, nullptr, nullptr, M, CC, CC);
    }

    // 7. LN2 -> h2 split
    ln_kernel<<<M, 256>>>(x2, ln2_w, ln2_b, nullptr, h2h, h2l);

    // 8. fc1 + gelu -> split
    {
        dim3 grid((4*CC)/128, MPAD/128);
        gemm_bf16x3<2,true><<<grid, 256, gemm_smem>>>(h2h, h2l, w1h, w1l,
            fc1_b, nullptr, nullptr, f1h, f1l, M, 4*CC, CC);
    }

    // 9. out = x2 + fc1g @ fc2_w^T + fc2_b
    {
        dim3 grid(CC/128, MPAD/128);
        gemm_bf16x3<1,false><<<grid, 256, gemm_smem>>>(f1h, f1l, w2h, w2l,
            fc2_b, x2, out, nullptr, nullptr, M, CC, 4*CC);
    }
}

// round 4
// speedup vs baseline: 1.7287x; 1.3775x over previous
#include <cuda_runtime.h>
#include <cuda_bf16.h>
#include <math.h>
#include <stdint.h>

// ---------------- problem constants ----------------
#define BB   8
#define NN   2049
#define CC   768
#define HH   12
#define NBB  4
#define HD   64
#define SPB  512
#define MROWS (BB*NN)      // 16392
#define MPAD  16512        // 129 * 128
#define SCALE 0.125f
#define LNEPS 1e-6f

// ---------------- scratch (static device globals; zero-initialized) -------------
__device__ float g_h1f [(size_t)MROWS * CC];
__device__ __nv_bfloat16 g_h1h[(size_t)MPAD * CC];
__device__ __nv_bfloat16 g_h1l[(size_t)MPAD * CC];
__device__ float g_qkv [(size_t)MROWS * 3 * CC];
__device__ float g_qkvc[BB * 3 * CC];
__device__ float g_cls [BB * CC];
__device__ __nv_bfloat16 g_yh [(size_t)MPAD * CC];
__device__ __nv_bfloat16 g_yl [(size_t)MPAD * CC];
__device__ float g_x2  [(size_t)MROWS * CC];
__device__ __nv_bfloat16 g_h2h[(size_t)MPAD * CC];
__device__ __nv_bfloat16 g_h2l[(size_t)MPAD * CC];
__device__ __nv_bfloat16 g_f1h[(size_t)MPAD * 4 * CC];
__device__ __nv_bfloat16 g_f1l[(size_t)MPAD * 4 * CC];
// weight splits
__device__ __nv_bfloat16 g_wqh[3*CC*CC], g_wql[3*CC*CC];
__device__ __nv_bfloat16 g_wph[CC*CC],   g_wpl[CC*CC];
__device__ __nv_bfloat16 g_w1h[4*CC*CC], g_w1l[4*CC*CC];
__device__ __nv_bfloat16 g_w2h[4*CC*CC], g_w2l[4*CC*CC];

// ---------------- helpers ----------------
__device__ __forceinline__ void split2(float v, __nv_bfloat16& h, __nv_bfloat16& l) {
    h = __float2bfloat16(v);
    l = __float2bfloat16(v - __bfloat162float(h));
}
__device__ __forceinline__ uint32_t smem_u32(const void* p) {
    return (uint32_t)__cvta_generic_to_shared(p);
}
__device__ __forceinline__ void cp16(uint32_t saddr, const void* g) {
    asm volatile("cp.async.cg.shared.global [%0], [%1], 16;\n" :: "r"(saddr), "l"(g));
}
__device__ __forceinline__ void cp_commit() { asm volatile("cp.async.commit_group;\n"); }
template<int NW> __device__ __forceinline__ void cp_wait() {
    asm volatile("cp.async.wait_group %0;\n" :: "n"(NW));
}
__device__ __forceinline__ void ldsm4(uint32_t addr, uint32_t& r0, uint32_t& r1,
                                      uint32_t& r2, uint32_t& r3) {
    asm volatile("ldmatrix.sync.aligned.m8n8.x4.shared.b16 {%0,%1,%2,%3}, [%4];"
                 : "=r"(r0), "=r"(r1), "=r"(r2), "=r"(r3) : "r"(addr));
}
__device__ __forceinline__ void mma16816(float* c, const uint32_t* a, const uint32_t* b) {
    asm volatile("mma.sync.aligned.m16n8k16.row.col.f32.bf16.bf16.f32 "
        "{%0,%1,%2,%3}, {%4,%5,%6,%7}, {%8,%9}, {%0,%1,%2,%3};"
        : "+f"(c[0]), "+f"(c[1]), "+f"(c[2]), "+f"(c[3])
        : "r"(a[0]), "r"(a[1]), "r"(a[2]), "r"(a[3]), "r"(b[0]), "r"(b[1]));
}

__global__ void __launch_bounds__(256) split_kernel(const float* __restrict__ in,
                                                    __nv_bfloat16* __restrict__ oh,
                                                    __nv_bfloat16* __restrict__ ol, int n)
{
    int i = blockIdx.x * 256 + threadIdx.x;
    if (i < n) {
        __nv_bfloat16 h, l;
        split2(in[i], h, l);
        oh[i] = h; ol[i] = l;
    }
}

// ---------------- LayerNorm: one block per row ----------------
// outf (fp32) is written only for rows where row % NN == 0 (cls rows; only ones read as fp32)
__global__ void __launch_bounds__(256) ln_kernel(const float* __restrict__ x,
                                                 const float* __restrict__ w,
                                                 const float* __restrict__ b,
                                                 float* __restrict__ outf,
                                                 __nv_bfloat16* __restrict__ oh,
                                                 __nv_bfloat16* __restrict__ ol)
{
    __shared__ float red[256];
    int row = blockIdx.x;
    int tid = threadIdx.x;
    const float* xr = x + (size_t)row * CC;

    float v0 = xr[tid], v1 = xr[tid + 256], v2 = xr[tid + 512];
    float s = v0 + v1 + v2;
    red[tid] = s; __syncthreads();
    for (int off = 128; off; off >>= 1) {
        if (tid < off) red[tid] += red[tid + off];
        __syncthreads();
    }
    float mu = red[0] * (1.0f / CC);
    __syncthreads();

    float d0 = v0 - mu, d1 = v1 - mu, d2 = v2 - mu;
    red[tid] = d0*d0 + d1*d1 + d2*d2; __syncthreads();
    for (int off = 128; off; off >>= 1) {
        if (tid < off) red[tid] += red[tid + off];
        __syncthreads();
    }
    float var = red[0] * (1.0f / CC);
    float rs = rsqrtf(var + LNEPS);

    float o0 = d0 * rs * w[tid      ] + b[tid      ];
    float o1 = d1 * rs * w[tid + 256] + b[tid + 256];
    float o2 = d2 * rs * w[tid + 512] + b[tid + 512];
    size_t base = (size_t)row * CC;
    if (outf && (row % NN) == 0) {
        outf[base+tid] = o0; outf[base+tid+256] = o1; outf[base+tid+512] = o2;
    }
    __nv_bfloat16 h, l;
    split2(o0, h, l); oh[base+tid    ] = h; ol[base+tid    ] = l;
    split2(o1, h, l); oh[base+tid+256] = h; ol[base+tid+256] = l;
    split2(o2, h, l); oh[base+tid+512] = h; ol[base+tid+512] = l;
}

// ================= bf16x3 mma.sync GEMM (ldmatrix + 3-stage cp.async) =============
// C[m][n] = sum_k A[m][k]*W[n][k]; A,W as (hi,lo) bf16 splits.
// CTA tile 128x128x64, 8 warps (2m x 4n), warp tile 64x32, m16n8k16.
// smem: per stage 4 tiles (Ah, Al, Wh, Wl), each 128 rows x 128B, xor-swizzled.
#define TILE_B   16384
#define STAGE_B  (4*TILE_B)
#define NSTAGE   3

template<int EPI, bool SPLIT>
__global__ void __launch_bounds__(256, 1) tc_gemm(
    const __nv_bfloat16* __restrict__ Ah, const __nv_bfloat16* __restrict__ Al,
    const __nv_bfloat16* __restrict__ Wh, const __nv_bfloat16* __restrict__ Wl,
    const float* __restrict__ bias, const float* __restrict__ res,
    float* __restrict__ Cf, __nv_bfloat16* __restrict__ Ch, __nv_bfloat16* __restrict__ Cl,
    int M, int N, int K)
{
    extern __shared__ char dynraw[];
    uint32_t raw = smem_u32(dynraw);
    uint32_t smb = (raw + 127) & ~127u;

    const int tid = threadIdx.x;
    const int bn = blockIdx.x * 128, bm = blockIdx.y * 128;
    const int nt = K >> 6;
    const int lane = tid & 31, wid = tid >> 5;
    const int wm = (wid & 1) * 64, wn = (wid >> 1) * 32;
    const int r8 = lane & 7, sub = lane >> 3;

    // ---- loader indices: 2 threads per row, 4 chunks of 16B each ----
    const int lrow = tid >> 1;
    const int c0 = (tid & 1) * 4;

    auto load_stage = [&](int kt, int s) {
        uint32_t sb = smb + s * STAGE_B;
        size_t goff = (size_t)(kt * 64 + c0 * 8);
        const __nv_bfloat16* gAh = Ah + (size_t)(bm + lrow) * K + goff;
        const __nv_bfloat16* gAl = Al + (size_t)(bm + lrow) * K + goff;
        const __nv_bfloat16* gWh = Wh + (size_t)(bn + lrow) * K + goff;
        const __nv_bfloat16* gWl = Wl + (size_t)(bn + lrow) * K + goff;
        uint32_t ro = lrow * 128;
        #pragma unroll
        for (int c = 0; c < 4; c++) {
            int chunk = c0 + c;
            uint32_t sw = ro + (uint32_t)((chunk ^ (lrow & 7)) << 4);
            cp16(sb            + sw, gAh + c*8);
            cp16(sb +   TILE_B + sw, gAl + c*8);
            cp16(sb + 2*TILE_B + sw, gWh + c*8);
            cp16(sb + 3*TILE_B + sw, gWl + c*8);
        }
        cp_commit();
    };

    float acc[4][4][4];
    #pragma unroll
    for (int i = 0; i < 4; i++)
        #pragma unroll
        for (int j = 0; j < 4; j++)
            #pragma unroll
            for (int t = 0; t < 4; t++) acc[i][j][t] = 0.0f;

    // ---- per-thread ldmatrix row bases ----
    // A frag (m16k16): row = wm + mi*16 + (sub&1)*8 + r8 ; chunk = kk*2 + (sub>>1)
    uint32_t aRowBase[4]; int aKey[4];
    #pragma unroll
    for (int mi = 0; mi < 4; mi++) {
        int row = wm + mi*16 + ((sub & 1) << 3) + r8;
        aRowBase[mi] = row * 128;
        aKey[mi] = row & 7;
    }
    const int aChunkOff = sub >> 1;
    // B frag (n16k16 pair): row = wn + pair*16 + (sub>>1)*8 + r8 ; chunk = kk*2 + (sub&1)
    uint32_t bRowBase[2]; int bKey[2];
    #pragma unroll
    for (int pr = 0; pr < 2; pr++) {
        int row = wn + pr*16 + ((sub >> 1) << 3) + r8;
        bRowBase[pr] = row * 128;
        bKey[pr] = row & 7;
    }
    const int bChunkOff = sub & 1;

    load_stage(0, 0);
    load_stage(1, 1);

    for (int kt = 0; kt < nt; kt++) {
        if (kt + 1 < nt) cp_wait<1>(); else cp_wait<0>();
        __syncthreads();

        uint32_t sb = smb + (kt % NSTAGE) * STAGE_B;

        #pragma unroll
        for (int kk = 0; kk < 4; kk++) {
            uint32_t Bh[2][4], Bl[2][4];
            #pragma unroll
            for (int pr = 0; pr < 2; pr++) {
                int chunk = kk*2 + bChunkOff;
                uint32_t ad = sb + 2*TILE_B + bRowBase[pr]
                            + (uint32_t)((chunk ^ bKey[pr]) << 4);
                ldsm4(ad,          Bh[pr][0], Bh[pr][1], Bh[pr][2], Bh[pr][3]);
                ldsm4(ad + TILE_B, Bl[pr][0], Bl[pr][1], Bl[pr][2], Bl[pr][3]);
            }
            #pragma unroll
            for (int mi = 0; mi < 4; mi++) {
                int chunk = kk*2 + aChunkOff;
                uint32_t ad = sb + aRowBase[mi]
                            + (uint32_t)((chunk ^ aKey[mi]) << 4);
                uint32_t Af[4], Alf[4];
                ldsm4(ad,          Af[0],  Af[1],  Af[2],  Af[3]);
                ldsm4(ad + TILE_B, Alf[0], Alf[1], Alf[2], Alf[3]);
                #pragma unroll
                for (int ni = 0; ni < 4; ni++) {
                    int pr = ni >> 1, half = (ni & 1) * 2;
                    mma16816(acc[mi][ni], Af,  &Bh[pr][half]);
                    mma16816(acc[mi][ni], Af,  &Bl[pr][half]);
                    mma16816(acc[mi][ni], Alf, &Bh[pr][half]);
                }
            }
        }

        if (kt + 2 < nt) {
            __syncthreads();
            load_stage(kt + 2, (kt + 2) % NSTAGE);
        }
    }

    // ---- epilogue ----
    int r4 = lane >> 2, c2 = (lane & 3) * 2;
    #pragma unroll
    for (int mi = 0; mi < 4; mi++) {
        #pragma unroll
        for (int hh = 0; hh < 2; hh++) {
            int m = bm + wm + mi*16 + r4 + hh*8;
            if (m >= M) continue;
            #pragma unroll
            for (int ni = 0; ni < 4; ni++) {
                int n0 = bn + wn + ni*8 + c2;
                #pragma unroll
                for (int t = 0; t < 2; t++) {
                    int n = n0 + t;
                    float v = acc[mi][ni][hh*2 + t];
                    if (EPI != 0) v += bias[n];
                    size_t idx = (size_t)m * N + n;
                    if (EPI == 1) v += res[idx];
                    if (EPI == 2) v = 0.5f * v * (1.0f + erff(v * 0.7071067811865476f));
                    if (SPLIT) {
                        __nv_bfloat16 h, l;
                        split2(v, h, l);
                        Ch[idx] = h; Cl[idx] = l;
                    } else {
                        Cf[idx] = v;
                    }
                }
            }
        }
    }
}

// ---------------- cls global attention: 1 block per (b,h) ----------------
__global__ void __launch_bounds__(256) cls_attn_kernel(const float* __restrict__ qkv,
                                                       const float* __restrict__ h1,
                                                       float* __restrict__ cls,
                                                       __nv_bfloat16* __restrict__ yh,
                                                       __nv_bfloat16* __restrict__ yl)
{
    __shared__ float sq[64];
    __shared__ float sc[NN];
    __shared__ float red[256];
    __shared__ float so[4][64];

    int bh = blockIdx.x;
    int b = bh / HH, h = bh % HH;
    int tid = threadIdx.x;

    const float* qbase = qkv + (size_t)(b * NN) * (3*CC) + h * HD;
    if (tid < 64) sq[tid] = qbase[tid];
    __syncthreads();

    float lmax = -1e30f;
    for (int i = tid; i < NN; i += 256) {
        const float* kr = qkv + (size_t)(b * NN + i) * (3*CC) + CC + h * HD;
        float s = 0.0f;
        #pragma unroll 16
        for (int d = 0; d < 64; d++) s = fmaf(sq[d], kr[d], s);
        s *= SCALE;
        sc[i] = s;
        lmax = fmaxf(lmax, s);
    }
    red[tid] = lmax; __syncthreads();
    for (int off = 128; off; off >>= 1) {
        if (tid < off) red[tid] = fmaxf(red[tid], red[tid + off]);
        __syncthreads();
    }
    float m = red[0];
    __syncthreads();

    float lsum = 0.0f;
    for (int i = tid; i < NN; i += 256) {
        float e = __expf(sc[i] - m);
        sc[i] = e;
        lsum += e;
    }
    red[tid] = lsum; __syncthreads();
    for (int off = 128; off; off >>= 1) {
        if (tid < off) red[tid] += red[tid + off];
        __syncthreads();
    }
    float l = red[0];
    __syncthreads();

    int d = tid & 63, part = tid >> 6;
    float o = 0.0f;
    for (int i = part; i < NN; i += 4)
        o = fmaf(sc[i], qkv[(size_t)(b * NN + i) * (3*CC) + 2*CC + h * HD + d], o);
    so[part][d] = o;
    __syncthreads();

    if (tid < 64) {
        float val = (so[0][tid] + so[1][tid] + so[2][tid] + so[3][tid]) / l;
        size_t off0 = (size_t)(b * NN) * CC + h * HD + tid;
        float v = val + h1[off0];
        cls[b * CC + h * HD + tid] = v;
        __nv_bfloat16 hi, lo;
        split2(v, hi, lo);
        yh[off0] = hi; yl[off0] = lo;
    }
}

// ---------------- cls qkv ----------------
__global__ void __launch_bounds__(256) cls_qkv_kernel(const float* __restrict__ cls,
                                                      const float* __restrict__ qkv_w,
                                                      float* __restrict__ qkvc)
{
    int j = blockIdx.x;
    int w = threadIdx.x >> 5;
    int lane = threadIdx.x & 31;
    const float* cr = cls + (size_t)w * CC;
    const float* wr = qkv_w + (size_t)j * CC;
    float s = 0.0f;
    for (int k = lane; k < CC; k += 32) s = fmaf(cr[k], wr[k], s);
    #pragma unroll
    for (int off = 16; off; off >>= 1) s += __shfl_xor_sync(0xffffffffu, s, off);
    if (lane == 0) qkvc[w * (3*CC) + j] = s;
}

// ---------------- branch attention ----------------
#define AS 68

__global__ void __launch_bounds__(256) branch_attn_kernel(const float* __restrict__ qkv,
                                                          const float* __restrict__ qkvc,
                                                          __nv_bfloat16* __restrict__ yh,
                                                          __nv_bfloat16* __restrict__ yl)
{
    extern __shared__ float smem[];
    float* Qs = smem;
    float* Ks = Qs + 64 * AS;
    float* Vs = Ks + 64 * AS;
    float* Ps = Vs + 64 * AS;

    int tid = threadIdx.x;
    int tx = tid & 15;
    int ty = tid >> 4;
    int qt = blockIdx.x;
    int nb = blockIdx.y;
    int b = blockIdx.z / HH, h = blockIdx.z % HH;

    {
        int q  = tid >> 2;
        int dg = (tid & 3) * 16;
        int token = 1 + nb * SPB + qt * 64 + q;
        const float* src = qkv + (size_t)(b * NN + token) * (3*CC) + h * HD + dg;
        #pragma unroll
        for (int ii = 0; ii < 4; ii++) {
            float4 v = *(const float4*)(src + ii * 4);
            int d = dg + ii * 4;
            Qs[(d+0)*AS + q] = v.x; Qs[(d+1)*AS + q] = v.y;
            Qs[(d+2)*AS + q] = v.z; Qs[(d+3)*AS + q] = v.w;
        }
    }

    float m[4], l[4], o[4][4];
    #pragma unroll
    for (int i = 0; i < 4; i++) {
        m[i] = -1e30f; l[i] = 0.0f;
        #pragma unroll
        for (int j = 0; j < 4; j++) o[i][j] = 0.0f;
    }

    for (int kt = 0; kt < 9; kt++) {
        {
            int key = tid >> 2;
            int dg  = (tid & 3) * 16;
            int jg  = kt * 64 + key;
            bool valid = jg < (SPB + 1);
            const float *ksrc = nullptr, *vsrc = nullptr;
            if (valid) {
                if (jg == 0) {
                    ksrc = qkvc + b * (3*CC) + CC   + h * HD + dg;
                    vsrc = qkvc + b * (3*CC) + 2*CC + h * HD + dg;
                } else {
                    int token = nb * SPB + jg;
                    size_t roff = (size_t)(b * NN + token) * (3*CC) + h * HD + dg;
                    ksrc = qkv + roff + CC;
                    vsrc = qkv + roff + 2*CC;
                }
            }
            #pragma unroll
            for (int ii = 0; ii < 4; ii++) {
                float4 kv = valid ? *(const float4*)(ksrc + ii*4) : make_float4(0.f,0.f,0.f,0.f);
                float4 vv = valid ? *(const float4*)(vsrc + ii*4) : make_float4(0.f,0.f,0.f,0.f);
                int d = dg + ii * 4;
                Ks[(d+0)*AS + key] = kv.x; Ks[(d+1)*AS + key] = kv.y;
                Ks[(d+2)*AS + key] = kv.z; Ks[(d+3)*AS + key] = kv.w;
                *(float4*)&Vs[key * AS + d] = vv;
            }
        }
        __syncthreads();

        float s[4][4];
        #pragma unroll
        for (int i = 0; i < 4; i++)
            #pragma unroll
            for (int j = 0; j < 4; j++) s[i][j] = 0.0f;

        #pragma unroll 16
        for (int d = 0; d < 64; d++) {
            float4 aq = *(const float4*)&Qs[d*AS + ty*4];
            float4 bk = *(const float4*)&Ks[d*AS + tx*4];
            float a[4] = {aq.x, aq.y, aq.z, aq.w};
            float bb[4] = {bk.x, bk.y, bk.z, bk.w};
            #pragma unroll
            for (int i = 0; i < 4; i++)
                #pragma unroll
                for (int j = 0; j < 4; j++)
                    s[i][j] = fmaf(a[i], bb[j], s[i][j]);
        }

        #pragma unroll
        for (int i = 0; i < 4; i++)
            #pragma unroll
            for (int j = 0; j < 4; j++) {
                s[i][j] *= SCALE;
                if (kt * 64 + tx * 4 + j >= (SPB + 1)) s[i][j] = -1e30f;
            }

        #pragma unroll
        for (int i = 0; i < 4; i++) {
            float mt = fmaxf(fmaxf(s[i][0], s[i][1]), fmaxf(s[i][2], s[i][3]));
            #pragma unroll
            for (int off = 8; off; off >>= 1)
                mt = fmaxf(mt, __shfl_xor_sync(0xffffffffu, mt, off));
            float mnew = fmaxf(m[i], mt);
            float alpha = __expf(m[i] - mnew);
            m[i] = mnew;
            float rs = 0.0f;
            #pragma unroll
            for (int j = 0; j < 4; j++) {
                s[i][j] = __expf(s[i][j] - mnew);
                rs += s[i][j];
            }
            #pragma unroll
            for (int off = 8; off; off >>= 1)
                rs += __shfl_xor_sync(0xffffffffu, rs, off);
            l[i] = l[i] * alpha + rs;
            #pragma unroll
            for (int j = 0; j < 4; j++) {
                o[i][j] *= alpha;
                Ps[(tx*4 + j)*AS + ty*4 + i] = s[i][j];
            }
        }
        __syncthreads();

        #pragma unroll 16
        for (int k = 0; k < 64; k++) {
            float4 ap = *(const float4*)&Ps[k*AS + ty*4];
            float4 bv = *(const float4*)&Vs[k*AS + tx*4];
            float a[4] = {ap.x, ap.y, ap.z, ap.w};
            float bb[4] = {bv.x, bv.y, bv.z, bv.w};
            #pragma unroll
            for (int i = 0; i < 4; i++)
                #pragma unroll
                for (int j = 0; j < 4; j++)
                    o[i][j] = fmaf(a[i], bb[j], o[i][j]);
        }
        __syncthreads();
    }

    #pragma unroll
    for (int i = 0; i < 4; i++) {
        int sp = qt * 64 + ty * 4 + i;
        float inv_l = 1.0f / l[i];
        #pragma unroll
        for (int j = 0; j < 4; j++) {
            int dp = tx * 4 + j;
            int linear = h * (SPB * HD) + sp * HD + dp;
            int s_ = linear / CC;
            int c  = linear - s_ * CC;
            int token = 1 + nb * SPB + s_;
            float v = o[i][j] * inv_l;
            __nv_bfloat16 hi, lo;
            split2(v, hi, lo);
            size_t idx = (size_t)(b * NN + token) * CC + c;
            yh[idx] = hi; yl[idx] = lo;
        }
    }
}

// ---------------- launch ----------------
extern "C" void kernel_launch(void* const* d_in, const int* in_sizes, int n_in,
                              void* d_out, int out_size)
{
    const float* x      = (const float*)d_in[0];
    const float* ln1_w  = (const float*)d_in[1];
    const float* ln1_b  = (const float*)d_in[2];
    const float* qkv_w  = (const float*)d_in[3];
    const float* proj_w = (const float*)d_in[4];
    const float* proj_b = (const float*)d_in[5];
    const float* ln2_w  = (const float*)d_in[6];
    const float* ln2_b  = (const float*)d_in[7];
    const float* fc1_w  = (const float*)d_in[8];
    const float* fc1_b  = (const float*)d_in[9];
    const float* fc2_w  = (const float*)d_in[10];
    const float* fc2_b  = (const float*)d_in[11];
    float* out = (float*)d_out;

    float *h1f, *qkv, *qkvc, *cls, *x2;
    __nv_bfloat16 *h1h, *h1l, *yh, *yl, *h2h, *h2l, *f1h, *f1l;
    __nv_bfloat16 *wqh, *wql, *wph, *wpl, *w1h, *w1l, *w2h, *w2l;
    cudaGetSymbolAddress((void**)&h1f,  g_h1f);
    cudaGetSymbolAddress((void**)&h1h,  g_h1h);
    cudaGetSymbolAddress((void**)&h1l,  g_h1l);
    cudaGetSymbolAddress((void**)&qkv,  g_qkv);
    cudaGetSymbolAddress((void**)&qkvc, g_qkvc);
    cudaGetSymbolAddress((void**)&cls,  g_cls);
    cudaGetSymbolAddress((void**)&yh,   g_yh);
    cudaGetSymbolAddress((void**)&yl,   g_yl);
    cudaGetSymbolAddress((void**)&x2,   g_x2);
    cudaGetSymbolAddress((void**)&h2h,  g_h2h);
    cudaGetSymbolAddress((void**)&h2l,  g_h2l);
    cudaGetSymbolAddress((void**)&f1h,  g_f1h);
    cudaGetSymbolAddress((void**)&f1l,  g_f1l);
    cudaGetSymbolAddress((void**)&wqh,  g_wqh);
    cudaGetSymbolAddress((void**)&wql,  g_wql);
    cudaGetSymbolAddress((void**)&wph,  g_wph);
    cudaGetSymbolAddress((void**)&wpl,  g_wpl);
    cudaGetSymbolAddress((void**)&w1h,  g_w1h);
    cudaGetSymbolAddress((void**)&w1l,  g_w1l);
    cudaGetSymbolAddress((void**)&w2h,  g_w2h);
    cudaGetSymbolAddress((void**)&w2l,  g_w2l);

    const int M = MROWS;
    const int tc_smem = NSTAGE * STAGE_B + 128;   // 196736
    cudaFuncSetAttribute(tc_gemm<0,false>, cudaFuncAttributeMaxDynamicSharedMemorySize, tc_smem);
    cudaFuncSetAttribute(tc_gemm<1,false>, cudaFuncAttributeMaxDynamicSharedMemorySize, tc_smem);
    cudaFuncSetAttribute(tc_gemm<2,true >, cudaFuncAttributeMaxDynamicSharedMemorySize, tc_smem);

    // 0. split weights
    split_kernel<<<(3*CC*CC + 255)/256, 256>>>(qkv_w,  wqh, wql, 3*CC*CC);
    split_kernel<<<(CC*CC   + 255)/256, 256>>>(proj_w, wph, wpl, CC*CC);
    split_kernel<<<(4*CC*CC + 255)/256, 256>>>(fc1_w,  w1h, w1l, 4*CC*CC);
    split_kernel<<<(4*CC*CC + 255)/256, 256>>>(fc2_w,  w2h, w2l, 4*CC*CC);

    // 1. LN1 -> h1 (cls-row fp32 + full split)
    ln_kernel<<<M, 256>>>(x, ln1_w, ln1_b, h1f, h1h, h1l);

    // 2. qkv = h1 @ qkv_w^T  (fp32 out)
    {
        dim3 grid((3*CC)/128, MPAD/128);
        tc_gemm<0,false><<<grid, 256, tc_smem>>>(h1h, h1l, wqh, wql,
            nullptr, nullptr, qkv, nullptr, nullptr, M, 3*CC, CC);
    }

    // 3. cls global attention
    cls_attn_kernel<<<BB*HH, 256>>>(qkv, h1f, cls, yh, yl);

    // 4. cls qkv
    cls_qkv_kernel<<<3*CC, 256>>>(cls, qkv_w, qkvc);

    // 5. branch attention
    {
        size_t smem = 4 * 64 * AS * sizeof(float);
        cudaFuncSetAttribute(branch_attn_kernel,
                             cudaFuncAttributeMaxDynamicSharedMemorySize, (int)smem);
        dim3 grid(8, NBB, BB*HH);
        branch_attn_kernel<<<grid, 256, smem>>>(qkv, qkvc, yh, yl);
    }

    // 6. x2 = x + y @ proj_w^T + proj_b
    {
        dim3 grid(CC/128, MPAD/128);
        tc_gemm<1,false><<<grid, 256, tc_smem>>>(yh, yl, wph, wpl,
            proj_b, x, x2, nullptr, nullptr, M, CC, CC);
    }

    // 7. LN2 -> h2 split
    ln_kernel<<<M, 256>>>(x2, ln2_w, ln2_b, nullptr, h2h, h2l);

    // 8. fc1 + gelu -> split
    {
        dim3 grid((4*CC)/128, MPAD/128);
        tc_gemm<2,true><<<grid, 256, tc_smem>>>(h2h, h2l, w1h, w1l,
            fc1_b, nullptr, nullptr, f1h, f1l, M, 4*CC, CC);
    }

    // 9. out = x2 + fc1g @ fc2_w^T + fc2_b
    {
        dim3 grid(CC/128, MPAD/128);
        tc_gemm<1,false><<<grid, 256, tc_smem>>>(f1h, f1l, w2h, w2l,
            fc2_b, x2, out, nullptr, nullptr, M, CC, 4*CC);
    }
}

// round 5
// speedup vs baseline: 1.9814x; 1.1462x over previous
#include <cuda_runtime.h>
#include <cuda_bf16.h>
#include <math.h>
#include <stdint.h>

// ---------------- problem constants ----------------
#define BB   8
#define NN   2049
#define CC   768
#define HH   12
#define NBB  4
#define HD   64
#define SPB  512
#define MROWS (BB*NN)      // 16392
#define MPAD  16512        // 129 * 128
#define SCALE 0.125f
#define LNEPS 1e-6f

// ---------------- scratch ----------------
__device__ float g_h1f [(size_t)MROWS * CC];
__device__ __nv_bfloat16 g_h1h[(size_t)MPAD * CC];
__device__ __nv_bfloat16 g_h1l[(size_t)MPAD * CC];
__device__ float g_qkv [(size_t)MROWS * 3 * CC];
__device__ __nv_bfloat16 g_qkvh[(size_t)MROWS * 3 * CC];
__device__ __nv_bfloat16 g_qkvl[(size_t)MROWS * 3 * CC];
__device__ float g_qkvc[BB * 3 * CC];
__device__ __nv_bfloat16 g_qkvch[BB * 3 * CC];
__device__ __nv_bfloat16 g_qkvcl[BB * 3 * CC];
__device__ float g_cls [BB * CC];
__device__ __nv_bfloat16 g_yh [(size_t)MPAD * CC];
__device__ __nv_bfloat16 g_yl [(size_t)MPAD * CC];
__device__ float g_x2  [(size_t)MROWS * CC];
__device__ __nv_bfloat16 g_h2h[(size_t)MPAD * CC];
__device__ __nv_bfloat16 g_h2l[(size_t)MPAD * CC];
__device__ __nv_bfloat16 g_f1h[(size_t)MPAD * 4 * CC];
__device__ __nv_bfloat16 g_f1l[(size_t)MPAD * 4 * CC];
__device__ __nv_bfloat16 g_wqh[3*CC*CC], g_wql[3*CC*CC];
__device__ __nv_bfloat16 g_wph[CC*CC],   g_wpl[CC*CC];
__device__ __nv_bfloat16 g_w1h[4*CC*CC], g_w1l[4*CC*CC];
__device__ __nv_bfloat16 g_w2h[4*CC*CC], g_w2l[4*CC*CC];

// ---------------- helpers ----------------
__device__ __forceinline__ void split2(float v, __nv_bfloat16& h, __nv_bfloat16& l) {
    h = __float2bfloat16(v);
    l = __float2bfloat16(v - __bfloat162float(h));
}
__device__ __forceinline__ uint32_t smem_u32(const void* p) {
    return (uint32_t)__cvta_generic_to_shared(p);
}
__device__ __forceinline__ void cp16(uint32_t saddr, const void* g) {
    asm volatile("cp.async.cg.shared.global [%0], [%1], 16;\n" :: "r"(saddr), "l"(g));
}
__device__ __forceinline__ void cp_commit() { asm volatile("cp.async.commit_group;\n"); }
template<int NW> __device__ __forceinline__ void cp_wait() {
    asm volatile("cp.async.wait_group %0;\n" :: "n"(NW));
}
__device__ __forceinline__ void ldsm4(uint32_t addr, uint32_t& r0, uint32_t& r1,
                                      uint32_t& r2, uint32_t& r3) {
    asm volatile("ldmatrix.sync.aligned.m8n8.x4.shared.b16 {%0,%1,%2,%3}, [%4];"
                 : "=r"(r0), "=r"(r1), "=r"(r2), "=r"(r3) : "r"(addr));
}
__device__ __forceinline__ void ldsm4t(uint32_t addr, uint32_t& r0, uint32_t& r1,
                                       uint32_t& r2, uint32_t& r3) {
    asm volatile("ldmatrix.sync.aligned.m8n8.x4.trans.shared.b16 {%0,%1,%2,%3}, [%4];"
                 : "=r"(r0), "=r"(r1), "=r"(r2), "=r"(r3) : "r"(addr));
}
__device__ __forceinline__ void mma16816(float* c, const uint32_t* a, const uint32_t* b) {
    asm volatile("mma.sync.aligned.m16n8k16.row.col.f32.bf16.bf16.f32 "
        "{%0,%1,%2,%3}, {%4,%5,%6,%7}, {%8,%9}, {%0,%1,%2,%3};"
        : "+f"(c[0]), "+f"(c[1]), "+f"(c[2]), "+f"(c[3])
        : "r"(a[0]), "r"(a[1]), "r"(a[2]), "r"(a[3]), "r"(b[0]), "r"(b[1]));
}
__device__ __forceinline__ void packsplit2(float a, float b, uint32_t& ph, uint32_t& pl) {
    __nv_bfloat16 ah, al, bh, bl;
    split2(a, ah, al); split2(b, bh, bl);
    ph = (uint32_t)__bfloat16_as_ushort(ah) | ((uint32_t)__bfloat16_as_ushort(bh) << 16);
    pl = (uint32_t)__bfloat16_as_ushort(al) | ((uint32_t)__bfloat16_as_ushort(bl) << 16);
}

__global__ void __launch_bounds__(256) split_kernel(const float* __restrict__ in,
                                                    __nv_bfloat16* __restrict__ oh,
                                                    __nv_bfloat16* __restrict__ ol, int n)
{
    int i = blockIdx.x * 256 + threadIdx.x;
    if (i < n) {
        __nv_bfloat16 h, l;
        split2(in[i], h, l);
        oh[i] = h; ol[i] = l;
    }
}

// ---------------- LayerNorm: warp per row ----------------
__global__ void __launch_bounds__(256) ln_kernel(const float* __restrict__ x,
                                                 const float* __restrict__ w,
                                                 const float* __restrict__ b,
                                                 float* __restrict__ outf,
                                                 __nv_bfloat16* __restrict__ oh,
                                                 __nv_bfloat16* __restrict__ ol,
                                                 int rows)
{
    int row = blockIdx.x * 8 + (threadIdx.x >> 5);
    if (row >= rows) return;
    int lane = threadIdx.x & 31;
    const float4* xr = (const float4*)(x + (size_t)row * CC);

    float4 v[6];
    float s = 0.0f;
    #pragma unroll
    for (int i = 0; i < 6; i++) {
        v[i] = xr[i * 32 + lane];
        s += v[i].x + v[i].y + v[i].z + v[i].w;
    }
    #pragma unroll
    for (int o = 16; o; o >>= 1) s += __shfl_xor_sync(0xffffffffu, s, o);
    float mu = s * (1.0f / CC);

    float q = 0.0f;
    #pragma unroll
    for (int i = 0; i < 6; i++) {
        v[i].x -= mu; v[i].y -= mu; v[i].z -= mu; v[i].w -= mu;
        q += v[i].x*v[i].x + v[i].y*v[i].y + v[i].z*v[i].z + v[i].w*v[i].w;
    }
    #pragma unroll
    for (int o = 16; o; o >>= 1) q += __shfl_xor_sync(0xffffffffu, q, o);
    float rs = rsqrtf(q * (1.0f / CC) + LNEPS);

    const float4* w4 = (const float4*)w;
    const float4* b4 = (const float4*)b;
    uint2* oh2 = (uint2*)(oh + (size_t)row * CC);
    uint2* ol2 = (uint2*)(ol + (size_t)row * CC);
    bool wf = (outf != nullptr) && (row % NN) == 0;
    float4* of4 = wf ? (float4*)(outf + (size_t)row * CC) : nullptr;

    #pragma unroll
    for (int i = 0; i < 6; i++) {
        float4 wv = w4[i * 32 + lane], bv = b4[i * 32 + lane];
        float o0 = v[i].x * rs * wv.x + bv.x;
        float o1 = v[i].y * rs * wv.y + bv.y;
        float o2 = v[i].z * rs * wv.z + bv.z;
        float o3 = v[i].w * rs * wv.w + bv.w;
        uint32_t h01, l01, h23, l23;
        packsplit2(o0, o1, h01, l01);
        packsplit2(o2, o3, h23, l23);
        oh2[i * 32 + lane] = make_uint2(h01, h23);
        ol2[i * 32 + lane] = make_uint2(l01, l23);
        if (wf) of4[i * 32 + lane] = make_float4(o0, o1, o2, o3);
    }
}

// ================= bf16x3 mma.sync GEMM =================
// EPI: 0 none, 1 bias+residual, 2 bias+gelu. OUTM: 0 f32, 1 split, 2 both.
#define TILE_B   16384
#define STAGE_B  (4*TILE_B)
#define NSTAGE   3

template<int EPI, int OUTM>
__global__ void __launch_bounds__(256, 1) tc_gemm(
    const __nv_bfloat16* __restrict__ Ah, const __nv_bfloat16* __restrict__ Al,
    const __nv_bfloat16* __restrict__ Wh, const __nv_bfloat16* __restrict__ Wl,
    const float* __restrict__ bias, const float* __restrict__ res,
    float* __restrict__ Cf, __nv_bfloat16* __restrict__ Ch, __nv_bfloat16* __restrict__ Cl,
    int M, int N, int K)
{
    extern __shared__ char dynraw[];
    uint32_t raw = smem_u32(dynraw);
    uint32_t smb = (raw + 127) & ~127u;

    const int tid = threadIdx.x;
    const int bn = blockIdx.x * 128, bm = blockIdx.y * 128;
    const int nt = K >> 6;
    const int lane = tid & 31, wid = tid >> 5;
    const int wm = (wid & 1) * 64, wn = (wid >> 1) * 32;
    const int r8 = lane & 7, sub = lane >> 3;

    const int lrow = tid >> 1;
    const int c0 = (tid & 1) * 4;

    auto load_stage = [&](int kt, int s) {
        uint32_t sb = smb + s * STAGE_B;
        size_t goff = (size_t)(kt * 64 + c0 * 8);
        const __nv_bfloat16* gAh = Ah + (size_t)(bm + lrow) * K + goff;
        const __nv_bfloat16* gAl = Al + (size_t)(bm + lrow) * K + goff;
        const __nv_bfloat16* gWh = Wh + (size_t)(bn + lrow) * K + goff;
        const __nv_bfloat16* gWl = Wl + (size_t)(bn + lrow) * K + goff;
        uint32_t ro = lrow * 128;
        #pragma unroll
        for (int c = 0; c < 4; c++) {
            int chunk = c0 + c;
            uint32_t sw = ro + (uint32_t)((chunk ^ (lrow & 7)) << 4);
            cp16(sb            + sw, gAh + c*8);
            cp16(sb +   TILE_B + sw, gAl + c*8);
            cp16(sb + 2*TILE_B + sw, gWh + c*8);
            cp16(sb + 3*TILE_B + sw, gWl + c*8);
        }
        cp_commit();
    };

    float acc[4][4][4];
    #pragma unroll
    for (int i = 0; i < 4; i++)
        #pragma unroll
        for (int j = 0; j < 4; j++)
            #pragma unroll
            for (int t = 0; t < 4; t++) acc[i][j][t] = 0.0f;

    uint32_t aRowBase[4]; int aKey[4];
    #pragma unroll
    for (int mi = 0; mi < 4; mi++) {
        int row = wm + mi*16 + ((sub & 1) << 3) + r8;
        aRowBase[mi] = row * 128;
        aKey[mi] = row & 7;
    }
    const int aChunkOff = sub >> 1;
    uint32_t bRowBase[2]; int bKey[2];
    #pragma unroll
    for (int pr = 0; pr < 2; pr++) {
        int row = wn + pr*16 + ((sub >> 1) << 3) + r8;
        bRowBase[pr] = row * 128;
        bKey[pr] = row & 7;
    }
    const int bChunkOff = sub & 1;

    load_stage(0, 0);
    load_stage(1, 1);

    for (int kt = 0; kt < nt; kt++) {
        if (kt + 1 < nt) cp_wait<1>(); else cp_wait<0>();
        __syncthreads();

        uint32_t sb = smb + (kt % NSTAGE) * STAGE_B;

        #pragma unroll
        for (int kk = 0; kk < 4; kk++) {
            uint32_t Bh[2][4], Bl[2][4];
            #pragma unroll
            for (int pr = 0; pr < 2; pr++) {
                int chunk = kk*2 + bChunkOff;
                uint32_t ad = sb + 2*TILE_B + bRowBase[pr]
                            + (uint32_t)((chunk ^ bKey[pr]) << 4);
                ldsm4(ad,          Bh[pr][0], Bh[pr][1], Bh[pr][2], Bh[pr][3]);
                ldsm4(ad + TILE_B, Bl[pr][0], Bl[pr][1], Bl[pr][2], Bl[pr][3]);
            }
            #pragma unroll
            for (int mi = 0; mi < 4; mi++) {
                int chunk = kk*2 + aChunkOff;
                uint32_t ad = sb + aRowBase[mi]
                            + (uint32_t)((chunk ^ aKey[mi]) << 4);
                uint32_t Af[4], Alf[4];
                ldsm4(ad,          Af[0],  Af[1],  Af[2],  Af[3]);
                ldsm4(ad + TILE_B, Alf[0], Alf[1], Alf[2], Alf[3]);
                #pragma unroll
                for (int ni = 0; ni < 4; ni++) {
                    int pr = ni >> 1, half = (ni & 1) * 2;
                    mma16816(acc[mi][ni], Af,  &Bh[pr][half]);
                    mma16816(acc[mi][ni], Af,  &Bl[pr][half]);
                    mma16816(acc[mi][ni], Alf, &Bh[pr][half]);
                }
            }
        }

        if (kt + 2 < nt) {
            __syncthreads();
            load_stage(kt + 2, (kt + 2) % NSTAGE);
        }
    }

    int r4 = lane >> 2, c2 = (lane & 3) * 2;
    #pragma unroll
    for (int mi = 0; mi < 4; mi++) {
        #pragma unroll
        for (int hh = 0; hh < 2; hh++) {
            int m = bm + wm + mi*16 + r4 + hh*8;
            if (m >= M) continue;
            #pragma unroll
            for (int ni = 0; ni < 4; ni++) {
                int n0 = bn + wn + ni*8 + c2;
                #pragma unroll
                for (int t = 0; t < 2; t++) {
                    int n = n0 + t;
                    float v = acc[mi][ni][hh*2 + t];
                    if (EPI != 0) v += bias[n];
                    size_t idx = (size_t)m * N + n;
                    if (EPI == 1) v += res[idx];
                    if (EPI == 2) v = 0.5f * v * (1.0f + erff(v * 0.7071067811865476f));
                    if (OUTM == 0) {
                        Cf[idx] = v;
                    } else if (OUTM == 1) {
                        __nv_bfloat16 h, l;
                        split2(v, h, l);
                        Ch[idx] = h; Cl[idx] = l;
                    } else {
                        Cf[idx] = v;
                        __nv_bfloat16 h, l;
                        split2(v, h, l);
                        Ch[idx] = h; Cl[idx] = l;
                    }
                }
            }
        }
    }
}

// ---------------- cls global attention ----------------
__global__ void __launch_bounds__(256) cls_attn_kernel(const float* __restrict__ qkv,
                                                       const float* __restrict__ h1,
                                                       float* __restrict__ cls,
                                                       __nv_bfloat16* __restrict__ yh,
                                                       __nv_bfloat16* __restrict__ yl)
{
    __shared__ float sq[64];
    __shared__ float sc[NN];
    __shared__ float red[256];
    __shared__ float so[4][64];

    int bh = blockIdx.x;
    int b = bh / HH, h = bh % HH;
    int tid = threadIdx.x;

    const float* qbase = qkv + (size_t)(b * NN) * (3*CC) + h * HD;
    if (tid < 64) sq[tid] = qbase[tid];
    __syncthreads();

    float lmax = -1e30f;
    for (int i = tid; i < NN; i += 256) {
        const float* kr = qkv + (size_t)(b * NN + i) * (3*CC) + CC + h * HD;
        float s = 0.0f;
        #pragma unroll 16
        for (int d = 0; d < 64; d++) s = fmaf(sq[d], kr[d], s);
        s *= SCALE;
        sc[i] = s;
        lmax = fmaxf(lmax, s);
    }
    red[tid] = lmax; __syncthreads();
    for (int off = 128; off; off >>= 1) {
        if (tid < off) red[tid] = fmaxf(red[tid], red[tid + off]);
        __syncthreads();
    }
    float m = red[0];
    __syncthreads();

    float lsum = 0.0f;
    for (int i = tid; i < NN; i += 256) {
        float e = __expf(sc[i] - m);
        sc[i] = e;
        lsum += e;
    }
    red[tid] = lsum; __syncthreads();
    for (int off = 128; off; off >>= 1) {
        if (tid < off) red[tid] += red[tid + off];
        __syncthreads();
    }
    float l = red[0];
    __syncthreads();

    int d = tid & 63, part = tid >> 6;
    float o = 0.0f;
    for (int i = part; i < NN; i += 4)
        o = fmaf(sc[i], qkv[(size_t)(b * NN + i) * (3*CC) + 2*CC + h * HD + d], o);
    so[part][d] = o;
    __syncthreads();

    if (tid < 64) {
        float val = (so[0][tid] + so[1][tid] + so[2][tid] + so[3][tid]) / l;
        size_t off0 = (size_t)(b * NN) * CC + h * HD + tid;
        float v = val + h1[off0];
        cls[b * CC + h * HD + tid] = v;
        __nv_bfloat16 hi, lo;
        split2(v, hi, lo);
        yh[off0] = hi; yl[off0] = lo;
    }
}

// ---------------- cls qkv ----------------
__global__ void __launch_bounds__(256) cls_qkv_kernel(const float* __restrict__ cls,
                                                      const float* __restrict__ qkv_w,
                                                      float* __restrict__ qkvc,
                                                      __nv_bfloat16* __restrict__ qkvch,
                                                      __nv_bfloat16* __restrict__ qkvcl)
{
    int j = blockIdx.x;
    int w = threadIdx.x >> 5;
    int lane = threadIdx.x & 31;
    const float* cr = cls + (size_t)w * CC;
    const float* wr = qkv_w + (size_t)j * CC;
    float s = 0.0f;
    for (int k = lane; k < CC; k += 32) s = fmaf(cr[k], wr[k], s);
    #pragma unroll
    for (int off = 16; off; off >>= 1) s += __shfl_xor_sync(0xffffffffu, s, off);
    if (lane == 0) {
        qkvc[w * (3*CC) + j] = s;
        __nv_bfloat16 h, l;
        split2(s, h, l);
        qkvch[w * (3*CC) + j] = h;
        qkvcl[w * (3*CC) + j] = l;
    }
}

// ---------------- branch attention (FA2 mma) ----------------
// grid (8, 4, 96), 128 threads (4 warps x 16 queries). 64 q x 513 keys x 64 d.
#define BQH 0
#define BQL 8192
#define BKH 16384
#define BKL 24576
#define BVH 32768
#define BVL 40960

__global__ void __launch_bounds__(128) branch_attn_kernel(
    const __nv_bfloat16* __restrict__ qkvh, const __nv_bfloat16* __restrict__ qkvl,
    const __nv_bfloat16* __restrict__ qkvch, const __nv_bfloat16* __restrict__ qkvcl,
    __nv_bfloat16* __restrict__ yh, __nv_bfloat16* __restrict__ yl)
{
    extern __shared__ char dynraw[];
    uint32_t raw = smem_u32(dynraw);
    uint32_t smb = (raw + 127) & ~127u;

    const int tid = threadIdx.x;
    const int lane = tid & 31, wid = tid >> 5;
    const int r8 = lane & 7, sub = lane >> 3;
    const int qt = blockIdx.x, nb = blockIdx.y;
    const int b = blockIdx.z / HH, h = blockIdx.z % HH;

    // ---- load Q tile (64 rows x 128B, h & l) ----
    {
        int qrow = tid >> 1;
        int ch0 = (tid & 1) * 4;
        int token = 1 + nb * SPB + qt * 64 + qrow;
        size_t rb = (size_t)(b * NN + token) * (3*CC) + h * HD;
        const __nv_bfloat16* gh = qkvh + rb;
        const __nv_bfloat16* gl = qkvl + rb;
        uint32_t ro = qrow * 128;
        #pragma unroll
        for (int c = 0; c < 4; c++) {
            int chunk = ch0 + c;
            uint32_t sw = ro + (uint32_t)((chunk ^ (qrow & 7)) << 4);
            cp16(smb + BQH + sw, gh + chunk*8);
            cp16(smb + BQL + sw, gl + chunk*8);
        }
        cp_commit();
    }

    float m0 = -1e30f, m1 = -1e30f, l0 = 0.0f, l1 = 0.0f;
    float oreg[8][4];
    #pragma unroll
    for (int i = 0; i < 8; i++)
        #pragma unroll
        for (int t = 0; t < 4; t++) oreg[i][t] = 0.0f;

    const int kr = tid >> 1;
    const int ch0 = (tid & 1) * 4;
    const uint32_t kro = kr * 128;

    for (int kt = 0; kt < 9; kt++) {
        __syncthreads();
        // ---- load K/V tile (h & l) ----
        {
            int jg = kt * 64 + kr;
            int jc = jg > 512 ? 512 : jg;
            const __nv_bfloat16 *kh_s, *kl_s, *vh_s, *vl_s;
            if (jc == 0) {
                size_t rb = (size_t)b * (3*CC) + h * HD;
                kh_s = qkvch + rb + CC;  kl_s = qkvcl + rb + CC;
                vh_s = qkvch + rb + 2*CC; vl_s = qkvcl + rb + 2*CC;
            } else {
                int token = nb * SPB + jc;
                size_t rb = (size_t)(b * NN + token) * (3*CC) + h * HD;
                kh_s = qkvh + rb + CC;   kl_s = qkvl + rb + CC;
                vh_s = qkvh + rb + 2*CC; vl_s = qkvl + rb + 2*CC;
            }
            #pragma unroll
            for (int c = 0; c < 4; c++) {
                int chunk = ch0 + c;
                uint32_t sw = kro + (uint32_t)((chunk ^ (kr & 7)) << 4);
                cp16(smb + BKH + sw, kh_s + chunk*8);
                cp16(smb + BKL + sw, kl_s + chunk*8);
                cp16(smb + BVH + sw, vh_s + chunk*8);
                cp16(smb + BVL + sw, vl_s + chunk*8);
            }
            cp_commit();
        }
        cp_wait<0>();
        __syncthreads();

        // ---- S = Q K^T (bf16x3) ----
        float sreg[8][4];
        #pragma unroll
        for (int i = 0; i < 8; i++)
            #pragma unroll
            for (int t = 0; t < 4; t++) sreg[i][t] = 0.0f;

        #pragma unroll
        for (int kk = 0; kk < 4; kk++) {
            int arow = wid*16 + ((sub & 1) << 3) + r8;
            uint32_t aad = smb + BQH + arow*128
                         + (uint32_t)(((kk*2 + (sub >> 1)) ^ (arow & 7)) << 4);
            uint32_t qh[4], ql[4];
            ldsm4(aad,               qh[0], qh[1], qh[2], qh[3]);
            ldsm4(aad + (BQL - BQH), ql[0], ql[1], ql[2], ql[3]);
            #pragma unroll
            for (int pr = 0; pr < 4; pr++) {
                int brow = pr*16 + ((sub >> 1) << 3) + r8;
                uint32_t bad = smb + BKH + brow*128
                             + (uint32_t)(((kk*2 + (sub & 1)) ^ (brow & 7)) << 4);
                uint32_t kh[4], kl[4];
                ldsm4(bad,               kh[0], kh[1], kh[2], kh[3]);
                ldsm4(bad + (BKL - BKH), kl[0], kl[1], kl[2], kl[3]);
                #pragma unroll
                for (int t2 = 0; t2 < 2; t2++) {
                    float* c = sreg[pr*2 + t2];
                    mma16816(c, qh, &kh[t2*2]);
                    mma16816(c, qh, &kl[t2*2]);
                    mma16816(c, ql, &kh[t2*2]);
                }
            }
        }

        // ---- scale + mask ----
        #pragma unroll
        for (int nt = 0; nt < 8; nt++)
            #pragma unroll
            for (int t = 0; t < 4; t++) {
                float v = sreg[nt][t] * SCALE;
                int gcol = kt*64 + nt*8 + (lane & 3)*2 + (t & 1);
                if (gcol > 512) v = -1e30f;
                sreg[nt][t] = v;
            }

        // ---- online softmax ----
        float mt0 = -1e30f, mt1 = -1e30f;
        #pragma unroll
        for (int nt = 0; nt < 8; nt++) {
            mt0 = fmaxf(mt0, fmaxf(sreg[nt][0], sreg[nt][1]));
            mt1 = fmaxf(mt1, fmaxf(sreg[nt][2], sreg[nt][3]));
        }
        mt0 = fmaxf(mt0, __shfl_xor_sync(0xffffffffu, mt0, 1));
        mt0 = fmaxf(mt0, __shfl_xor_sync(0xffffffffu, mt0, 2));
        mt1 = fmaxf(mt1, __shfl_xor_sync(0xffffffffu, mt1, 1));
        mt1 = fmaxf(mt1, __shfl_xor_sync(0xffffffffu, mt1, 2));
        float mn0 = fmaxf(m0, mt0), mn1 = fmaxf(m1, mt1);
        float a0 = __expf(m0 - mn0), a1 = __expf(m1 - mn1);
        m0 = mn0; m1 = mn1;
        float rs0 = 0.0f, rs1 = 0.0f;
        #pragma unroll
        for (int nt = 0; nt < 8; nt++) {
            sreg[nt][0] = __expf(sreg[nt][0] - mn0);
            sreg[nt][1] = __expf(sreg[nt][1] - mn0);
            sreg[nt][2] = __expf(sreg[nt][2] - mn1);
            sreg[nt][3] = __expf(sreg[nt][3] - mn1);
            rs0 += sreg[nt][0] + sreg[nt][1];
            rs1 += sreg[nt][2] + sreg[nt][3];
        }
        rs0 += __shfl_xor_sync(0xffffffffu, rs0, 1);
        rs0 += __shfl_xor_sync(0xffffffffu, rs0, 2);
        rs1 += __shfl_xor_sync(0xffffffffu, rs1, 1);
        rs1 += __shfl_xor_sync(0xffffffffu, rs1, 2);
        l0 = l0 * a0 + rs0;
        l1 = l1 * a1 + rs1;
        #pragma unroll
        for (int dt = 0; dt < 8; dt++) {
            oreg[dt][0] *= a0; oreg[dt][1] *= a0;
            oreg[dt][2] *= a1; oreg[dt][3] *= a1;
        }

        // ---- pack P into A frags (hi/lo) ----
        uint32_t ph[4][4], pl[4][4];
        #pragma unroll
        for (int kc = 0; kc < 4; kc++) {
            packsplit2(sreg[2*kc][0],   sreg[2*kc][1],   ph[kc][0], pl[kc][0]);
            packsplit2(sreg[2*kc][2],   sreg[2*kc][3],   ph[kc][1], pl[kc][1]);
            packsplit2(sreg[2*kc+1][0], sreg[2*kc+1][1], ph[kc][2], pl[kc][2]);
            packsplit2(sreg[2*kc+1][2], sreg[2*kc+1][3], ph[kc][3], pl[kc][3]);
        }

        // ---- O += P V ----
        #pragma unroll
        for (int kc = 0; kc < 4; kc++) {
            #pragma unroll
            for (int dg = 0; dg < 4; dg++) {
                int vrow = kc*16 + ((sub & 1) << 3) + r8;
                uint32_t vad = smb + BVH + vrow*128
                             + (uint32_t)(((dg*2 + (sub >> 1)) ^ (vrow & 7)) << 4);
                uint32_t vh[4], vl[4];
                ldsm4t(vad,               vh[0], vh[1], vh[2], vh[3]);
                ldsm4t(vad + (BVL - BVH), vl[0], vl[1], vl[2], vl[3]);
                #pragma unroll
                for (int t2 = 0; t2 < 2; t2++) {
                    float* c = oreg[dg*2 + t2];
                    mma16816(c, ph[kc], &vh[t2*2]);
                    mma16816(c, ph[kc], &vl[t2*2]);
                    mma16816(c, pl[kc], &vh[t2*2]);
                }
            }
        }
    }

    // ---- write out with scrambled reshape ----
    float inv0 = 1.0f / l0, inv1 = 1.0f / l1;
    int r4 = lane >> 2, c2 = (lane & 3) * 2;
    #pragma unroll
    for (int dt = 0; dt < 8; dt++) {
        #pragma unroll
        for (int t = 0; t < 4; t++) {
            int rh = t >> 1;
            int sp = qt*64 + wid*16 + r4 + rh*8;
            int dp = dt*8 + c2 + (t & 1);
            float v = oreg[dt][t] * (rh ? inv1 : inv0);
            int linear = h * (SPB * HD) + sp * HD + dp;
            int s_ = linear / CC;
            int c = linear - s_ * CC;
            int token = 1 + nb * SPB + s_;
            __nv_bfloat16 hi, lo;
            split2(v, hi, lo);
            size_t idx = (size_t)(b * NN + token) * CC + c;
            yh[idx] = hi; yl[idx] = lo;
        }
    }
}

// ---------------- launch ----------------
extern "C" void kernel_launch(void* const* d_in, const int* in_sizes, int n_in,
                              void* d_out, int out_size)
{
    const float* x      = (const float*)d_in[0];
    const float* ln1_w  = (const float*)d_in[1];
    const float* ln1_b  = (const float*)d_in[2];
    const float* qkv_w  = (const float*)d_in[3];
    const float* proj_w = (const float*)d_in[4];
    const float* proj_b = (const float*)d_in[5];
    const float* ln2_w  = (const float*)d_in[6];
    const float* ln2_b  = (const float*)d_in[7];
    const float* fc1_w  = (const float*)d_in[8];
    const float* fc1_b  = (const float*)d_in[9];
    const float* fc2_w  = (const float*)d_in[10];
    const float* fc2_b  = (const float*)d_in[11];
    float* out = (float*)d_out;

    float *h1f, *qkv, *qkvc, *cls, *x2;
    __nv_bfloat16 *h1h, *h1l, *qkvh, *qkvl, *qkvch, *qkvcl, *yh, *yl, *h2h, *h2l, *f1h, *f1l;
    __nv_bfloat16 *wqh, *wql, *wph, *wpl, *w1h, *w1l, *w2h, *w2l;
    cudaGetSymbolAddress((void**)&h1f,   g_h1f);
    cudaGetSymbolAddress((void**)&h1h,   g_h1h);
    cudaGetSymbolAddress((void**)&h1l,   g_h1l);
    cudaGetSymbolAddress((void**)&qkv,   g_qkv);
    cudaGetSymbolAddress((void**)&qkvh,  g_qkvh);
    cudaGetSymbolAddress((void**)&qkvl,  g_qkvl);
    cudaGetSymbolAddress((void**)&qkvc,  g_qkvc);
    cudaGetSymbolAddress((void**)&qkvch, g_qkvch);
    cudaGetSymbolAddress((void**)&qkvcl, g_qkvcl);
    cudaGetSymbolAddress((void**)&cls,   g_cls);
    cudaGetSymbolAddress((void**)&yh,    g_yh);
    cudaGetSymbolAddress((void**)&yl,    g_yl);
    cudaGetSymbolAddress((void**)&x2,    g_x2);
    cudaGetSymbolAddress((void**)&h2h,   g_h2h);
    cudaGetSymbolAddress((void**)&h2l,   g_h2l);
    cudaGetSymbolAddress((void**)&f1h,   g_f1h);
    cudaGetSymbolAddress((void**)&f1l,   g_f1l);
    cudaGetSymbolAddress((void**)&wqh,   g_wqh);
    cudaGetSymbolAddress((void**)&wql,   g_wql);
    cudaGetSymbolAddress((void**)&wph,   g_wph);
    cudaGetSymbolAddress((void**)&wpl,   g_wpl);
    cudaGetSymbolAddress((void**)&w1h,   g_w1h);
    cudaGetSymbolAddress((void**)&w1l,   g_w1l);
    cudaGetSymbolAddress((void**)&w2h,   g_w2h);
    cudaGetSymbolAddress((void**)&w2l,   g_w2l);

    const int M = MROWS;
    const int tc_smem = NSTAGE * STAGE_B + 128;
    cudaFuncSetAttribute(tc_gemm<0,2>, cudaFuncAttributeMaxDynamicSharedMemorySize, tc_smem);
    cudaFuncSetAttribute(tc_gemm<1,0>, cudaFuncAttributeMaxDynamicSharedMemorySize, tc_smem);
    cudaFuncSetAttribute(tc_gemm<2,1>, cudaFuncAttributeMaxDynamicSharedMemorySize, tc_smem);
    const int ba_smem = 6*8192 + 128;
    cudaFuncSetAttribute(branch_attn_kernel, cudaFuncAttributeMaxDynamicSharedMemorySize, ba_smem);

    // 0. split weights
    split_kernel<<<(3*CC*CC + 255)/256, 256>>>(qkv_w,  wqh, wql, 3*CC*CC);
    split_kernel<<<(CC*CC   + 255)/256, 256>>>(proj_w, wph, wpl, CC*CC);
    split_kernel<<<(4*CC*CC + 255)/256, 256>>>(fc1_w,  w1h, w1l, 4*CC*CC);
    split_kernel<<<(4*CC*CC + 255)/256, 256>>>(fc2_w,  w2h, w2l, 4*CC*CC);

    // 1. LN1
    ln_kernel<<<(M + 7)/8, 256>>>(x, ln1_w, ln1_b, h1f, h1h, h1l, M);

    // 2. qkv = h1 @ qkv_w^T  (fp32 + bf16 splits)
    {
        dim3 grid((3*CC)/128, MPAD/128);
        tc_gemm<0,2><<<grid, 256, tc_smem>>>(h1h, h1l, wqh, wql,
            nullptr, nullptr, qkv, qkvh, qkvl, M, 3*CC, CC);
    }

    // 3. cls global attention
    cls_attn_kernel<<<BB*HH, 256>>>(qkv, h1f, cls, yh, yl);

    // 4. cls qkv
    cls_qkv_kernel<<<3*CC, 256>>>(cls, qkv_w, qkvc, qkvch, qkvcl);

    // 5. branch attention (tensor-core)
    {
        dim3 grid(8, NBB, BB*HH);
        branch_attn_kernel<<<grid, 128, ba_smem>>>(qkvh, qkvl, qkvch, qkvcl, yh, yl);
    }

    // 6. x2 = x + y @ proj_w^T + proj_b
    {
        dim3 grid(CC/128, MPAD/128);
        tc_gemm<1,0><<<grid, 256, tc_smem>>>(yh, yl, wph, wpl,
            proj_b, x, x2, nullptr, nullptr, M, CC, CC);
    }

    // 7. LN2
    ln_kernel<<<(M + 7)/8, 256>>>(x2, ln2_w, ln2_b, nullptr, h2h, h2l, M);

    // 8. fc1 + gelu -> split
    {
        dim3 grid((4*CC)/128, MPAD/128);
        tc_gemm<2,1><<<grid, 256, tc_smem>>>(h2h, h2l, w1h, w1l,
            fc1_b, nullptr, nullptr, f1h, f1l, M, 4*CC, CC);
    }

    // 9. out = x2 + fc1g @ fc2_w^T + fc2_b
    {
        dim3 grid(CC/128, MPAD/128);
        tc_gemm<1,0><<<grid, 256, tc_smem>>>(f1h, f1l, w2h, w2l,
            fc2_b, x2, out, nullptr, nullptr, M, CC, 4*CC);
    }
}

// round 7
// speedup vs baseline: 2.9250x; 1.4762x over previous
#include <cuda_runtime.h>
#include <cuda_fp16.h>
#include <math.h>
#include <stdint.h>

// ---------------- problem constants ----------------
#define BB   8
#define NN   2049
#define CC   768
#define HH   12
#define NBB  4
#define HD   64
#define SPB  512
#define MROWS (BB*NN)      // 16392
#define MPAD  16512        // 129 * 128
#define SCALE 0.125f
#define LNEPS 1e-6f

// ---------------- scratch ----------------
__device__ float g_h1f [(size_t)MROWS * CC];
__device__ __half g_h1h[(size_t)MPAD * CC];
__device__ __half g_h1l[(size_t)MPAD * CC];
__device__ __half g_qkvh[(size_t)MROWS * 3 * CC];
__device__ __half g_qkvl[(size_t)MROWS * 3 * CC];
__device__ float g_qkvc[BB * 3 * CC];
__device__ __half g_qkvch[BB * 3 * CC];
__device__ __half g_qkvcl[BB * 3 * CC];
__device__ float g_cls [BB * CC];
__device__ __half g_yh [(size_t)MPAD * CC];
__device__ __half g_yl [(size_t)MPAD * CC];
__device__ float g_x2  [(size_t)MROWS * CC];
__device__ __half g_h2h[(size_t)MPAD * CC];
__device__ __half g_f1h[(size_t)MPAD * 4 * CC];
__device__ __half g_wqh[3*CC*CC], g_wql[3*CC*CC];
__device__ __half g_wph[CC*CC],   g_wpl[CC*CC];
__device__ __half g_w1h[4*CC*CC];
__device__ __half g_w2h[4*CC*CC];

// ---------------- helpers ----------------
__device__ __forceinline__ void split2h(float v, __half& h, __half& l) {
    h = __float2half_rn(v);
    l = __float2half_rn(v - __half2float(h));
}
__device__ __forceinline__ uint32_t smem_u32(const void* p) {
    return (uint32_t)__cvta_generic_to_shared(p);
}
__device__ __forceinline__ void cp16(uint32_t saddr, const void* g) {
    asm volatile("cp.async.cg.shared.global [%0], [%1], 16;\n" :: "r"(saddr), "l"(g));
}
__device__ __forceinline__ void cp_commit() { asm volatile("cp.async.commit_group;\n"); }
template<int NW> __device__ __forceinline__ void cp_wait() {
    asm volatile("cp.async.wait_group %0;\n" :: "n"(NW));
}
__device__ __forceinline__ void ldsm4(uint32_t addr, uint32_t& r0, uint32_t& r1,
                                      uint32_t& r2, uint32_t& r3) {
    asm volatile("ldmatrix.sync.aligned.m8n8.x4.shared.b16 {%0,%1,%2,%3}, [%4];"
                 : "=r"(r0), "=r"(r1), "=r"(r2), "=r"(r3) : "r"(addr));
}
__device__ __forceinline__ void ldsm4t(uint32_t addr, uint32_t& r0, uint32_t& r1,
                                       uint32_t& r2, uint32_t& r3) {
    asm volatile("ldmatrix.sync.aligned.m8n8.x4.trans.shared.b16 {%0,%1,%2,%3}, [%4];"
                 : "=r"(r0), "=r"(r1), "=r"(r2), "=r"(r3) : "r"(addr));
}
__device__ __forceinline__ void mma16816(float* c, const uint32_t* a, const uint32_t* b) {
    asm volatile("mma.sync.aligned.m16n8k16.row.col.f32.f16.f16.f32 "
        "{%0,%1,%2,%3}, {%4,%5,%6,%7}, {%8,%9}, {%0,%1,%2,%3};"
        : "+f"(c[0]), "+f"(c[1]), "+f"(c[2]), "+f"(c[3])
        : "r"(a[0]), "r"(a[1]), "r"(a[2]), "r"(a[3]), "r"(b[0]), "r"(b[1]));
}
__device__ __forceinline__ void packsplit2h(float a, float b, uint32_t& ph, uint32_t& pl) {
    __half ah, al, bh, bl;
    split2h(a, ah, al); split2h(b, bh, bl);
    ph = (uint32_t)__half_as_ushort(ah) | ((uint32_t)__half_as_ushort(bh) << 16);
    pl = (uint32_t)__half_as_ushort(al) | ((uint32_t)__half_as_ushort(bl) << 16);
}

template<bool LO>
__global__ void __launch_bounds__(256) split_kernel(const float* __restrict__ in,
                                                    __half* __restrict__ oh,
                                                    __half* __restrict__ ol, int n)
{
    int i = blockIdx.x * 256 + threadIdx.x;
    if (i < n) {
        float v = in[i];
        __half h = __float2half_rn(v);
        oh[i] = h;
        if (LO) ol[i] = __float2half_rn(v - __half2float(h));
    }
}

// ---------------- LayerNorm: warp per row ----------------
__global__ void __launch_bounds__(256) ln_kernel(const float* __restrict__ x,
                                                 const float* __restrict__ w,
                                                 const float* __restrict__ b,
                                                 float* __restrict__ outf,
                                                 __half* __restrict__ oh,
                                                 __half* __restrict__ ol,
                                                 int rows)
{
    int row = blockIdx.x * 8 + (threadIdx.x >> 5);
    if (row >= rows) return;
    int lane = threadIdx.x & 31;
    const float4* xr = (const float4*)(x + (size_t)row * CC);

    float4 v[6];
    float s = 0.0f;
    #pragma unroll
    for (int i = 0; i < 6; i++) {
        v[i] = xr[i * 32 + lane];
        s += v[i].x + v[i].y + v[i].z + v[i].w;
    }
    #pragma unroll
    for (int o = 16; o; o >>= 1) s += __shfl_xor_sync(0xffffffffu, s, o);
    float mu = s * (1.0f / CC);

    float q = 0.0f;
    #pragma unroll
    for (int i = 0; i < 6; i++) {
        v[i].x -= mu; v[i].y -= mu; v[i].z -= mu; v[i].w -= mu;
        q += v[i].x*v[i].x + v[i].y*v[i].y + v[i].z*v[i].z + v[i].w*v[i].w;
    }
    #pragma unroll
    for (int o = 16; o; o >>= 1) q += __shfl_xor_sync(0xffffffffu, q, o);
    float rs = rsqrtf(q * (1.0f / CC) + LNEPS);

    const float4* w4 = (const float4*)w;
    const float4* b4 = (const float4*)b;
    uint2* oh2 = (uint2*)(oh + (size_t)row * CC);
    uint2* ol2 = ol ? (uint2*)(ol + (size_t)row * CC) : nullptr;
    bool wf = (outf != nullptr) && (row % NN) == 0;
    float4* of4 = wf ? (float4*)(outf + (size_t)row * CC) : nullptr;

    #pragma unroll
    for (int i = 0; i < 6; i++) {
        float4 wv = w4[i * 32 + lane], bv = b4[i * 32 + lane];
        float o0 = v[i].x * rs * wv.x + bv.x;
        float o1 = v[i].y * rs * wv.y + bv.y;
        float o2 = v[i].z * rs * wv.z + bv.z;
        float o3 = v[i].w * rs * wv.w + bv.w;
        uint32_t h01, l01, h23, l23;
        packsplit2h(o0, o1, h01, l01);
        packsplit2h(o2, o3, h23, l23);
        oh2[i * 32 + lane] = make_uint2(h01, h23);
        if (ol2) ol2[i * 32 + lane] = make_uint2(l01, l23);
        if (wf) of4[i * 32 + lane] = make_float4(o0, o1, o2, o3);
    }
}

// ================= fp16 mma.sync GEMM =================
// EPI: 0 none, 1 bias+residual, 2 bias+gelu.
// OUTM: 0 f32, 1 split h+l, 3 hi only.
// NT: 3 = fp16x3 (A,W hi/lo), 1 = single-pass fp16.
#define TILE_B   16384
#define NSTAGE   3

template<int EPI, int OUTM, int NT>
__global__ void __launch_bounds__(256, 1) tc_gemm(
    const __half* __restrict__ Ah, const __half* __restrict__ Al,
    const __half* __restrict__ Wh, const __half* __restrict__ Wl,
    const float* __restrict__ bias, const float* __restrict__ res,
    float* __restrict__ Cf, __half* __restrict__ Ch, __half* __restrict__ Cl,
    int M, int N, int K)
{
    constexpr int TPS = (NT == 3) ? 4 : 2;         // tiles per stage
    constexpr uint32_t STB = TPS * TILE_B;
    const uint32_t WOFF = (NT == 3) ? 2*TILE_B : TILE_B;

    extern __shared__ char dynraw[];
    uint32_t raw = smem_u32(dynraw);
    uint32_t smb = (raw + 127) & ~127u;

    const int tid = threadIdx.x;
    const int bn = blockIdx.x * 128, bm = blockIdx.y * 128;
    const int nt = K >> 6;
    const int lane = tid & 31, wid = tid >> 5;
    const int wm = (wid & 1) * 64, wn = (wid >> 1) * 32;
    const int r8 = lane & 7, sub = lane >> 3;

    const int lrow = tid >> 1;
    const int c0 = (tid & 1) * 4;

    auto load_stage = [&](int kt, int s) {
        uint32_t sb = smb + s * STB;
        size_t goff = (size_t)(kt * 64 + c0 * 8);
        const __half* gAh = Ah + (size_t)(bm + lrow) * K + goff;
        const __half* gWh = Wh + (size_t)(bn + lrow) * K + goff;
        const __half* gAl = (NT == 3) ? Al + (size_t)(bm + lrow) * K + goff : nullptr;
        const __half* gWl = (NT == 3) ? Wl + (size_t)(bn + lrow) * K + goff : nullptr;
        uint32_t ro = lrow * 128;
        #pragma unroll
        for (int c = 0; c < 4; c++) {
            int chunk = c0 + c;
            uint32_t sw = ro + (uint32_t)((chunk ^ (lrow & 7)) << 4);
            cp16(sb        + sw, gAh + c*8);
            cp16(sb + WOFF + sw, gWh + c*8);
            if (NT == 3) {
                cp16(sb +   TILE_B + sw, gAl + c*8);
                cp16(sb + 3*TILE_B + sw, gWl + c*8);
            }
        }
        cp_commit();
    };

    float acc[4][4][4];
    #pragma unroll
    for (int i = 0; i < 4; i++)
        #pragma unroll
        for (int j = 0; j < 4; j++)
            #pragma unroll
            for (int t = 0; t < 4; t++) acc[i][j][t] = 0.0f;

    uint32_t aRowBase[4]; int aKey[4];
    #pragma unroll
    for (int mi = 0; mi < 4; mi++) {
        int row = wm + mi*16 + ((sub & 1) << 3) + r8;
        aRowBase[mi] = row * 128;
        aKey[mi] = row & 7;
    }
    const int aChunkOff = sub >> 1;
    uint32_t bRowBase[2]; int bKey[2];
    #pragma unroll
    for (int pr = 0; pr < 2; pr++) {
        int row = wn + pr*16 + ((sub >> 1) << 3) + r8;
        bRowBase[pr] = row * 128;
        bKey[pr] = row & 7;
    }
    const int bChunkOff = sub & 1;

    load_stage(0, 0);
    load_stage(1, 1);

    for (int kt = 0; kt < nt; kt++) {
        if (kt + 1 < nt) cp_wait<1>(); else cp_wait<0>();
        __syncthreads();

        uint32_t sb = smb + (kt % NSTAGE) * STB;

        #pragma unroll
        for (int kk = 0; kk < 4; kk++) {
            uint32_t Bh[2][4], Bl[2][4];
            #pragma unroll
            for (int pr = 0; pr < 2; pr++) {
                int chunk = kk*2 + bChunkOff;
                uint32_t ad = sb + WOFF + bRowBase[pr]
                            + (uint32_t)((chunk ^ bKey[pr]) << 4);
                ldsm4(ad, Bh[pr][0], Bh[pr][1], Bh[pr][2], Bh[pr][3]);
                if (NT == 3)
                    ldsm4(ad + TILE_B, Bl[pr][0], Bl[pr][1], Bl[pr][2], Bl[pr][3]);
            }
            #pragma unroll
            for (int mi = 0; mi < 4; mi++) {
                int chunk = kk*2 + aChunkOff;
                uint32_t ad = sb + aRowBase[mi]
                            + (uint32_t)((chunk ^ aKey[mi]) << 4);
                uint32_t Af[4], Alf[4];
                ldsm4(ad, Af[0], Af[1], Af[2], Af[3]);
                if (NT == 3)
                    ldsm4(ad + TILE_B, Alf[0], Alf[1], Alf[2], Alf[3]);
                #pragma unroll
                for (int ni = 0; ni < 4; ni++) {
                    int pr = ni >> 1, half = (ni & 1) * 2;
                    mma16816(acc[mi][ni], Af, &Bh[pr][half]);
                    if (NT == 3) {
                        mma16816(acc[mi][ni], Af,  &Bl[pr][half]);
                        mma16816(acc[mi][ni], Alf, &Bh[pr][half]);
                    }
                }
            }
        }

        if (kt + 2 < nt) {
            __syncthreads();
            load_stage(kt + 2, (kt + 2) % NSTAGE);
        }
    }

    int r4 = lane >> 2, c2 = (lane & 3) * 2;
    #pragma unroll
    for (int mi = 0; mi < 4; mi++) {
        #pragma unroll
        for (int hh = 0; hh < 2; hh++) {
            int m = bm + wm + mi*16 + r4 + hh*8;
            if (m >= M) continue;
            #pragma unroll
            for (int ni = 0; ni < 4; ni++) {
                int n0 = bn + wn + ni*8 + c2;
                #pragma unroll
                for (int t = 0; t < 2; t++) {
                    int n = n0 + t;
                    float v = acc[mi][ni][hh*2 + t];
                    if (EPI != 0) v += bias[n];
                    size_t idx = (size_t)m * N + n;
                    if (EPI == 1) v += res[idx];
                    if (EPI == 2) v = 0.5f * v * (1.0f + erff(v * 0.7071067811865476f));
                    if (OUTM == 0) {
                        Cf[idx] = v;
                    } else if (OUTM == 1) {
                        __half h, l;
                        split2h(v, h, l);
                        Ch[idx] = h; Cl[idx] = l;
                    } else {
                        Ch[idx] = __float2half_rn(v);
                    }
                }
            }
        }
    }
}

// ---------------- cls global attention ----------------
__global__ void __launch_bounds__(256) cls_attn_kernel(const __half* __restrict__ qkvh,
                                                       const float* __restrict__ h1,
                                                       float* __restrict__ cls,
                                                       __half* __restrict__ yh,
                                                       __half* __restrict__ yl)
{
    __shared__ float sq[64];
    __shared__ float sc[NN];
    __shared__ float red[256];
    __shared__ float so[4][64];

    int bh = blockIdx.x;
    int b = bh / HH, h = bh % HH;
    int tid = threadIdx.x;

    const __half* qbase = qkvh + (size_t)(b * NN) * (3*CC) + h * HD;
    if (tid < 64) sq[tid] = __half2float(qbase[tid]);
    __syncthreads();

    float lmax = -1e30f;
    for (int i = tid; i < NN; i += 256) {
        const __half2* kr = (const __half2*)(qkvh + (size_t)(b * NN + i) * (3*CC) + CC + h * HD);
        float s = 0.0f;
        #pragma unroll 8
        for (int d = 0; d < 32; d++) {
            float2 kv = __half22float2(kr[d]);
            s = fmaf(sq[2*d], kv.x, s);
            s = fmaf(sq[2*d+1], kv.y, s);
        }
        s *= SCALE;
        sc[i] = s;
        lmax = fmaxf(lmax, s);
    }
    red[tid] = lmax; __syncthreads();
    for (int off = 128; off; off >>= 1) {
        if (tid < off) red[tid] = fmaxf(red[tid], red[tid + off]);
        __syncthreads();
    }
    float m = red[0];
    __syncthreads();

    float lsum = 0.0f;
    for (int i = tid; i < NN; i += 256) {
        float e = __expf(sc[i] - m);
        sc[i] = e;
        lsum += e;
    }
    red[tid] = lsum; __syncthreads();
    for (int off = 128; off; off >>= 1) {
        if (tid < off) red[tid] += red[tid + off];
        __syncthreads();
    }
    float l = red[0];
    __syncthreads();

    int d = tid & 63, part = tid >> 6;
    float o = 0.0f;
    for (int i = part; i < NN; i += 4)
        o = fmaf(sc[i], __half2float(qkvh[(size_t)(b * NN + i) * (3*CC) + 2*CC + h * HD + d]), o);
    so[part][d] = o;
    __syncthreads();

    if (tid < 64) {
        float val = (so[0][tid] + so[1][tid] + so[2][tid] + so[3][tid]) / l;
        size_t off0 = (size_t)(b * NN) * CC + h * HD + tid;
        float v = val + h1[off0];
        cls[b * CC + h * HD + tid] = v;
        __half hi, lo;
        split2h(v, hi, lo);
        yh[off0] = hi; yl[off0] = lo;
    }
}

// ---------------- cls qkv ----------------
__global__ void __launch_bounds__(256) cls_qkv_kernel(const float* __restrict__ cls,
                                                      const float* __restrict__ qkv_w,
                                                      float* __restrict__ qkvc,
                                                      __half* __restrict__ qkvch,
                                                      __half* __restrict__ qkvcl)
{
    int j = blockIdx.x;
    int w = threadIdx.x >> 5;
    int lane = threadIdx.x & 31;
    const float* cr = cls + (size_t)w * CC;
    const float* wr = qkv_w + (size_t)j * CC;
    float s = 0.0f;
    for (int k = lane; k < CC; k += 32) s = fmaf(cr[k], wr[k], s);
    #pragma unroll
    for (int off = 16; off; off >>= 1) s += __shfl_xor_sync(0xffffffffu, s, off);
    if (lane == 0) {
        qkvc[w * (3*CC) + j] = s;
        __half h, l;
        split2h(s, h, l);
        qkvch[w * (3*CC) + j] = h;
        qkvcl[w * (3*CC) + j] = l;
    }
}

// ---------------- branch attention (FA2 mma, fp16x3) ----------------
#define BQH 0
#define BQL 8192
#define BKH 16384
#define BKL 24576
#define BVH 32768
#define BVL 40960

__global__ void __launch_bounds__(128) branch_attn_kernel(
    const __half* __restrict__ qkvh, const __half* __restrict__ qkvl,
    const __half* __restrict__ qkvch, const __half* __restrict__ qkvcl,
    __half* __restrict__ yh, __half* __restrict__ yl)
{
    extern __shared__ char dynraw[];
    uint32_t raw = smem_u32(dynraw);
    uint32_t smb = (raw + 127) & ~127u;

    const int tid = threadIdx.x;
    const int lane = tid & 31, wid = tid >> 5;
    const int r8 = lane & 7, sub = lane >> 3;
    const int qt = blockIdx.x, nb = blockIdx.y;
    const int b = blockIdx.z / HH, h = blockIdx.z % HH;

    {
        int qrow = tid >> 1;
        int ch0 = (tid & 1) * 4;
        int token = 1 + nb * SPB + qt * 64 + qrow;
        size_t rb = (size_t)(b * NN + token) * (3*CC) + h * HD;
        const __half* gh = qkvh + rb;
        const __half* gl = qkvl + rb;
        uint32_t ro = qrow * 128;
        #pragma unroll
        for (int c = 0; c < 4; c++) {
            int chunk = ch0 + c;
            uint32_t sw = ro + (uint32_t)((chunk ^ (qrow & 7)) << 4);
            cp16(smb + BQH + sw, gh + chunk*8);
            cp16(smb + BQL + sw, gl + chunk*8);
        }
        cp_commit();
    }

    float m0 = -1e30f, m1 = -1e30f, l0 = 0.0f, l1 = 0.0f;
    float oreg[8][4];
    #pragma unroll
    for (int i = 0; i < 8; i++)
        #pragma unroll
        for (int t = 0; t < 4; t++) oreg[i][t] = 0.0f;

    const int kr = tid >> 1;
    const int ch0 = (tid & 1) * 4;
    const uint32_t kro = kr * 128;

    for (int kt = 0; kt < 9; kt++) {
        __syncthreads();
        {
            int jg = kt * 64 + kr;
            int jc = jg > 512 ? 512 : jg;
            const __half *kh_s, *kl_s, *vh_s, *vl_s;
            if (jc == 0) {
                size_t rb = (size_t)b * (3*CC) + h * HD;
                kh_s = qkvch + rb + CC;  kl_s = qkvcl + rb + CC;
                vh_s = qkvch + rb + 2*CC; vl_s = qkvcl + rb + 2*CC;
            } else {
                int token = nb * SPB + jc;
                size_t rb = (size_t)(b * NN + token) * (3*CC) + h * HD;
                kh_s = qkvh + rb + CC;   kl_s = qkvl + rb + CC;
                vh_s = qkvh + rb + 2*CC; vl_s = qkvl + rb + 2*CC;
            }
            #pragma unroll
            for (int c = 0; c < 4; c++) {
                int chunk = ch0 + c;
                uint32_t sw = kro + (uint32_t)((chunk ^ (kr & 7)) << 4);
                cp16(smb + BKH + sw, kh_s + chunk*8);
                cp16(smb + BKL + sw, kl_s + chunk*8);
                cp16(smb + BVH + sw, vh_s + chunk*8);
                cp16(smb + BVL + sw, vl_s + chunk*8);
            }
            cp_commit();
        }
        cp_wait<0>();
        __syncthreads();

        float sreg[8][4];
        #pragma unroll
        for (int i = 0; i < 8; i++)
            #pragma unroll
            for (int t = 0; t < 4; t++) sreg[i][t] = 0.0f;

        #pragma unroll
        for (int kk = 0; kk < 4; kk++) {
            int arow = wid*16 + ((sub & 1) << 3) + r8;
            uint32_t aad = smb + BQH + arow*128
                         + (uint32_t)(((kk*2 + (sub >> 1)) ^ (arow & 7)) << 4);
            uint32_t qh[4], ql[4];
            ldsm4(aad,               qh[0], qh[1], qh[2], qh[3]);
            ldsm4(aad + (BQL - BQH), ql[0], ql[1], ql[2], ql[3]);
            #pragma unroll
            for (int pr = 0; pr < 4; pr++) {
                int brow = pr*16 + ((sub >> 1) << 3) + r8;
                uint32_t bad = smb + BKH + brow*128
                             + (uint32_t)(((kk*2 + (sub & 1)) ^ (brow & 7)) << 4);
                uint32_t kh[4], kl[4];
                ldsm4(bad,               kh[0], kh[1], kh[2], kh[3]);
                ldsm4(bad + (BKL - BKH), kl[0], kl[1], kl[2], kl[3]);
                #pragma unroll
                for (int t2 = 0; t2 < 2; t2++) {
                    float* c = sreg[pr*2 + t2];
                    mma16816(c, qh, &kh[t2*2]);
                    mma16816(c, qh, &kl[t2*2]);
                    mma16816(c, ql, &kh[t2*2]);
                }
            }
        }

        #pragma unroll
        for (int nt = 0; nt < 8; nt++)
            #pragma unroll
            for (int t = 0; t < 4; t++) {
                float v = sreg[nt][t] * SCALE;
                int gcol = kt*64 + nt*8 + (lane & 3)*2 + (t & 1);
                if (gcol > 512) v = -1e30f;
                sreg[nt][t] = v;
            }

        float mt0 = -1e30f, mt1 = -1e30f;
        #pragma unroll
        for (int nt = 0; nt < 8; nt++) {
            mt0 = fmaxf(mt0, fmaxf(sreg[nt][0], sreg[nt][1]));
            mt1 = fmaxf(mt1, fmaxf(sreg[nt][2], sreg[nt][3]));
        }
        mt0 = fmaxf(mt0, __shfl_xor_sync(0xffffffffu, mt0, 1));
        mt0 = fmaxf(mt0, __shfl_xor_sync(0xffffffffu, mt0, 2));
        mt1 = fmaxf(mt1, __shfl_xor_sync(0xffffffffu, mt1, 1));
        mt1 = fmaxf(mt1, __shfl_xor_sync(0xffffffffu, mt1, 2));
        float mn0 = fmaxf(m0, mt0), mn1 = fmaxf(m1, mt1);
        float a0 = __expf(m0 - mn0), a1 = __expf(m1 - mn1);
        m0 = mn0; m1 = mn1;
        float rs0 = 0.0f, rs1 = 0.0f;
        #pragma unroll
        for (int nt = 0; nt < 8; nt++) {
            sreg[nt][0] = __expf(sreg[nt][0] - mn0);
            sreg[nt][1] = __expf(sreg[nt][1] - mn0);
            sreg[nt][2] = __expf(sreg[nt][2] - mn1);
            sreg[nt][3] = __expf(sreg[nt][3] - mn1);
            rs0 += sreg[nt][0] + sreg[nt][1];
            rs1 += sreg[nt][2] + sreg[nt][3];
        }
        rs0 += __shfl_xor_sync(0xffffffffu, rs0, 1);
        rs0 += __shfl_xor_sync(0xffffffffu, rs0, 2);
        rs1 += __shfl_xor_sync(0xffffffffu, rs1, 1);
        rs1 += __shfl_xor_sync(0xffffffffu, rs1, 2);
        l0 = l0 * a0 + rs0;
        l1 = l1 * a1 + rs1;
        #pragma unroll
        for (int dt = 0; dt < 8; dt++) {
            oreg[dt][0] *= a0; oreg[dt][1] *= a0;
            oreg[dt][2] *= a1; oreg[dt][3] *= a1;
        }

        uint32_t ph[4][4], pl[4][4];
        #pragma unroll
        for (int kc = 0; kc < 4; kc++) {
            packsplit2h(sreg[2*kc][0],   sreg[2*kc][1],   ph[kc][0], pl[kc][0]);
            packsplit2h(sreg[2*kc][2],   sreg[2*kc][3],   ph[kc][1], pl[kc][1]);
            packsplit2h(sreg[2*kc+1][0], sreg[2*kc+1][1], ph[kc][2], pl[kc][2]);
            packsplit2h(sreg[2*kc+1][2], sreg[2*kc+1][3], ph[kc][3], pl[kc][3]);
        }

        #pragma unroll
        for (int kc = 0; kc < 4; kc++) {
            #pragma unroll
            for (int dg = 0; dg < 4; dg++) {
                int vrow = kc*16 + ((sub & 1) << 3) + r8;
                uint32_t vad = smb + BVH + vrow*128
                             + (uint32_t)(((dg*2 + (sub >> 1)) ^ (vrow & 7)) << 4);
                uint32_t vh[4], vl[4];
                ldsm4t(vad,               vh[0], vh[1], vh[2], vh[3]);
                ldsm4t(vad + (BVL - BVH), vl[0], vl[1], vl[2], vl[3]);
                #pragma unroll
                for (int t2 = 0; t2 < 2; t2++) {
                    float* c = oreg[dg*2 + t2];
                    mma16816(c, ph[kc], &vh[t2*2]);
                    mma16816(c, ph[kc], &vl[t2*2]);
                    mma16816(c, pl[kc], &vh[t2*2]);
                }
            }
        }
    }

    float inv0 = 1.0f / l0, inv1 = 1.0f / l1;
    int r4 = lane >> 2, c2 = (lane & 3) * 2;
    #pragma unroll
    for (int dt = 0; dt < 8; dt++) {
        #pragma unroll
        for (int t = 0; t < 4; t++) {
            int rh = t >> 1;
            int sp = qt*64 + wid*16 + r4 + rh*8;
            int dp = dt*8 + c2 + (t & 1);
            float v = oreg[dt][t] * (rh ? inv1 : inv0);
            int linear = h * (SPB * HD) + sp * HD + dp;
            int s_ = linear / CC;
            int c = linear - s_ * CC;
            int token = 1 + nb * SPB + s_;
            __half hi, lo;
            split2h(v, hi, lo);
            size_t idx = (size_t)(b * NN + token) * CC + c;
            yh[idx] = hi; yl[idx] = lo;
        }
    }
}

// ---------------- launch ----------------
extern "C" void kernel_launch(void* const* d_in, const int* in_sizes, int n_in,
                              void* d_out, int out_size)
{
    const float* x      = (const float*)d_in[0];
    const float* ln1_w  = (const float*)d_in[1];
    const float* ln1_b  = (const float*)d_in[2];
    const float* qkv_w  = (const float*)d_in[3];
    const float* proj_w = (const float*)d_in[4];
    const float* proj_b = (const float*)d_in[5];
    const float* ln2_w  = (const float*)d_in[6];
    const float* ln2_b  = (const float*)d_in[7];
    const float* fc1_w  = (const float*)d_in[8];
    const float* fc1_b  = (const float*)d_in[9];
    const float* fc2_w  = (const float*)d_in[10];
    const float* fc2_b  = (const float*)d_in[11];
    float* out = (float*)d_out;

    float *h1f, *qkvc, *cls, *x2;
    __half *h1h, *h1l, *qkvh, *qkvl, *qkvch, *qkvcl, *yh, *yl, *h2h, *f1h;
    __half *wqh, *wql, *wph, *wpl, *w1h, *w2h;
    cudaGetSymbolAddress((void**)&h1f,   g_h1f);
    cudaGetSymbolAddress((void**)&h1h,   g_h1h);
    cudaGetSymbolAddress((void**)&h1l,   g_h1l);
    cudaGetSymbolAddress((void**)&qkvh,  g_qkvh);
    cudaGetSymbolAddress((void**)&qkvl,  g_qkvl);
    cudaGetSymbolAddress((void**)&qkvc,  g_qkvc);
    cudaGetSymbolAddress((void**)&qkvch, g_qkvch);
    cudaGetSymbolAddress((void**)&qkvcl, g_qkvcl);
    cudaGetSymbolAddress((void**)&cls,   g_cls);
    cudaGetSymbolAddress((void**)&yh,    g_yh);
    cudaGetSymbolAddress((void**)&yl,    g_yl);
    cudaGetSymbolAddress((void**)&x2,    g_x2);
    cudaGetSymbolAddress((void**)&h2h,   g_h2h);
    cudaGetSymbolAddress((void**)&f1h,   g_f1h);
    cudaGetSymbolAddress((void**)&wqh,   g_wqh);
    cudaGetSymbolAddress((void**)&wql,   g_wql);
    cudaGetSymbolAddress((void**)&wph,   g_wph);
    cudaGetSymbolAddress((void**)&wpl,   g_wpl);
    cudaGetSymbolAddress((void**)&w1h,   g_w1h);
    cudaGetSymbolAddress((void**)&w2h,   g_w2h);

    const int M = MROWS;
    const int smem3 = NSTAGE * 4 * TILE_B + 128;   // 196736
    const int smem1 = NSTAGE * 2 * TILE_B + 128;   // 98432
    cudaFuncSetAttribute(tc_gemm<0,1,3>, cudaFuncAttributeMaxDynamicSharedMemorySize, smem3);
    cudaFuncSetAttribute(tc_gemm<1,0,3>, cudaFuncAttributeMaxDynamicSharedMemorySize, smem3);
    cudaFuncSetAttribute(tc_gemm<2,3,1>, cudaFuncAttributeMaxDynamicSharedMemorySize, smem1);
    cudaFuncSetAttribute(tc_gemm<1,0,1>, cudaFuncAttributeMaxDynamicSharedMemorySize, smem1);
    const int ba_smem = 6*8192 + 128;
    cudaFuncSetAttribute(branch_attn_kernel, cudaFuncAttributeMaxDynamicSharedMemorySize, ba_smem);

    // 0. split weights (qkv/proj hi+lo; fc hi only)
    split_kernel<true ><<<(3*CC*CC + 255)/256, 256>>>(qkv_w,  wqh, wql, 3*CC*CC);
    split_kernel<true ><<<(CC*CC   + 255)/256, 256>>>(proj_w, wph, wpl, CC*CC);
    split_kernel<false><<<(4*CC*CC + 255)/256, 256>>>(fc1_w,  w1h, nullptr, 4*CC*CC);
    split_kernel<false><<<(4*CC*CC + 255)/256, 256>>>(fc2_w,  w2h, nullptr, 4*CC*CC);

    // 1. LN1 (cls rows fp32 + full hi/lo)
    ln_kernel<<<(M + 7)/8, 256>>>(x, ln1_w, ln1_b, h1f, h1h, h1l, M);

    // 2. qkv = h1 @ qkv_w^T  (fp16 splits only), x3
    {
        dim3 grid((3*CC)/128, MPAD/128);
        tc_gemm<0,1,3><<<grid, 256, smem3>>>(h1h, h1l, wqh, wql,
            nullptr, nullptr, nullptr, qkvh, qkvl, M, 3*CC, CC);
    }

    // 3. cls global attention (reads fp16 hi)
    cls_attn_kernel<<<BB*HH, 256>>>(qkvh, h1f, cls, yh, yl);

    // 4. cls qkv
    cls_qkv_kernel<<<3*CC, 256>>>(cls, qkv_w, qkvc, qkvch, qkvcl);

    // 5. branch attention
    {
        dim3 grid(8, NBB, BB*HH);
        branch_attn_kernel<<<grid, 128, ba_smem>>>(qkvh, qkvl, qkvch, qkvcl, yh, yl);
    }

    // 6. x2 = x + y @ proj_w^T + proj_b  (x3)
    {
        dim3 grid(CC/128, MPAD/128);
        tc_gemm<1,0,3><<<grid, 256, smem3>>>(yh, yl, wph, wpl,
            proj_b, x, x2, nullptr, nullptr, M, CC, CC);
    }

    // 7. LN2 (hi only)
    ln_kernel<<<(M + 7)/8, 256>>>(x2, ln2_w, ln2_b, nullptr, h2h, nullptr, M);

    // 8. fc1 + gelu -> hi only  (x1)
    {
        dim3 grid((4*CC)/128, MPAD/128);
        tc_gemm<2,3,1><<<grid, 256, smem1>>>(h2h, nullptr, w1h, nullptr,
            fc1_b, nullptr, nullptr, f1h, nullptr, M, 4*CC, CC);
    }

    // 9. out = x2 + fc1g @ fc2_w^T + fc2_b  (x1)
    {
        dim3 grid(CC/128, MPAD/128);
        tc_gemm<1,0,1><<<grid, 256, smem1>>>(f1h, nullptr, w2h, nullptr,
            fc2_b, x2, out, nullptr, nullptr, M, CC, 4*CC);
    }
}

// round 8
// speedup vs baseline: 4.2030x; 1.4369x over previous
#include <cuda_runtime.h>
#include <cuda_fp16.h>
#include <math.h>
#include <stdint.h>

// ---------------- problem constants ----------------
#define BB   8
#define NN   2049
#define CC   768
#define HH   12
#define NBB  4
#define HD   64
#define SPB  512
#define MROWS (BB*NN)      // 16392
#define MPAD  16512        // 129 * 128
#define SCALE 0.125f
#define LNEPS 1e-6f

// ---------------- scratch ----------------
__device__ float g_h1f [(size_t)MROWS * CC];       // only cls rows written/read
__device__ __half g_h1h[(size_t)MPAD * CC];
__device__ __half g_qkvh[(size_t)MROWS * 3 * CC];
__device__ float g_qkvc[BB * 3 * CC];
__device__ __half g_qkvch[BB * 3 * CC];
__device__ float g_cls [BB * CC];
__device__ __half g_yh [(size_t)MPAD * CC];
__device__ float g_x2  [(size_t)MROWS * CC];
__device__ __half g_h2h[(size_t)MPAD * CC];
__device__ __half g_f1h[(size_t)MPAD * 4 * CC];
__device__ __half g_wqh[3*CC*CC];
__device__ __half g_wph[CC*CC];
__device__ __half g_w1h[4*CC*CC];
__device__ __half g_w2h[4*CC*CC];

// ---------------- helpers ----------------
__device__ __forceinline__ uint32_t smem_u32(const void* p) {
    return (uint32_t)__cvta_generic_to_shared(p);
}
__device__ __forceinline__ void cp16(uint32_t saddr, const void* g) {
    asm volatile("cp.async.cg.shared.global [%0], [%1], 16;\n" :: "r"(saddr), "l"(g));
}
__device__ __forceinline__ void cp_commit() { asm volatile("cp.async.commit_group;\n"); }
template<int NW> __device__ __forceinline__ void cp_wait() {
    asm volatile("cp.async.wait_group %0;\n" :: "n"(NW));
}
__device__ __forceinline__ void ldsm4(uint32_t addr, uint32_t& r0, uint32_t& r1,
                                      uint32_t& r2, uint32_t& r3) {
    asm volatile("ldmatrix.sync.aligned.m8n8.x4.shared.b16 {%0,%1,%2,%3}, [%4];"
                 : "=r"(r0), "=r"(r1), "=r"(r2), "=r"(r3) : "r"(addr));
}
__device__ __forceinline__ void ldsm4t(uint32_t addr, uint32_t& r0, uint32_t& r1,
                                       uint32_t& r2, uint32_t& r3) {
    asm volatile("ldmatrix.sync.aligned.m8n8.x4.trans.shared.b16 {%0,%1,%2,%3}, [%4];"
                 : "=r"(r0), "=r"(r1), "=r"(r2), "=r"(r3) : "r"(addr));
}
__device__ __forceinline__ void mma16816(float* c, const uint32_t* a, const uint32_t* b) {
    asm volatile("mma.sync.aligned.m16n8k16.row.col.f32.f16.f16.f32 "
        "{%0,%1,%2,%3}, {%4,%5,%6,%7}, {%8,%9}, {%0,%1,%2,%3};"
        : "+f"(c[0]), "+f"(c[1]), "+f"(c[2]), "+f"(c[3])
        : "r"(a[0]), "r"(a[1]), "r"(a[2]), "r"(a[3]), "r"(b[0]), "r"(b[1]));
}
__device__ __forceinline__ uint32_t pack2h(float a, float b) {
    __half2 h = __float22half2_rn(make_float2(a, b));
    return *(uint32_t*)&h;
}

// ---------------- fp32 -> fp16 convert (4 elems/thread) ----------------
__global__ void __launch_bounds__(256) cvt_kernel(const float* __restrict__ in,
                                                  __half* __restrict__ oh, int n4)
{
    int i = blockIdx.x * 256 + threadIdx.x;
    if (i < n4) {
        float4 v = ((const float4*)in)[i];
        uint2 o;
        o.x = pack2h(v.x, v.y);
        o.y = pack2h(v.z, v.w);
        ((uint2*)oh)[i] = o;
    }
}

// ---------------- LayerNorm: warp per row, fp16-hi out ----------------
__global__ void __launch_bounds__(256) ln_kernel(const float* __restrict__ x,
                                                 const float* __restrict__ w,
                                                 const float* __restrict__ b,
                                                 float* __restrict__ outf,
                                                 __half* __restrict__ oh,
                                                 int rows)
{
    int row = blockIdx.x * 8 + (threadIdx.x >> 5);
    if (row >= rows) return;
    int lane = threadIdx.x & 31;
    const float4* xr = (const float4*)(x + (size_t)row * CC);

    float4 v[6];
    float s = 0.0f;
    #pragma unroll
    for (int i = 0; i < 6; i++) {
        v[i] = xr[i * 32 + lane];
        s += v[i].x + v[i].y + v[i].z + v[i].w;
    }
    #pragma unroll
    for (int o = 16; o; o >>= 1) s += __shfl_xor_sync(0xffffffffu, s, o);
    float mu = s * (1.0f / CC);

    float q = 0.0f;
    #pragma unroll
    for (int i = 0; i < 6; i++) {
        v[i].x -= mu; v[i].y -= mu; v[i].z -= mu; v[i].w -= mu;
        q += v[i].x*v[i].x + v[i].y*v[i].y + v[i].z*v[i].z + v[i].w*v[i].w;
    }
    #pragma unroll
    for (int o = 16; o; o >>= 1) q += __shfl_xor_sync(0xffffffffu, q, o);
    float rs = rsqrtf(q * (1.0f / CC) + LNEPS);

    const float4* w4 = (const float4*)w;
    const float4* b4 = (const float4*)b;
    uint2* oh2 = (uint2*)(oh + (size_t)row * CC);
    bool wf = (outf != nullptr) && (row % NN) == 0;
    float4* of4 = wf ? (float4*)(outf + (size_t)row * CC) : nullptr;

    #pragma unroll
    for (int i = 0; i < 6; i++) {
        float4 wv = w4[i * 32 + lane], bv = b4[i * 32 + lane];
        float o0 = v[i].x * rs * wv.x + bv.x;
        float o1 = v[i].y * rs * wv.y + bv.y;
        float o2 = v[i].z * rs * wv.z + bv.z;
        float o3 = v[i].w * rs * wv.w + bv.w;
        oh2[i * 32 + lane] = make_uint2(pack2h(o0, o1), pack2h(o2, o3));
        if (wf) of4[i * 32 + lane] = make_float4(o0, o1, o2, o3);
    }
}

// ================= single-pass fp16 mma.sync GEMM =================
// C[m][n] = sum_k A[m][k]*W[n][k], fp32 accumulate.
// EPI: 0 none, 1 bias+residual, 2 bias+gelu. OUTM: 0 f32, 3 fp16.
// CTA 128x128x64, 8 warps (2m x 4n), 3-stage cp.async, ldmatrix.
#define TILE_B   16384
#define NSTAGE   3

template<int EPI, int OUTM>
__global__ void __launch_bounds__(256, 1) tc_gemm(
    const __half* __restrict__ Ah, const __half* __restrict__ Wh,
    const float* __restrict__ bias, const float* __restrict__ res,
    float* __restrict__ Cf, __half* __restrict__ Ch,
    int M, int N, int K)
{
    constexpr uint32_t STB = 2 * TILE_B;

    extern __shared__ char dynraw[];
    uint32_t raw = smem_u32(dynraw);
    uint32_t smb = (raw + 127) & ~127u;

    const int tid = threadIdx.x;
    const int bn = blockIdx.x * 128, bm = blockIdx.y * 128;
    const int nt = K >> 6;
    const int lane = tid & 31, wid = tid >> 5;
    const int wm = (wid & 1) * 64, wn = (wid >> 1) * 32;
    const int r8 = lane & 7, sub = lane >> 3;

    const int lrow = tid >> 1;
    const int c0 = (tid & 1) * 4;

    auto load_stage = [&](int kt, int s) {
        uint32_t sb = smb + s * STB;
        size_t goff = (size_t)(kt * 64 + c0 * 8);
        const __half* gAh = Ah + (size_t)(bm + lrow) * K + goff;
        const __half* gWh = Wh + (size_t)(bn + lrow) * K + goff;
        uint32_t ro = lrow * 128;
        #pragma unroll
        for (int c = 0; c < 4; c++) {
            int chunk = c0 + c;
            uint32_t sw = ro + (uint32_t)((chunk ^ (lrow & 7)) << 4);
            cp16(sb          + sw, gAh + c*8);
            cp16(sb + TILE_B + sw, gWh + c*8);
        }
        cp_commit();
    };

    float acc[4][4][4];
    #pragma unroll
    for (int i = 0; i < 4; i++)
        #pragma unroll
        for (int j = 0; j < 4; j++)
            #pragma unroll
            for (int t = 0; t < 4; t++) acc[i][j][t] = 0.0f;

    uint32_t aRowBase[4]; int aKey[4];
    #pragma unroll
    for (int mi = 0; mi < 4; mi++) {
        int row = wm + mi*16 + ((sub & 1) << 3) + r8;
        aRowBase[mi] = row * 128;
        aKey[mi] = row & 7;
    }
    const int aChunkOff = sub >> 1;
    uint32_t bRowBase[2]; int bKey[2];
    #pragma unroll
    for (int pr = 0; pr < 2; pr++) {
        int row = wn + pr*16 + ((sub >> 1) << 3) + r8;
        bRowBase[pr] = row * 128;
        bKey[pr] = row & 7;
    }
    const int bChunkOff = sub & 1;

    load_stage(0, 0);
    load_stage(1, 1);

    for (int kt = 0; kt < nt; kt++) {
        if (kt + 1 < nt) cp_wait<1>(); else cp_wait<0>();
        __syncthreads();

        uint32_t sb = smb + (kt % NSTAGE) * STB;

        #pragma unroll
        for (int kk = 0; kk < 4; kk++) {
            uint32_t Bh[2][4];
            #pragma unroll
            for (int pr = 0; pr < 2; pr++) {
                int chunk = kk*2 + bChunkOff;
                uint32_t ad = sb + TILE_B + bRowBase[pr]
                            + (uint32_t)((chunk ^ bKey[pr]) << 4);
                ldsm4(ad, Bh[pr][0], Bh[pr][1], Bh[pr][2], Bh[pr][3]);
            }
            #pragma unroll
            for (int mi = 0; mi < 4; mi++) {
                int chunk = kk*2 + aChunkOff;
                uint32_t ad = sb + aRowBase[mi]
                            + (uint32_t)((chunk ^ aKey[mi]) << 4);
                uint32_t Af[4];
                ldsm4(ad, Af[0], Af[1], Af[2], Af[3]);
                #pragma unroll
                for (int ni = 0; ni < 4; ni++) {
                    int pr = ni >> 1, half = (ni & 1) * 2;
                    mma16816(acc[mi][ni], Af, &Bh[pr][half]);
                }
            }
        }

        if (kt + 2 < nt) {
            __syncthreads();
            load_stage(kt + 2, (kt + 2) % NSTAGE);
        }
    }

    int r4 = lane >> 2, c2 = (lane & 3) * 2;
    #pragma unroll
    for (int mi = 0; mi < 4; mi++) {
        #pragma unroll
        for (int hh = 0; hh < 2; hh++) {
            int m = bm + wm + mi*16 + r4 + hh*8;
            if (m >= M) continue;
            #pragma unroll
            for (int ni = 0; ni < 4; ni++) {
                int n0 = bn + wn + ni*8 + c2;
                #pragma unroll
                for (int t = 0; t < 2; t++) {
                    int n = n0 + t;
                    float v = acc[mi][ni][hh*2 + t];
                    if (EPI != 0) v += bias[n];
                    size_t idx = (size_t)m * N + n;
                    if (EPI == 1) v += res[idx];
                    if (EPI == 2) v = 0.5f * v * (1.0f + erff(v * 0.7071067811865476f));
                    if (OUTM == 0) Cf[idx] = v;
                    else           Ch[idx] = __float2half_rn(v);
                }
            }
        }
    }
}

// ---------------- cls global attention ----------------
__global__ void __launch_bounds__(256) cls_attn_kernel(const __half* __restrict__ qkvh,
                                                       const float* __restrict__ h1,
                                                       float* __restrict__ cls,
                                                       __half* __restrict__ yh)
{
    __shared__ float sq[64];
    __shared__ float sc[NN];
    __shared__ float red[256];
    __shared__ float so[4][64];

    int bh = blockIdx.x;
    int b = bh / HH, h = bh % HH;
    int tid = threadIdx.x;

    const __half* qbase = qkvh + (size_t)(b * NN) * (3*CC) + h * HD;
    if (tid < 64) sq[tid] = __half2float(qbase[tid]);
    __syncthreads();

    float lmax = -1e30f;
    for (int i = tid; i < NN; i += 256) {
        const __half2* kr = (const __half2*)(qkvh + (size_t)(b * NN + i) * (3*CC) + CC + h * HD);
        float s = 0.0f;
        #pragma unroll 8
        for (int d = 0; d < 32; d++) {
            float2 kv = __half22float2(kr[d]);
            s = fmaf(sq[2*d], kv.x, s);
            s = fmaf(sq[2*d+1], kv.y, s);
        }
        s *= SCALE;
        sc[i] = s;
        lmax = fmaxf(lmax, s);
    }
    red[tid] = lmax; __syncthreads();
    for (int off = 128; off; off >>= 1) {
        if (tid < off) red[tid] = fmaxf(red[tid], red[tid + off]);
        __syncthreads();
    }
    float m = red[0];
    __syncthreads();

    float lsum = 0.0f;
    for (int i = tid; i < NN; i += 256) {
        float e = __expf(sc[i] - m);
        sc[i] = e;
        lsum += e;
    }
    red[tid] = lsum; __syncthreads();
    for (int off = 128; off; off >>= 1) {
        if (tid < off) red[tid] += red[tid + off];
        __syncthreads();
    }
    float l = red[0];
    __syncthreads();

    int d = tid & 63, part = tid >> 6;
    float o = 0.0f;
    for (int i = part; i < NN; i += 4)
        o = fmaf(sc[i], __half2float(qkvh[(size_t)(b * NN + i) * (3*CC) + 2*CC + h * HD + d]), o);
    so[part][d] = o;
    __syncthreads();

    if (tid < 64) {
        float val = (so[0][tid] + so[1][tid] + so[2][tid] + so[3][tid]) / l;
        size_t off0 = (size_t)(b * NN) * CC + h * HD + tid;
        float v = val + h1[off0];
        cls[b * CC + h * HD + tid] = v;
        yh[off0] = __float2half_rn(v);
    }
}

// ---------------- cls qkv ----------------
__global__ void __launch_bounds__(256) cls_qkv_kernel(const float* __restrict__ cls,
                                                      const float* __restrict__ qkv_w,
                                                      float* __restrict__ qkvc,
                                                      __half* __restrict__ qkvch)
{
    int j = blockIdx.x;
    int w = threadIdx.x >> 5;
    int lane = threadIdx.x & 31;
    const float* cr = cls + (size_t)w * CC;
    const float* wr = qkv_w + (size_t)j * CC;
    float s = 0.0f;
    for (int k = lane; k < CC; k += 32) s = fmaf(cr[k], wr[k], s);
    #pragma unroll
    for (int off = 16; off; off >>= 1) s += __shfl_xor_sync(0xffffffffu, s, off);
    if (lane == 0) {
        qkvc[w * (3*CC) + j] = s;
        qkvch[w * (3*CC) + j] = __float2half_rn(s);
    }
}

// ---------------- branch attention (FA2 mma, single-pass fp16) ----------------
#define BQ 0
#define BK 8192
#define BV 16384

__global__ void __launch_bounds__(128) branch_attn_kernel(
    const __half* __restrict__ qkvh, const __half* __restrict__ qkvch,
    __half* __restrict__ yh)
{
    extern __shared__ char dynraw[];
    uint32_t raw = smem_u32(dynraw);
    uint32_t smb = (raw + 127) & ~127u;

    const int tid = threadIdx.x;
    const int lane = tid & 31, wid = tid >> 5;
    const int r8 = lane & 7, sub = lane >> 3;
    const int qt = blockIdx.x, nb = blockIdx.y;
    const int b = blockIdx.z / HH, h = blockIdx.z % HH;

    // ---- load Q tile ----
    {
        int qrow = tid >> 1;
        int ch0 = (tid & 1) * 4;
        int token = 1 + nb * SPB + qt * 64 + qrow;
        const __half* gh = qkvh + (size_t)(b * NN + token) * (3*CC) + h * HD;
        uint32_t ro = qrow * 128;
        #pragma unroll
        for (int c = 0; c < 4; c++) {
            int chunk = ch0 + c;
            uint32_t sw = ro + (uint32_t)((chunk ^ (qrow & 7)) << 4);
            cp16(smb + BQ + sw, gh + chunk*8);
        }
        cp_commit();
    }

    float m0 = -1e30f, m1 = -1e30f, l0 = 0.0f, l1 = 0.0f;
    float oreg[8][4];
    #pragma unroll
    for (int i = 0; i < 8; i++)
        #pragma unroll
        for (int t = 0; t < 4; t++) oreg[i][t] = 0.0f;

    const int kr = tid >> 1;
    const int ch0 = (tid & 1) * 4;
    const uint32_t kro = kr * 128;

    for (int kt = 0; kt < 9; kt++) {
        __syncthreads();
        // ---- load K/V tile ----
        {
            int jg = kt * 64 + kr;
            int jc = jg > 512 ? 512 : jg;
            const __half *kh_s, *vh_s;
            if (jc == 0) {
                size_t rb = (size_t)b * (3*CC) + h * HD;
                kh_s = qkvch + rb + CC;
                vh_s = qkvch + rb + 2*CC;
            } else {
                int token = nb * SPB + jc;
                size_t rb = (size_t)(b * NN + token) * (3*CC) + h * HD;
                kh_s = qkvh + rb + CC;
                vh_s = qkvh + rb + 2*CC;
            }
            #pragma unroll
            for (int c = 0; c < 4; c++) {
                int chunk = ch0 + c;
                uint32_t sw = kro + (uint32_t)((chunk ^ (kr & 7)) << 4);
                cp16(smb + BK + sw, kh_s + chunk*8);
                cp16(smb + BV + sw, vh_s + chunk*8);
            }
            cp_commit();
        }
        cp_wait<0>();
        __syncthreads();

        // ---- S = Q K^T ----
        float sreg[8][4];
        #pragma unroll
        for (int i = 0; i < 8; i++)
            #pragma unroll
            for (int t = 0; t < 4; t++) sreg[i][t] = 0.0f;

        #pragma unroll
        for (int kk = 0; kk < 4; kk++) {
            int arow = wid*16 + ((sub & 1) << 3) + r8;
            uint32_t aad = smb + BQ + arow*128
                         + (uint32_t)(((kk*2 + (sub >> 1)) ^ (arow & 7)) << 4);
            uint32_t qh[4];
            ldsm4(aad, qh[0], qh[1], qh[2], qh[3]);
            #pragma unroll
            for (int pr = 0; pr < 4; pr++) {
                int brow = pr*16 + ((sub >> 1) << 3) + r8;
                uint32_t bad = smb + BK + brow*128
                             + (uint32_t)(((kk*2 + (sub & 1)) ^ (brow & 7)) << 4);
                uint32_t kh[4];
                ldsm4(bad, kh[0], kh[1], kh[2], kh[3]);
                mma16816(sreg[pr*2    ], qh, &kh[0]);
                mma16816(sreg[pr*2 + 1], qh, &kh[2]);
            }
        }

        // ---- scale + mask ----
        #pragma unroll
        for (int nt = 0; nt < 8; nt++)
            #pragma unroll
            for (int t = 0; t < 4; t++) {
                float v = sreg[nt][t] * SCALE;
                int gcol = kt*64 + nt*8 + (lane & 3)*2 + (t & 1);
                if (gcol > 512) v = -1e30f;
                sreg[nt][t] = v;
            }

        // ---- online softmax ----
        float mt0 = -1e30f, mt1 = -1e30f;
        #pragma unroll
        for (int nt = 0; nt < 8; nt++) {
            mt0 = fmaxf(mt0, fmaxf(sreg[nt][0], sreg[nt][1]));
            mt1 = fmaxf(mt1, fmaxf(sreg[nt][2], sreg[nt][3]));
        }
        mt0 = fmaxf(mt0, __shfl_xor_sync(0xffffffffu, mt0, 1));
        mt0 = fmaxf(mt0, __shfl_xor_sync(0xffffffffu, mt0, 2));
        mt1 = fmaxf(mt1, __shfl_xor_sync(0xffffffffu, mt1, 1));
        mt1 = fmaxf(mt1, __shfl_xor_sync(0xffffffffu, mt1, 2));
        float mn0 = fmaxf(m0, mt0), mn1 = fmaxf(m1, mt1);
        float a0 = __expf(m0 - mn0), a1 = __expf(m1 - mn1);
        m0 = mn0; m1 = mn1;
        float rs0 = 0.0f, rs1 = 0.0f;
        #pragma unroll
        for (int nt = 0; nt < 8; nt++) {
            sreg[nt][0] = __expf(sreg[nt][0] - mn0);
            sreg[nt][1] = __expf(sreg[nt][1] - mn0);
            sreg[nt][2] = __expf(sreg[nt][2] - mn1);
            sreg[nt][3] = __expf(sreg[nt][3] - mn1);
            rs0 += sreg[nt][0] + sreg[nt][1];
            rs1 += sreg[nt][2] + sreg[nt][3];
        }
        rs0 += __shfl_xor_sync(0xffffffffu, rs0, 1);
        rs0 += __shfl_xor_sync(0xffffffffu, rs0, 2);
        rs1 += __shfl_xor_sync(0xffffffffu, rs1, 1);
        rs1 += __shfl_xor_sync(0xffffffffu, rs1, 2);
        l0 = l0 * a0 + rs0;
        l1 = l1 * a1 + rs1;
        #pragma unroll
        for (int dt = 0; dt < 8; dt++) {
            oreg[dt][0] *= a0; oreg[dt][1] *= a0;
            oreg[dt][2] *= a1; oreg[dt][3] *= a1;
        }

        // ---- pack P ----
        uint32_t ph[4][4];
        #pragma unroll
        for (int kc = 0; kc < 4; kc++) {
            ph[kc][0] = pack2h(sreg[2*kc][0],   sreg[2*kc][1]);
            ph[kc][1] = pack2h(sreg[2*kc][2],   sreg[2*kc][3]);
            ph[kc][2] = pack2h(sreg[2*kc+1][0], sreg[2*kc+1][1]);
            ph[kc][3] = pack2h(sreg[2*kc+1][2], sreg[2*kc+1][3]);
        }

        // ---- O += P V ----
        #pragma unroll
        for (int kc = 0; kc < 4; kc++) {
            #pragma unroll
            for (int dg = 0; dg < 4; dg++) {
                int vrow = kc*16 + ((sub & 1) << 3) + r8;
                uint32_t vad = smb + BV + vrow*128
                             + (uint32_t)(((dg*2 + (sub >> 1)) ^ (vrow & 7)) << 4);
                uint32_t vh[4];
                ldsm4t(vad, vh[0], vh[1], vh[2], vh[3]);
                mma16816(oreg[dg*2    ], ph[kc], &vh[0]);
                mma16816(oreg[dg*2 + 1], ph[kc], &vh[2]);
            }
        }
    }

    // ---- write out (scrambled reshape) ----
    float inv0 = 1.0f / l0, inv1 = 1.0f / l1;
    int r4 = lane >> 2, c2 = (lane & 3) * 2;
    #pragma unroll
    for (int dt = 0; dt < 8; dt++) {
        #pragma unroll
        for (int t = 0; t < 4; t++) {
            int rh = t >> 1;
            int sp = qt*64 + wid*16 + r4 + rh*8;
            int dp = dt*8 + c2 + (t & 1);
            float v = oreg[dt][t] * (rh ? inv1 : inv0);
            int linear = h * (SPB * HD) + sp * HD + dp;
            int s_ = linear / CC;
            int c = linear - s_ * CC;
            int token = 1 + nb * SPB + s_;
            yh[(size_t)(b * NN + token) * CC + c] = __float2half_rn(v);
        }
    }
}

// ---------------- launch ----------------
extern "C" void kernel_launch(void* const* d_in, const int* in_sizes, int n_in,
                              void* d_out, int out_size)
{
    const float* x      = (const float*)d_in[0];
    const float* ln1_w  = (const float*)d_in[1];
    const float* ln1_b  = (const float*)d_in[2];
    const float* qkv_w  = (const float*)d_in[3];
    const float* proj_w = (const float*)d_in[4];
    const float* proj_b = (const float*)d_in[5];
    const float* ln2_w  = (const float*)d_in[6];
    const float* ln2_b  = (const float*)d_in[7];
    const float* fc1_w  = (const float*)d_in[8];
    const float* fc1_b  = (const float*)d_in[9];
    const float* fc2_w  = (const float*)d_in[10];
    const float* fc2_b  = (const float*)d_in[11];
    float* out = (float*)d_out;

    float *h1f, *qkvc, *cls, *x2;
    __half *h1h, *qkvh, *qkvch, *yh, *h2h, *f1h;
    __half *wqh, *wph, *w1h, *w2h;
    cudaGetSymbolAddress((void**)&h1f,   g_h1f);
    cudaGetSymbolAddress((void**)&h1h,   g_h1h);
    cudaGetSymbolAddress((void**)&qkvh,  g_qkvh);
    cudaGetSymbolAddress((void**)&qkvc,  g_qkvc);
    cudaGetSymbolAddress((void**)&qkvch, g_qkvch);
    cudaGetSymbolAddress((void**)&cls,   g_cls);
    cudaGetSymbolAddress((void**)&yh,    g_yh);
    cudaGetSymbolAddress((void**)&x2,    g_x2);
    cudaGetSymbolAddress((void**)&h2h,   g_h2h);
    cudaGetSymbolAddress((void**)&f1h,   g_f1h);
    cudaGetSymbolAddress((void**)&wqh,   g_wqh);
    cudaGetSymbolAddress((void**)&wph,   g_wph);
    cudaGetSymbolAddress((void**)&w1h,   g_w1h);
    cudaGetSymbolAddress((void**)&w2h,   g_w2h);

    const int M = MROWS;
    const int smem1 = NSTAGE * 2 * TILE_B + 128;   // 98432
    cudaFuncSetAttribute(tc_gemm<0,3>, cudaFuncAttributeMaxDynamicSharedMemorySize, smem1);
    cudaFuncSetAttribute(tc_gemm<1,0>, cudaFuncAttributeMaxDynamicSharedMemorySize, smem1);
    cudaFuncSetAttribute(tc_gemm<2,3>, cudaFuncAttributeMaxDynamicSharedMemorySize, smem1);
    const int ba_smem = 3*8192 + 128;
    cudaFuncSetAttribute(branch_attn_kernel, cudaFuncAttributeMaxDynamicSharedMemorySize, ba_smem);

    // 0. convert weights to fp16
    cvt_kernel<<<(3*CC*CC/4 + 255)/256, 256>>>(qkv_w,  wqh, 3*CC*CC/4);
    cvt_kernel<<<(CC*CC/4   + 255)/256, 256>>>(proj_w, wph, CC*CC/4);
    cvt_kernel<<<(4*CC*CC/4 + 255)/256, 256>>>(fc1_w,  w1h, 4*CC*CC/4);
    cvt_kernel<<<(4*CC*CC/4 + 255)/256, 256>>>(fc2_w,  w2h, 4*CC*CC/4);

    // 1. LN1 (cls rows fp32 + fp16)
    ln_kernel<<<(M + 7)/8, 256>>>(x, ln1_w, ln1_b, h1f, h1h, M);

    // 2. qkv = h1 @ qkv_w^T  (fp16 out)
    {
        dim3 grid((3*CC)/128, MPAD/128);
        tc_gemm<0,3><<<grid, 256, smem1>>>(h1h, wqh, nullptr, nullptr,
                                           nullptr, qkvh, M, 3*CC, CC);
    }

    // 3. cls global attention
    cls_attn_kernel<<<BB*HH, 256>>>(qkvh, h1f, cls, yh);

    // 4. cls qkv
    cls_qkv_kernel<<<3*CC, 256>>>(cls, qkv_w, qkvc, qkvch);

    // 5. branch attention
    {
        dim3 grid(8, NBB, BB*HH);
        branch_attn_kernel<<<grid, 128, ba_smem>>>(qkvh, qkvch, yh);
    }

    // 6. x2 = x + y @ proj_w^T + proj_b
    {
        dim3 grid(CC/128, MPAD/128);
        tc_gemm<1,0><<<grid, 256, smem1>>>(yh, wph, proj_b, x,
                                           x2, nullptr, M, CC, CC);
    }

    // 7. LN2 (fp16 out)
    ln_kernel<<<(M + 7)/8, 256>>>(x2, ln2_w, ln2_b, nullptr, h2h, M);

    // 8. fc1 + gelu (fp16 out)
    {
        dim3 grid((4*CC)/128, MPAD/128);
        tc_gemm<2,3><<<grid, 256, smem1>>>(h2h, w1h, fc1_b, nullptr,
                                           nullptr, f1h, M, 4*CC, CC);
    }

    // 9. out = x2 + fc1g @ fc2_w^T + fc2_b
    {
        dim3 grid(CC/128, MPAD/128);
        tc_gemm<1,0><<<grid, 256, smem1>>>(f1h, w2h, fc2_b, x2,
                                           out, nullptr, M, CC, 4*CC);
    }
}

// round 9
// speedup vs baseline: 4.2379x; 1.0083x over previous
#include <cuda_runtime.h>
#include <cuda_fp16.h>
#include <math.h>
#include <stdint.h>

// ---------------- problem constants ----------------
#define BB   8
#define NN   2049
#define CC   768
#define HH   12
#define NBB  4
#define HD   64
#define SPB  512
#define MROWS (BB*NN)      // 16392
#define MPAD  16512        // 129 * 128
#define SCALE 0.125f
#define LNEPS 1e-6f

// ---------------- scratch ----------------
__device__ float g_h1f [(size_t)MROWS * CC];       // only cls rows written/read
__device__ __half g_h1h[(size_t)MPAD * CC];
__device__ __half g_qkvh[(size_t)MROWS * 3 * CC];
__device__ float g_qkvc[BB * 3 * CC];
__device__ __half g_qkvch[BB * 3 * CC];
__device__ float g_cls [BB * CC];
__device__ __half g_yh [(size_t)MPAD * CC];
__device__ float g_x2  [(size_t)MROWS * CC];
__device__ __half g_h2h[(size_t)MPAD * CC];
__device__ __half g_f1h[(size_t)MPAD * 4 * CC];
__device__ __half g_wqh[3*CC*CC];
__device__ __half g_wph[CC*CC];
__device__ __half g_w1h[4*CC*CC];
__device__ __half g_w2h[4*CC*CC];

// ---------------- helpers ----------------
__device__ __forceinline__ uint32_t smem_u32(const void* p) {
    return (uint32_t)__cvta_generic_to_shared(p);
}
__device__ __forceinline__ void cp16(uint32_t saddr, const void* g) {
    asm volatile("cp.async.cg.shared.global [%0], [%1], 16;\n" :: "r"(saddr), "l"(g));
}
__device__ __forceinline__ void cp_commit() { asm volatile("cp.async.commit_group;\n"); }
template<int NW> __device__ __forceinline__ void cp_wait() {
    asm volatile("cp.async.wait_group %0;\n" :: "n"(NW));
}
__device__ __forceinline__ void ldsm4(uint32_t addr, uint32_t& r0, uint32_t& r1,
                                      uint32_t& r2, uint32_t& r3) {
    asm volatile("ldmatrix.sync.aligned.m8n8.x4.shared.b16 {%0,%1,%2,%3}, [%4];"
                 : "=r"(r0), "=r"(r1), "=r"(r2), "=r"(r3) : "r"(addr));
}
__device__ __forceinline__ void ldsm4t(uint32_t addr, uint32_t& r0, uint32_t& r1,
                                       uint32_t& r2, uint32_t& r3) {
    asm volatile("ldmatrix.sync.aligned.m8n8.x4.trans.shared.b16 {%0,%1,%2,%3}, [%4];"
                 : "=r"(r0), "=r"(r1), "=r"(r2), "=r"(r3) : "r"(addr));
}
__device__ __forceinline__ void mma16816(float* c, const uint32_t* a, const uint32_t* b) {
    asm volatile("mma.sync.aligned.m16n8k16.row.col.f32.f16.f16.f32 "
        "{%0,%1,%2,%3}, {%4,%5,%6,%7}, {%8,%9}, {%0,%1,%2,%3};"
        : "+f"(c[0]), "+f"(c[1]), "+f"(c[2]), "+f"(c[3])
        : "r"(a[0]), "r"(a[1]), "r"(a[2]), "r"(a[3]), "r"(b[0]), "r"(b[1]));
}
__device__ __forceinline__ uint32_t pack2h(float a, float b) {
    __half2 h = __float22half2_rn(make_float2(a, b));
    return *(uint32_t*)&h;
}

// ---------------- fp32 -> fp16 convert (4 elems/thread) ----------------
__global__ void __launch_bounds__(256) cvt_kernel(const float* __restrict__ in,
                                                  __half* __restrict__ oh, int n4)
{
    int i = blockIdx.x * 256 + threadIdx.x;
    if (i < n4) {
        float4 v = ((const float4*)in)[i];
        uint2 o;
        o.x = pack2h(v.x, v.y);
        o.y = pack2h(v.z, v.w);
        ((uint2*)oh)[i] = o;
    }
}

// ---------------- LayerNorm: warp per row, fp16 out ----------------
__global__ void __launch_bounds__(256) ln_kernel(const float* __restrict__ x,
                                                 const float* __restrict__ w,
                                                 const float* __restrict__ b,
                                                 float* __restrict__ outf,
                                                 __half* __restrict__ oh,
                                                 int rows)
{
    int row = blockIdx.x * 8 + (threadIdx.x >> 5);
    if (row >= rows) return;
    int lane = threadIdx.x & 31;
    const float4* xr = (const float4*)(x + (size_t)row * CC);

    float4 v[6];
    float s = 0.0f;
    #pragma unroll
    for (int i = 0; i < 6; i++) {
        v[i] = xr[i * 32 + lane];
        s += v[i].x + v[i].y + v[i].z + v[i].w;
    }
    #pragma unroll
    for (int o = 16; o; o >>= 1) s += __shfl_xor_sync(0xffffffffu, s, o);
    float mu = s * (1.0f / CC);

    float q = 0.0f;
    #pragma unroll
    for (int i = 0; i < 6; i++) {
        v[i].x -= mu; v[i].y -= mu; v[i].z -= mu; v[i].w -= mu;
        q += v[i].x*v[i].x + v[i].y*v[i].y + v[i].z*v[i].z + v[i].w*v[i].w;
    }
    #pragma unroll
    for (int o = 16; o; o >>= 1) q += __shfl_xor_sync(0xffffffffu, q, o);
    float rs = rsqrtf(q * (1.0f / CC) + LNEPS);

    const float4* w4 = (const float4*)w;
    const float4* b4 = (const float4*)b;
    uint2* oh2 = (uint2*)(oh + (size_t)row * CC);
    bool wf = (outf != nullptr) && (row % NN) == 0;
    float4* of4 = wf ? (float4*)(outf + (size_t)row * CC) : nullptr;

    #pragma unroll
    for (int i = 0; i < 6; i++) {
        float4 wv = w4[i * 32 + lane], bv = b4[i * 32 + lane];
        float o0 = v[i].x * rs * wv.x + bv.x;
        float o1 = v[i].y * rs * wv.y + bv.y;
        float o2 = v[i].z * rs * wv.z + bv.z;
        float o3 = v[i].w * rs * wv.w + bv.w;
        oh2[i * 32 + lane] = make_uint2(pack2h(o0, o1), pack2h(o2, o3));
        if (wf) of4[i * 32 + lane] = make_float4(o0, o1, o2, o3);
    }
}

// ================= single-pass fp16 mma.sync GEMM =================
// C[m][n] = sum_k A[m][k]*W[n][k], fp32 accumulate.
// EPI: 0 none, 1 bias+residual, 2 bias+gelu. OUTM: 0 f32, 3 fp16.
// CTA 128x128x64, 8 warps (2m x 4n), 3-stage cp.async (loads issued BEFORE
// compute each k-tile -> true triple buffering, 1 barrier per tile).
#define TILE_B   16384
#define NSTAGE   3

template<int EPI, int OUTM>
__global__ void __launch_bounds__(256, 1) tc_gemm(
    const __half* __restrict__ Ah, const __half* __restrict__ Wh,
    const float* __restrict__ bias, const float* __restrict__ res,
    float* __restrict__ Cf, __half* __restrict__ Ch,
    int M, int N, int K)
{
    constexpr uint32_t STB = 2 * TILE_B;

    extern __shared__ char dynraw[];
    uint32_t raw = smem_u32(dynraw);
    uint32_t smb = (raw + 127) & ~127u;

    const int tid = threadIdx.x;
    const int bn = blockIdx.x * 128, bm = blockIdx.y * 128;
    const int nt = K >> 6;
    const int lane = tid & 31, wid = tid >> 5;
    const int wm = (wid & 1) * 64, wn = (wid >> 1) * 32;
    const int r8 = lane & 7, sub = lane >> 3;

    const int lrow = tid >> 1;
    const int c0 = (tid & 1) * 4;

    auto load_stage = [&](int kt, int s) {
        uint32_t sb = smb + s * STB;
        size_t goff = (size_t)(kt * 64 + c0 * 8);
        const __half* gAh = Ah + (size_t)(bm + lrow) * K + goff;
        const __half* gWh = Wh + (size_t)(bn + lrow) * K + goff;
        uint32_t ro = lrow * 128;
        #pragma unroll
        for (int c = 0; c < 4; c++) {
            int chunk = c0 + c;
            uint32_t sw = ro + (uint32_t)((chunk ^ (lrow & 7)) << 4);
            cp16(sb          + sw, gAh + c*8);
            cp16(sb + TILE_B + sw, gWh + c*8);
        }
        cp_commit();
    };

    float acc[4][4][4];
    #pragma unroll
    for (int i = 0; i < 4; i++)
        #pragma unroll
        for (int j = 0; j < 4; j++)
            #pragma unroll
            for (int t = 0; t < 4; t++) acc[i][j][t] = 0.0f;

    uint32_t aRowBase[4]; int aKey[4];
    #pragma unroll
    for (int mi = 0; mi < 4; mi++) {
        int row = wm + mi*16 + ((sub & 1) << 3) + r8;
        aRowBase[mi] = row * 128;
        aKey[mi] = row & 7;
    }
    const int aChunkOff = sub >> 1;
    uint32_t bRowBase[2]; int bKey[2];
    #pragma unroll
    for (int pr = 0; pr < 2; pr++) {
        int row = wn + pr*16 + ((sub >> 1) << 3) + r8;
        bRowBase[pr] = row * 128;
        bKey[pr] = row & 7;
    }
    const int bChunkOff = sub & 1;

    load_stage(0, 0);
    load_stage(1, 1);

    for (int kt = 0; kt < nt; kt++) {
        if (kt + 1 < nt) cp_wait<1>(); else cp_wait<0>();
        __syncthreads();
        // prefetch stage kt+2 while computing kt (its buffer was freed by the
        // barrier above: last used by compute of kt-1)
        if (kt + 2 < nt) load_stage(kt + 2, (kt + 2) % NSTAGE);

        uint32_t sb = smb + (kt % NSTAGE) * STB;

        #pragma unroll
        for (int kk = 0; kk < 4; kk++) {
            uint32_t Bh[2][4];
            #pragma unroll
            for (int pr = 0; pr < 2; pr++) {
                int chunk = kk*2 + bChunkOff;
                uint32_t ad = sb + TILE_B + bRowBase[pr]
                            + (uint32_t)((chunk ^ bKey[pr]) << 4);
                ldsm4(ad, Bh[pr][0], Bh[pr][1], Bh[pr][2], Bh[pr][3]);
            }
            #pragma unroll
            for (int mi = 0; mi < 4; mi++) {
                int chunk = kk*2 + aChunkOff;
                uint32_t ad = sb + aRowBase[mi]
                            + (uint32_t)((chunk ^ aKey[mi]) << 4);
                uint32_t Af[4];
                ldsm4(ad, Af[0], Af[1], Af[2], Af[3]);
                #pragma unroll
                for (int ni = 0; ni < 4; ni++) {
                    int pr = ni >> 1, half = (ni & 1) * 2;
                    mma16816(acc[mi][ni], Af, &Bh[pr][half]);
                }
            }
        }
    }

    int r4 = lane >> 2, c2 = (lane & 3) * 2;
    #pragma unroll
    for (int mi = 0; mi < 4; mi++) {
        #pragma unroll
        for (int hh = 0; hh < 2; hh++) {
            int m = bm + wm + mi*16 + r4 + hh*8;
            if (m >= M) continue;
            #pragma unroll
            for (int ni = 0; ni < 4; ni++) {
                int n0 = bn + wn + ni*8 + c2;
                #pragma unroll
                for (int t = 0; t < 2; t++) {
                    int n = n0 + t;
                    float v = acc[mi][ni][hh*2 + t];
                    if (EPI != 0) v += bias[n];
                    size_t idx = (size_t)m * N + n;
                    if (EPI == 1) v += res[idx];
                    if (EPI == 2) v = 0.5f * v * (1.0f + erff(v * 0.7071067811865476f));
                    if (OUTM == 0) Cf[idx] = v;
                    else           Ch[idx] = __float2half_rn(v);
                }
            }
        }
    }
}

// ---------------- cls global attention (512 threads) ----------------
__global__ void __launch_bounds__(512) cls_attn_kernel(const __half* __restrict__ qkvh,
                                                       const float* __restrict__ h1,
                                                       float* __restrict__ cls,
                                                       __half* __restrict__ yh)
{
    __shared__ float sq[64];
    __shared__ float sc[NN];
    __shared__ float red[512];
    __shared__ float so[8][64];

    int bh = blockIdx.x;
    int b = bh / HH, h = bh % HH;
    int tid = threadIdx.x;

    const __half* qbase = qkvh + (size_t)(b * NN) * (3*CC) + h * HD;
    if (tid < 64) sq[tid] = __half2float(qbase[tid]);
    __syncthreads();

    float lmax = -1e30f;
    for (int i = tid; i < NN; i += 512) {
        const __half2* kr = (const __half2*)(qkvh + (size_t)(b * NN + i) * (3*CC) + CC + h * HD);
        float s = 0.0f;
        #pragma unroll 8
        for (int d = 0; d < 32; d++) {
            float2 kv = __half22float2(kr[d]);
            s = fmaf(sq[2*d], kv.x, s);
            s = fmaf(sq[2*d+1], kv.y, s);
        }
        s *= SCALE;
        sc[i] = s;
        lmax = fmaxf(lmax, s);
    }
    red[tid] = lmax; __syncthreads();
    for (int off = 256; off; off >>= 1) {
        if (tid < off) red[tid] = fmaxf(red[tid], red[tid + off]);
        __syncthreads();
    }
    float m = red[0];
    __syncthreads();

    float lsum = 0.0f;
    for (int i = tid; i < NN; i += 512) {
        float e = __expf(sc[i] - m);
        sc[i] = e;
        lsum += e;
    }
    red[tid] = lsum; __syncthreads();
    for (int off = 256; off; off >>= 1) {
        if (tid < off) red[tid] += red[tid + off];
        __syncthreads();
    }
    float l = red[0];
    __syncthreads();

    int d = tid & 63, part = tid >> 6;   // 8 parts
    float o = 0.0f;
    for (int i = part; i < NN; i += 8)
        o = fmaf(sc[i], __half2float(qkvh[(size_t)(b * NN + i) * (3*CC) + 2*CC + h * HD + d]), o);
    so[part][d] = o;
    __syncthreads();

    if (tid < 64) {
        float val = 0.0f;
        #pragma unroll
        for (int p = 0; p < 8; p++) val += so[p][tid];
        val /= l;
        size_t off0 = (size_t)(b * NN) * CC + h * HD + tid;
        float v = val + h1[off0];
        cls[b * CC + h * HD + tid] = v;
        yh[off0] = __float2half_rn(v);
    }
}

// ---------------- cls qkv ----------------
__global__ void __launch_bounds__(256) cls_qkv_kernel(const float* __restrict__ cls,
                                                      const float* __restrict__ qkv_w,
                                                      float* __restrict__ qkvc,
                                                      __half* __restrict__ qkvch)
{
    int j = blockIdx.x;
    int w = threadIdx.x >> 5;
    int lane = threadIdx.x & 31;
    const float* cr = cls + (size_t)w * CC;
    const float* wr = qkv_w + (size_t)j * CC;
    float s = 0.0f;
    for (int k = lane; k < CC; k += 32) s = fmaf(cr[k], wr[k], s);
    #pragma unroll
    for (int off = 16; off; off >>= 1) s += __shfl_xor_sync(0xffffffffu, s, off);
    if (lane == 0) {
        qkvc[w * (3*CC) + j] = s;
        qkvch[w * (3*CC) + j] = __float2half_rn(s);
    }
}

// ---------------- branch attention (FA2 mma, double-buffered K/V) ----------------
#define BQ  0
#define BK0 8192
#define BV0 16384
#define BK1 24576
#define BV1 32768

__global__ void __launch_bounds__(128) branch_attn_kernel(
    const __half* __restrict__ qkvh, const __half* __restrict__ qkvch,
    __half* __restrict__ yh)
{
    extern __shared__ char dynraw[];
    uint32_t raw = smem_u32(dynraw);
    uint32_t smb = (raw + 127) & ~127u;

    const int tid = threadIdx.x;
    const int lane = tid & 31, wid = tid >> 5;
    const int r8 = lane & 7, sub = lane >> 3;
    const int qt = blockIdx.x, nb = blockIdx.y;
    const int b = blockIdx.z / HH, h = blockIdx.z % HH;

    const int kr = tid >> 1;
    const int ch0 = (tid & 1) * 4;
    const uint32_t kro = kr * 128;

    auto load_kv = [&](int kt, int buf) {
        int jg = kt * 64 + kr;
        int jc = jg > 512 ? 512 : jg;
        const __half *kh_s, *vh_s;
        if (jc == 0) {
            size_t rb = (size_t)b * (3*CC) + h * HD;
            kh_s = qkvch + rb + CC;
            vh_s = qkvch + rb + 2*CC;
        } else {
            int token = nb * SPB + jc;
            size_t rb = (size_t)(b * NN + token) * (3*CC) + h * HD;
            kh_s = qkvh + rb + CC;
            vh_s = qkvh + rb + 2*CC;
        }
        uint32_t bk = smb + (buf ? BK1 : BK0);
        uint32_t bv = smb + (buf ? BV1 : BV0);
        #pragma unroll
        for (int c = 0; c < 4; c++) {
            int chunk = ch0 + c;
            uint32_t sw = kro + (uint32_t)((chunk ^ (kr & 7)) << 4);
            cp16(bk + sw, kh_s + chunk*8);
            cp16(bv + sw, vh_s + chunk*8);
        }
        cp_commit();
    };

    // ---- load Q tile (group 0) ----
    {
        int qrow = tid >> 1;
        int token = 1 + nb * SPB + qt * 64 + qrow;
        const __half* gh = qkvh + (size_t)(b * NN + token) * (3*CC) + h * HD;
        uint32_t ro = qrow * 128;
        #pragma unroll
        for (int c = 0; c < 4; c++) {
            int chunk = ch0 + c;
            uint32_t sw = ro + (uint32_t)((chunk ^ (qrow & 7)) << 4);
            cp16(smb + BQ + sw, gh + chunk*8);
        }
        cp_commit();
    }
    // ---- KV tile 0 (group 1) ----
    load_kv(0, 0);

    float m0 = -1e30f, m1 = -1e30f, l0 = 0.0f, l1 = 0.0f;
    float oreg[8][4];
    #pragma unroll
    for (int i = 0; i < 8; i++)
        #pragma unroll
        for (int t = 0; t < 4; t++) oreg[i][t] = 0.0f;

    for (int kt = 0; kt < 9; kt++) {
        __syncthreads();                        // prior compute done -> buffer free
        if (kt + 1 < 9) load_kv(kt + 1, (kt + 1) & 1);
        if (kt + 1 < 9) cp_wait<1>(); else cp_wait<0>();
        __syncthreads();

        uint32_t bk = smb + ((kt & 1) ? BK1 : BK0);
        uint32_t bv = smb + ((kt & 1) ? BV1 : BV0);

        // ---- S = Q K^T ----
        float sreg[8][4];
        #pragma unroll
        for (int i = 0; i < 8; i++)
            #pragma unroll
            for (int t = 0; t < 4; t++) sreg[i][t] = 0.0f;

        #pragma unroll
        for (int kk = 0; kk < 4; kk++) {
            int arow = wid*16 + ((sub & 1) << 3) + r8;
            uint32_t aad = smb + BQ + arow*128
                         + (uint32_t)(((kk*2 + (sub >> 1)) ^ (arow & 7)) << 4);
            uint32_t qh[4];
            ldsm4(aad, qh[0], qh[1], qh[2], qh[3]);
            #pragma unroll
            for (int pr = 0; pr < 4; pr++) {
                int brow = pr*16 + ((sub >> 1) << 3) + r8;
                uint32_t bad = bk + brow*128
                             + (uint32_t)(((kk*2 + (sub & 1)) ^ (brow & 7)) << 4);
                uint32_t kh[4];
                ldsm4(bad, kh[0], kh[1], kh[2], kh[3]);
                mma16816(sreg[pr*2    ], qh, &kh[0]);
                mma16816(sreg[pr*2 + 1], qh, &kh[2]);
            }
        }

        // ---- scale + mask ----
        #pragma unroll
        for (int nt = 0; nt < 8; nt++)
            #pragma unroll
            for (int t = 0; t < 4; t++) {
                float v = sreg[nt][t] * SCALE;
                int gcol = kt*64 + nt*8 + (lane & 3)*2 + (t & 1);
                if (gcol > 512) v = -1e30f;
                sreg[nt][t] = v;
            }

        // ---- online softmax ----
        float mt0 = -1e30f, mt1 = -1e30f;
        #pragma unroll
        for (int nt = 0; nt < 8; nt++) {
            mt0 = fmaxf(mt0, fmaxf(sreg[nt][0], sreg[nt][1]));
            mt1 = fmaxf(mt1, fmaxf(sreg[nt][2], sreg[nt][3]));
        }
        mt0 = fmaxf(mt0, __shfl_xor_sync(0xffffffffu, mt0, 1));
        mt0 = fmaxf(mt0, __shfl_xor_sync(0xffffffffu, mt0, 2));
        mt1 = fmaxf(mt1, __shfl_xor_sync(0xffffffffu, mt1, 1));
        mt1 = fmaxf(mt1, __shfl_xor_sync(0xffffffffu, mt1, 2));
        float mn0 = fmaxf(m0, mt0), mn1 = fmaxf(m1, mt1);
        float a0 = __expf(m0 - mn0), a1 = __expf(m1 - mn1);
        m0 = mn0; m1 = mn1;
        float rs0 = 0.0f, rs1 = 0.0f;
        #pragma unroll
        for (int nt = 0; nt < 8; nt++) {
            sreg[nt][0] = __expf(sreg[nt][0] - mn0);
            sreg[nt][1] = __expf(sreg[nt][1] - mn0);
            sreg[nt][2] = __expf(sreg[nt][2] - mn1);
            sreg[nt][3] = __expf(sreg[nt][3] - mn1);
            rs0 += sreg[nt][0] + sreg[nt][1];
            rs1 += sreg[nt][2] + sreg[nt][3];
        }
        rs0 += __shfl_xor_sync(0xffffffffu, rs0, 1);
        rs0 += __shfl_xor_sync(0xffffffffu, rs0, 2);
        rs1 += __shfl_xor_sync(0xffffffffu, rs1, 1);
        rs1 += __shfl_xor_sync(0xffffffffu, rs1, 2);
        l0 = l0 * a0 + rs0;
        l1 = l1 * a1 + rs1;
        #pragma unroll
        for (int dt = 0; dt < 8; dt++) {
            oreg[dt][0] *= a0; oreg[dt][1] *= a0;
            oreg[dt][2] *= a1; oreg[dt][3] *= a1;
        }

        // ---- pack P ----
        uint32_t ph[4][4];
        #pragma unroll
        for (int kc = 0; kc < 4; kc++) {
            ph[kc][0] = pack2h(sreg[2*kc][0],   sreg[2*kc][1]);
            ph[kc][1] = pack2h(sreg[2*kc][2],   sreg[2*kc][3]);
            ph[kc][2] = pack2h(sreg[2*kc+1][0], sreg[2*kc+1][1]);
            ph[kc][3] = pack2h(sreg[2*kc+1][2], sreg[2*kc+1][3]);
        }

        // ---- O += P V ----
        #pragma unroll
        for (int kc = 0; kc < 4; kc++) {
            #pragma unroll
            for (int dg = 0; dg < 4; dg++) {
                int vrow = kc*16 + ((sub & 1) << 3) + r8;
                uint32_t vad = bv + vrow*128
                             + (uint32_t)(((dg*2 + (sub >> 1)) ^ (vrow & 7)) << 4);
                uint32_t vh[4];
                ldsm4t(vad, vh[0], vh[1], vh[2], vh[3]);
                mma16816(oreg[dg*2    ], ph[kc], &vh[0]);
                mma16816(oreg[dg*2 + 1], ph[kc], &vh[2]);
            }
        }
    }

    // ---- write out (scrambled reshape) ----
    float inv0 = 1.0f / l0, inv1 = 1.0f / l1;
    int r4 = lane >> 2, c2 = (lane & 3) * 2;
    #pragma unroll
    for (int dt = 0; dt < 8; dt++) {
        #pragma unroll
        for (int t = 0; t < 4; t++) {
            int rh = t >> 1;
            int sp = qt*64 + wid*16 + r4 + rh*8;
            int dp = dt*8 + c2 + (t & 1);
            float v = oreg[dt][t] * (rh ? inv1 : inv0);
            int linear = h * (SPB * HD) + sp * HD + dp;
            int s_ = linear / CC;
            int c = linear - s_ * CC;
            int token = 1 + nb * SPB + s_;
            yh[(size_t)(b * NN + token) * CC + c] = __float2half_rn(v);
        }
    }
}

// ---------------- launch ----------------
extern "C" void kernel_launch(void* const* d_in, const int* in_sizes, int n_in,
                              void* d_out, int out_size)
{
    const float* x      = (const float*)d_in[0];
    const float* ln1_w  = (const float*)d_in[1];
    const float* ln1_b  = (const float*)d_in[2];
    const float* qkv_w  = (const float*)d_in[3];
    const float* proj_w = (const float*)d_in[4];
    const float* proj_b = (const float*)d_in[5];
    const float* ln2_w  = (const float*)d_in[6];
    const float* ln2_b  = (const float*)d_in[7];
    const float* fc1_w  = (const float*)d_in[8];
    const float* fc1_b  = (const float*)d_in[9];
    const float* fc2_w  = (const float*)d_in[10];
    const float* fc2_b  = (const float*)d_in[11];
    float* out = (float*)d_out;

    float *h1f, *qkvc, *cls, *x2;
    __half *h1h, *qkvh, *qkvch, *yh, *h2h, *f1h;
    __half *wqh, *wph, *w1h, *w2h;
    cudaGetSymbolAddress((void**)&h1f,   g_h1f);
    cudaGetSymbolAddress((void**)&h1h,   g_h1h);
    cudaGetSymbolAddress((void**)&qkvh,  g_qkvh);
    cudaGetSymbolAddress((void**)&qkvc,  g_qkvc);
    cudaGetSymbolAddress((void**)&qkvch, g_qkvch);
    cudaGetSymbolAddress((void**)&cls,   g_cls);
    cudaGetSymbolAddress((void**)&yh,    g_yh);
    cudaGetSymbolAddress((void**)&x2,    g_x2);
    cudaGetSymbolAddress((void**)&h2h,   g_h2h);
    cudaGetSymbolAddress((void**)&f1h,   g_f1h);
    cudaGetSymbolAddress((void**)&wqh,   g_wqh);
    cudaGetSymbolAddress((void**)&wph,   g_wph);
    cudaGetSymbolAddress((void**)&w1h,   g_w1h);
    cudaGetSymbolAddress((void**)&w2h,   g_w2h);

    const int M = MROWS;
    const int smem1 = NSTAGE * 2 * TILE_B + 128;   // 98432
    cudaFuncSetAttribute(tc_gemm<0,3>, cudaFuncAttributeMaxDynamicSharedMemorySize, smem1);
    cudaFuncSetAttribute(tc_gemm<1,0>, cudaFuncAttributeMaxDynamicSharedMemorySize, smem1);
    cudaFuncSetAttribute(tc_gemm<2,3>, cudaFuncAttributeMaxDynamicSharedMemorySize, smem1);
    const int ba_smem = 5*8192 + 128;              // Q + 2x(K,V)
    cudaFuncSetAttribute(branch_attn_kernel, cudaFuncAttributeMaxDynamicSharedMemorySize, ba_smem);

    // 0. convert weights to fp16
    cvt_kernel<<<(3*CC*CC/4 + 255)/256, 256>>>(qkv_w,  wqh, 3*CC*CC/4);
    cvt_kernel<<<(CC*CC/4   + 255)/256, 256>>>(proj_w, wph, CC*CC/4);
    cvt_kernel<<<(4*CC*CC/4 + 255)/256, 256>>>(fc1_w,  w1h, 4*CC*CC/4);
    cvt_kernel<<<(4*CC*CC/4 + 255)/256, 256>>>(fc2_w,  w2h, 4*CC*CC/4);

    // 1. LN1 (cls rows fp32 + fp16)
    ln_kernel<<<(M + 7)/8, 256>>>(x, ln1_w, ln1_b, h1f, h1h, M);

    // 2. qkv = h1 @ qkv_w^T  (fp16 out)
    {
        dim3 grid((3*CC)/128, MPAD/128);
        tc_gemm<0,3><<<grid, 256, smem1>>>(h1h, wqh, nullptr, nullptr,
                                           nullptr, qkvh, M, 3*CC, CC);
    }

    // 3. cls global attention
    cls_attn_kernel<<<BB*HH, 512>>>(qkvh, h1f, cls, yh);

    // 4. cls qkv
    cls_qkv_kernel<<<3*CC, 256>>>(cls, qkv_w, qkvc, qkvch);

    // 5. branch attention
    {
        dim3 grid(8, NBB, BB*HH);
        branch_attn_kernel<<<grid, 128, ba_smem>>>(qkvh, qkvch, yh);
    }

    // 6. x2 = x + y @ proj_w^T + proj_b
    {
        dim3 grid(CC/128, MPAD/128);
        tc_gemm<1,0><<<grid, 256, smem1>>>(yh, wph, proj_b, x,
                                           x2, nullptr, M, CC, CC);
    }

    // 7. LN2 (fp16 out)
    ln_kernel<<<(M + 7)/8, 256>>>(x2, ln2_w, ln2_b, nullptr, h2h, M);

    // 8. fc1 + gelu (fp16 out)
    {
        dim3 grid((4*CC)/128, MPAD/128);
        tc_gemm<2,3><<<grid, 256, smem1>>>(h2h, w1h, fc1_b, nullptr,
                                           nullptr, f1h, M, 4*CC, CC);
    }

    // 9. out = x2 + fc1g @ fc2_w^T + fc2_b
    {
        dim3 grid(CC/128, MPAD/128);
        tc_gemm<1,0><<<grid, 256, smem1>>>(f1h, w2h, fc2_b, x2,
                                           out, nullptr, M, CC, 4*CC);
    }
}

// round 10
// speedup vs baseline: 4.9912x; 1.1777x over previous
#include <cuda_runtime.h>
#include <cuda_fp16.h>
#include <math.h>
#include <stdint.h>

// ---------------- problem constants ----------------
#define BB   8
#define NN   2049
#define CC   768
#define HH   12
#define NBB  4
#define HD   64
#define SPB  512
#define MROWS (BB*NN)      // 16392
#define MPAD  16512        // 129 * 128
#define SCALE 0.125f
#define LNEPS 1e-6f

// ---------------- scratch ----------------
__device__ float g_h1f [(size_t)MROWS * CC];       // only cls rows written/read
__device__ __half g_h1h[(size_t)MPAD * CC];
__device__ __half g_qkvh[(size_t)MROWS * 3 * CC];
__device__ float g_qkvc[BB * 3 * CC];
__device__ __half g_qkvch[BB * 3 * CC];
__device__ float g_cls [BB * CC];
__device__ __half g_yh [(size_t)MPAD * CC];
__device__ float g_x2  [(size_t)MROWS * CC];
__device__ __half g_h2h[(size_t)MPAD * CC];
__device__ __half g_f1h[(size_t)MPAD * 4 * CC];
__device__ __half g_wqh[3*CC*CC];
__device__ __half g_wph[CC*CC];
__device__ __half g_w1h[4*CC*CC];
__device__ __half g_w2h[4*CC*CC];

// ---------------- helpers ----------------
__device__ __forceinline__ uint32_t smem_u32(const void* p) {
    return (uint32_t)__cvta_generic_to_shared(p);
}
__device__ __forceinline__ void cp16(uint32_t saddr, const void* g) {
    asm volatile("cp.async.cg.shared.global [%0], [%1], 16;\n" :: "r"(saddr), "l"(g));
}
__device__ __forceinline__ void cp_commit() { asm volatile("cp.async.commit_group;\n"); }
template<int NW> __device__ __forceinline__ void cp_wait() {
    asm volatile("cp.async.wait_group %0;\n" :: "n"(NW));
}
__device__ __forceinline__ void ldsm4(uint32_t addr, uint32_t& r0, uint32_t& r1,
                                      uint32_t& r2, uint32_t& r3) {
    asm volatile("ldmatrix.sync.aligned.m8n8.x4.shared.b16 {%0,%1,%2,%3}, [%4];"
                 : "=r"(r0), "=r"(r1), "=r"(r2), "=r"(r3) : "r"(addr));
}
__device__ __forceinline__ void ldsm4t(uint32_t addr, uint32_t& r0, uint32_t& r1,
                                       uint32_t& r2, uint32_t& r3) {
    asm volatile("ldmatrix.sync.aligned.m8n8.x4.trans.shared.b16 {%0,%1,%2,%3}, [%4];"
                 : "=r"(r0), "=r"(r1), "=r"(r2), "=r"(r3) : "r"(addr));
}
__device__ __forceinline__ void mma16816(float* c, const uint32_t* a, const uint32_t* b) {
    asm volatile("mma.sync.aligned.m16n8k16.row.col.f32.f16.f16.f32 "
        "{%0,%1,%2,%3}, {%4,%5,%6,%7}, {%8,%9}, {%0,%1,%2,%3};"
        : "+f"(c[0]), "+f"(c[1]), "+f"(c[2]), "+f"(c[3])
        : "r"(a[0]), "r"(a[1]), "r"(a[2]), "r"(a[3]), "r"(b[0]), "r"(b[1]));
}
__device__ __forceinline__ uint32_t pack2h(float a, float b) {
    __half2 h = __float22half2_rn(make_float2(a, b));
    return *(uint32_t*)&h;
}

// ---------------- fused fp32 -> fp16 convert for all 4 weight arrays ----------------
__global__ void __launch_bounds__(256) cvt4_kernel(
    const float* __restrict__ i0, const float* __restrict__ i1,
    const float* __restrict__ i2, const float* __restrict__ i3,
    __half* __restrict__ o0, __half* __restrict__ o1,
    __half* __restrict__ o2, __half* __restrict__ o3,
    int b1, int b2, int b3)   // cumulative block starts of segments 1..3
{
    int bi = blockIdx.x;
    const float* in; __half* oh; int base;
    if (bi < b1)      { in = i0; oh = o0; base = 0;  }
    else if (bi < b2) { in = i1; oh = o1; base = b1; }
    else if (bi < b3) { in = i2; oh = o2; base = b2; }
    else              { in = i3; oh = o3; base = b3; }
    int i = (bi - base) * 256 + threadIdx.x;
    float4 v = ((const float4*)in)[i];
    uint2 o;
    o.x = pack2h(v.x, v.y);
    o.y = pack2h(v.z, v.w);
    ((uint2*)oh)[i] = o;
}

// ---------------- LayerNorm: warp per row, fp16 out ----------------
__global__ void __launch_bounds__(256) ln_kernel(const float* __restrict__ x,
                                                 const float* __restrict__ w,
                                                 const float* __restrict__ b,
                                                 float* __restrict__ outf,
                                                 __half* __restrict__ oh,
                                                 int rows)
{
    int row = blockIdx.x * 8 + (threadIdx.x >> 5);
    if (row >= rows) return;
    int lane = threadIdx.x & 31;
    const float4* xr = (const float4*)(x + (size_t)row * CC);

    float4 v[6];
    float s = 0.0f;
    #pragma unroll
    for (int i = 0; i < 6; i++) {
        v[i] = xr[i * 32 + lane];
        s += v[i].x + v[i].y + v[i].z + v[i].w;
    }
    #pragma unroll
    for (int o = 16; o; o >>= 1) s += __shfl_xor_sync(0xffffffffu, s, o);
    float mu = s * (1.0f / CC);

    float q = 0.0f;
    #pragma unroll
    for (int i = 0; i < 6; i++) {
        v[i].x -= mu; v[i].y -= mu; v[i].z -= mu; v[i].w -= mu;
        q += v[i].x*v[i].x + v[i].y*v[i].y + v[i].z*v[i].z + v[i].w*v[i].w;
    }
    #pragma unroll
    for (int o = 16; o; o >>= 1) q += __shfl_xor_sync(0xffffffffu, q, o);
    float rs = rsqrtf(q * (1.0f / CC) + LNEPS);

    const float4* w4 = (const float4*)w;
    const float4* b4 = (const float4*)b;
    uint2* oh2 = (uint2*)(oh + (size_t)row * CC);
    bool wf = (outf != nullptr) && (row % NN) == 0;
    float4* of4 = wf ? (float4*)(outf + (size_t)row * CC) : nullptr;

    #pragma unroll
    for (int i = 0; i < 6; i++) {
        float4 wv = w4[i * 32 + lane], bv = b4[i * 32 + lane];
        float o0 = v[i].x * rs * wv.x + bv.x;
        float o1 = v[i].y * rs * wv.y + bv.y;
        float o2 = v[i].z * rs * wv.z + bv.z;
        float o3 = v[i].w * rs * wv.w + bv.w;
        oh2[i * 32 + lane] = make_uint2(pack2h(o0, o1), pack2h(o2, o3));
        if (wf) of4[i * 32 + lane] = make_float4(o0, o1, o2, o3);
    }
}

// ================= single-pass fp16 mma.sync GEMM =================
// C[m][n] = sum_k A[m][k]*W[n][k], fp32 accumulate.
// EPI: 0 none, 1 bias+residual, 2 bias+gelu. OUTM: 0 f32, 3 fp16.
// CTA 128x128x64, 8 warps (2m x 4n), 3-stage cp.async, occupancy 2/SM.
#define TILE_B   16384
#define NSTAGE   3

template<int EPI, int OUTM>
__global__ void __launch_bounds__(256, 2) tc_gemm(
    const __half* __restrict__ Ah, const __half* __restrict__ Wh,
    const float* __restrict__ bias, const float* __restrict__ res,
    float* __restrict__ Cf, __half* __restrict__ Ch,
    int M, int N, int K)
{
    constexpr uint32_t STB = 2 * TILE_B;

    extern __shared__ char dynraw[];
    uint32_t raw = smem_u32(dynraw);
    uint32_t smb = (raw + 127) & ~127u;

    const int tid = threadIdx.x;
    const int bn = blockIdx.x * 128, bm = blockIdx.y * 128;
    const int nt = K >> 6;
    const int lane = tid & 31, wid = tid >> 5;
    const int wm = (wid & 1) * 64, wn = (wid >> 1) * 32;
    const int r8 = lane & 7, sub = lane >> 3;

    const int lrow = tid >> 1;
    const int c0 = (tid & 1) * 4;

    auto load_stage = [&](int kt, int s) {
        uint32_t sb = smb + s * STB;
        size_t goff = (size_t)(kt * 64 + c0 * 8);
        const __half* gAh = Ah + (size_t)(bm + lrow) * K + goff;
        const __half* gWh = Wh + (size_t)(bn + lrow) * K + goff;
        uint32_t ro = lrow * 128;
        #pragma unroll
        for (int c = 0; c < 4; c++) {
            int chunk = c0 + c;
            uint32_t sw = ro + (uint32_t)((chunk ^ (lrow & 7)) << 4);
            cp16(sb          + sw, gAh + c*8);
            cp16(sb + TILE_B + sw, gWh + c*8);
        }
        cp_commit();
    };

    float acc[4][4][4];
    #pragma unroll
    for (int i = 0; i < 4; i++)
        #pragma unroll
        for (int j = 0; j < 4; j++)
            #pragma unroll
            for (int t = 0; t < 4; t++) acc[i][j][t] = 0.0f;

    uint32_t aRowBase[4]; int aKey[4];
    #pragma unroll
    for (int mi = 0; mi < 4; mi++) {
        int row = wm + mi*16 + ((sub & 1) << 3) + r8;
        aRowBase[mi] = row * 128;
        aKey[mi] = row & 7;
    }
    const int aChunkOff = sub >> 1;
    uint32_t bRowBase[2]; int bKey[2];
    #pragma unroll
    for (int pr = 0; pr < 2; pr++) {
        int row = wn + pr*16 + ((sub >> 1) << 3) + r8;
        bRowBase[pr] = row * 128;
        bKey[pr] = row & 7;
    }
    const int bChunkOff = sub & 1;

    load_stage(0, 0);
    load_stage(1, 1);

    for (int kt = 0; kt < nt; kt++) {
        if (kt + 1 < nt) cp_wait<1>(); else cp_wait<0>();
        __syncthreads();
        if (kt + 2 < nt) load_stage(kt + 2, (kt + 2) % NSTAGE);

        uint32_t sb = smb + (kt % NSTAGE) * STB;

        #pragma unroll
        for (int kk = 0; kk < 4; kk++) {
            uint32_t Bh[2][4];
            #pragma unroll
            for (int pr = 0; pr < 2; pr++) {
                int chunk = kk*2 + bChunkOff;
                uint32_t ad = sb + TILE_B + bRowBase[pr]
                            + (uint32_t)((chunk ^ bKey[pr]) << 4);
                ldsm4(ad, Bh[pr][0], Bh[pr][1], Bh[pr][2], Bh[pr][3]);
            }
            #pragma unroll
            for (int mi = 0; mi < 4; mi++) {
                int chunk = kk*2 + aChunkOff;
                uint32_t ad = sb + aRowBase[mi]
                            + (uint32_t)((chunk ^ aKey[mi]) << 4);
                uint32_t Af[4];
                ldsm4(ad, Af[0], Af[1], Af[2], Af[3]);
                #pragma unroll
                for (int ni = 0; ni < 4; ni++) {
                    int pr = ni >> 1, half = (ni & 1) * 2;
                    mma16816(acc[mi][ni], Af, &Bh[pr][half]);
                }
            }
        }
    }

    int r4 = lane >> 2, c2 = (lane & 3) * 2;
    #pragma unroll
    for (int mi = 0; mi < 4; mi++) {
        #pragma unroll
        for (int hh = 0; hh < 2; hh++) {
            int m = bm + wm + mi*16 + r4 + hh*8;
            if (m >= M) continue;
            #pragma unroll
            for (int ni = 0; ni < 4; ni++) {
                int n0 = bn + wn + ni*8 + c2;
                #pragma unroll
                for (int t = 0; t < 2; t++) {
                    int n = n0 + t;
                    float v = acc[mi][ni][hh*2 + t];
                    if (EPI != 0) v += bias[n];
                    size_t idx = (size_t)m * N + n;
                    if (EPI == 1) v += res[idx];
                    if (EPI == 2) v = 0.5f * v * (1.0f + erff(v * 0.7071067811865476f));
                    if (OUTM == 0) Cf[idx] = v;
                    else           Ch[idx] = __float2half_rn(v);
                }
            }
        }
    }
}

// ---------------- cls global attention (512 threads) ----------------
__global__ void __launch_bounds__(512) cls_attn_kernel(const __half* __restrict__ qkvh,
                                                       const float* __restrict__ h1,
                                                       float* __restrict__ cls,
                                                       __half* __restrict__ yh)
{
    __shared__ float sq[64];
    __shared__ float sc[NN];
    __shared__ float red[512];
    __shared__ float so[8][64];

    int bh = blockIdx.x;
    int b = bh / HH, h = bh % HH;
    int tid = threadIdx.x;

    const __half* qbase = qkvh + (size_t)(b * NN) * (3*CC) + h * HD;
    if (tid < 64) sq[tid] = __half2float(qbase[tid]);
    __syncthreads();

    float lmax = -1e30f;
    for (int i = tid; i < NN; i += 512) {
        const __half2* kr = (const __half2*)(qkvh + (size_t)(b * NN + i) * (3*CC) + CC + h * HD);
        float s = 0.0f;
        #pragma unroll 8
        for (int d = 0; d < 32; d++) {
            float2 kv = __half22float2(kr[d]);
            s = fmaf(sq[2*d], kv.x, s);
            s = fmaf(sq[2*d+1], kv.y, s);
        }
        s *= SCALE;
        sc[i] = s;
        lmax = fmaxf(lmax, s);
    }
    red[tid] = lmax; __syncthreads();
    for (int off = 256; off; off >>= 1) {
        if (tid < off) red[tid] = fmaxf(red[tid], red[tid + off]);
        __syncthreads();
    }
    float m = red[0];
    __syncthreads();

    float lsum = 0.0f;
    for (int i = tid; i < NN; i += 512) {
        float e = __expf(sc[i] - m);
        sc[i] = e;
        lsum += e;
    }
    red[tid] = lsum; __syncthreads();
    for (int off = 256; off; off >>= 1) {
        if (tid < off) red[tid] += red[tid + off];
        __syncthreads();
    }
    float l = red[0];
    __syncthreads();

    int d = tid & 63, part = tid >> 6;   // 8 parts
    float o = 0.0f;
    for (int i = part; i < NN; i += 8)
        o = fmaf(sc[i], __half2float(qkvh[(size_t)(b * NN + i) * (3*CC) + 2*CC + h * HD + d]), o);
    so[part][d] = o;
    __syncthreads();

    if (tid < 64) {
        float val = 0.0f;
        #pragma unroll
        for (int p = 0; p < 8; p++) val += so[p][tid];
        val /= l;
        size_t off0 = (size_t)(b * NN) * CC + h * HD + tid;
        float v = val + h1[off0];
        cls[b * CC + h * HD + tid] = v;
        yh[off0] = __float2half_rn(v);
    }
}

// ---------------- cls qkv ----------------
__global__ void __launch_bounds__(256) cls_qkv_kernel(const float* __restrict__ cls,
                                                      const float* __restrict__ qkv_w,
                                                      float* __restrict__ qkvc,
                                                      __half* __restrict__ qkvch)
{
    int j = blockIdx.x;
    int w = threadIdx.x >> 5;
    int lane = threadIdx.x & 31;
    const float* cr = cls + (size_t)w * CC;
    const float* wr = qkv_w + (size_t)j * CC;
    float s = 0.0f;
    for (int k = lane; k < CC; k += 32) s = fmaf(cr[k], wr[k], s);
    #pragma unroll
    for (int off = 16; off; off >>= 1) s += __shfl_xor_sync(0xffffffffu, s, off);
    if (lane == 0) {
        qkvc[w * (3*CC) + j] = s;
        qkvch[w * (3*CC) + j] = __float2half_rn(s);
    }
}

// ---------------- branch attention (FA2 mma, 3-buffer KV ring) ----------------
// smem: Q 8KB + 3 x (K 8KB + V 8KB) = 56KB -> 4 CTAs/SM. ONE barrier per tile.
#define BQ   0
#define BKV  8192   // start of KV ring; buffer b: K at BKV+b*16384, V at +8192

__global__ void __launch_bounds__(128) branch_attn_kernel(
    const __half* __restrict__ qkvh, const __half* __restrict__ qkvch,
    __half* __restrict__ yh)
{
    extern __shared__ char dynraw[];
    uint32_t raw = smem_u32(dynraw);
    uint32_t smb = (raw + 127) & ~127u;

    const int tid = threadIdx.x;
    const int lane = tid & 31, wid = tid >> 5;
    const int r8 = lane & 7, sub = lane >> 3;
    const int qt = blockIdx.x, nb = blockIdx.y;
    const int b = blockIdx.z / HH, h = blockIdx.z % HH;

    const int kr = tid >> 1;
    const int ch0 = (tid & 1) * 4;
    const uint32_t kro = kr * 128;

    auto load_kv = [&](int kt, int buf) {
        int jg = kt * 64 + kr;
        int jc = jg > 512 ? 512 : jg;
        const __half *kh_s, *vh_s;
        if (jc == 0) {
            size_t rb = (size_t)b * (3*CC) + h * HD;
            kh_s = qkvch + rb + CC;
            vh_s = qkvch + rb + 2*CC;
        } else {
            int token = nb * SPB + jc;
            size_t rb = (size_t)(b * NN + token) * (3*CC) + h * HD;
            kh_s = qkvh + rb + CC;
            vh_s = qkvh + rb + 2*CC;
        }
        uint32_t bk = smb + BKV + buf * 16384;
        uint32_t bv = bk + 8192;
        #pragma unroll
        for (int c = 0; c < 4; c++) {
            int chunk = ch0 + c;
            uint32_t sw = kro + (uint32_t)((chunk ^ (kr & 7)) << 4);
            cp16(bk + sw, kh_s + chunk*8);
            cp16(bv + sw, vh_s + chunk*8);
        }
        cp_commit();
    };

    // ---- load Q tile (group 0) ----
    {
        int qrow = tid >> 1;
        int token = 1 + nb * SPB + qt * 64 + qrow;
        const __half* gh = qkvh + (size_t)(b * NN + token) * (3*CC) + h * HD;
        uint32_t ro = qrow * 128;
        #pragma unroll
        for (int c = 0; c < 4; c++) {
            int chunk = ch0 + c;
            uint32_t sw = ro + (uint32_t)((chunk ^ (qrow & 7)) << 4);
            cp16(smb + BQ + sw, gh + chunk*8);
        }
        cp_commit();
    }
    load_kv(0, 0);
    load_kv(1, 1);

    float m0 = -1e30f, m1 = -1e30f, l0 = 0.0f, l1 = 0.0f;
    float oreg[8][4];
    #pragma unroll
    for (int i = 0; i < 8; i++)
        #pragma unroll
        for (int t = 0; t < 4; t++) oreg[i][t] = 0.0f;

    for (int kt = 0; kt < 9; kt++) {
        if (kt < 8) cp_wait<1>(); else cp_wait<0>();
        __syncthreads();   // publishes kv(kt); all threads done with compute(kt-1)
        if (kt + 2 < 9) load_kv(kt + 2, (kt + 2) % 3);  // buffer (kt-1)%3, now free

        uint32_t bk = smb + BKV + (kt % 3) * 16384;
        uint32_t bv = bk + 8192;

        // ---- S = Q K^T ----
        float sreg[8][4];
        #pragma unroll
        for (int i = 0; i < 8; i++)
            #pragma unroll
            for (int t = 0; t < 4; t++) sreg[i][t] = 0.0f;

        #pragma unroll
        for (int kk = 0; kk < 4; kk++) {
            int arow = wid*16 + ((sub & 1) << 3) + r8;
            uint32_t aad = smb + BQ + arow*128
                         + (uint32_t)(((kk*2 + (sub >> 1)) ^ (arow & 7)) << 4);
            uint32_t qh[4];
            ldsm4(aad, qh[0], qh[1], qh[2], qh[3]);
            #pragma unroll
            for (int pr = 0; pr < 4; pr++) {
                int brow = pr*16 + ((sub >> 1) << 3) + r8;
                uint32_t bad = bk + brow*128
                             + (uint32_t)(((kk*2 + (sub & 1)) ^ (brow & 7)) << 4);
                uint32_t kh[4];
                ldsm4(bad, kh[0], kh[1], kh[2], kh[3]);
                mma16816(sreg[pr*2    ], qh, &kh[0]);
                mma16816(sreg[pr*2 + 1], qh, &kh[2]);
            }
        }

        // ---- scale + mask ----
        #pragma unroll
        for (int nt = 0; nt < 8; nt++)
            #pragma unroll
            for (int t = 0; t < 4; t++) {
                float v = sreg[nt][t] * SCALE;
                int gcol = kt*64 + nt*8 + (lane & 3)*2 + (t & 1);
                if (gcol > 512) v = -1e30f;
                sreg[nt][t] = v;
            }

        // ---- online softmax ----
        float mt0 = -1e30f, mt1 = -1e30f;
        #pragma unroll
        for (int nt = 0; nt < 8; nt++) {
            mt0 = fmaxf(mt0, fmaxf(sreg[nt][0], sreg[nt][1]));
            mt1 = fmaxf(mt1, fmaxf(sreg[nt][2], sreg[nt][3]));
        }
        mt0 = fmaxf(mt0, __shfl_xor_sync(0xffffffffu, mt0, 1));
        mt0 = fmaxf(mt0, __shfl_xor_sync(0xffffffffu, mt0, 2));
        mt1 = fmaxf(mt1, __shfl_xor_sync(0xffffffffu, mt1, 1));
        mt1 = fmaxf(mt1, __shfl_xor_sync(0xffffffffu, mt1, 2));
        float mn0 = fmaxf(m0, mt0), mn1 = fmaxf(m1, mt1);
        float a0 = __expf(m0 - mn0), a1 = __expf(m1 - mn1);
        m0 = mn0; m1 = mn1;
        float rs0 = 0.0f, rs1 = 0.0f;
        #pragma unroll
        for (int nt = 0; nt < 8; nt++) {
            sreg[nt][0] = __expf(sreg[nt][0] - mn0);
            sreg[nt][1] = __expf(sreg[nt][1] - mn0);
            sreg[nt][2] = __expf(sreg[nt][2] - mn1);
            sreg[nt][3] = __expf(sreg[nt][3] - mn1);
            rs0 += sreg[nt][0] + sreg[nt][1];
            rs1 += sreg[nt][2] + sreg[nt][3];
        }
        rs0 += __shfl_xor_sync(0xffffffffu, rs0, 1);
        rs0 += __shfl_xor_sync(0xffffffffu, rs0, 2);
        rs1 += __shfl_xor_sync(0xffffffffu, rs1, 1);
        rs1 += __shfl_xor_sync(0xffffffffu, rs1, 2);
        l0 = l0 * a0 + rs0;
        l1 = l1 * a1 + rs1;
        #pragma unroll
        for (int dt = 0; dt < 8; dt++) {
            oreg[dt][0] *= a0; oreg[dt][1] *= a0;
            oreg[dt][2] *= a1; oreg[dt][3] *= a1;
        }

        // ---- pack P ----
        uint32_t ph[4][4];
        #pragma unroll
        for (int kc = 0; kc < 4; kc++) {
            ph[kc][0] = pack2h(sreg[2*kc][0],   sreg[2*kc][1]);
            ph[kc][1] = pack2h(sreg[2*kc][2],   sreg[2*kc][3]);
            ph[kc][2] = pack2h(sreg[2*kc+1][0], sreg[2*kc+1][1]);
            ph[kc][3] = pack2h(sreg[2*kc+1][2], sreg[2*kc+1][3]);
        }

        // ---- O += P V ----
        #pragma unroll
        for (int kc = 0; kc < 4; kc++) {
            #pragma unroll
            for (int dg = 0; dg < 4; dg++) {
                int vrow = kc*16 + ((sub & 1) << 3) + r8;
                uint32_t vad = bv + vrow*128
                             + (uint32_t)(((dg*2 + (sub >> 1)) ^ (vrow & 7)) << 4);
                uint32_t vh[4];
                ldsm4t(vad, vh[0], vh[1], vh[2], vh[3]);
                mma16816(oreg[dg*2    ], ph[kc], &vh[0]);
                mma16816(oreg[dg*2 + 1], ph[kc], &vh[2]);
            }
        }
    }

    // ---- write out (scrambled reshape) ----
    float inv0 = 1.0f / l0, inv1 = 1.0f / l1;
    int r4 = lane >> 2, c2 = (lane & 3) * 2;
    #pragma unroll
    for (int dt = 0; dt < 8; dt++) {
        #pragma unroll
        for (int t = 0; t < 4; t++) {
            int rh = t >> 1;
            int sp = qt*64 + wid*16 + r4 + rh*8;
            int dp = dt*8 + c2 + (t & 1);
            float v = oreg[dt][t] * (rh ? inv1 : inv0);
            int linear = h * (SPB * HD) + sp * HD + dp;
            int s_ = linear / CC;
            int c = linear - s_ * CC;
            int token = 1 + nb * SPB + s_;
            yh[(size_t)(b * NN + token) * CC + c] = __float2half_rn(v);
        }
    }
}

// ---------------- launch ----------------
extern "C" void kernel_launch(void* const* d_in, const int* in_sizes, int n_in,
                              void* d_out, int out_size)
{
    const float* x      = (const float*)d_in[0];
    const float* ln1_w  = (const float*)d_in[1];
    const float* ln1_b  = (const float*)d_in[2];
    const float* qkv_w  = (const float*)d_in[3];
    const float* proj_w = (const float*)d_in[4];
    const float* proj_b = (const float*)d_in[5];
    const float* ln2_w  = (const float*)d_in[6];
    const float* ln2_b  = (const float*)d_in[7];
    const float* fc1_w  = (const float*)d_in[8];
    const float* fc1_b  = (const float*)d_in[9];
    const float* fc2_w  = (const float*)d_in[10];
    const float* fc2_b  = (const float*)d_in[11];
    float* out = (float*)d_out;

    float *h1f, *qkvc, *cls, *x2;
    __half *h1h, *qkvh, *qkvch, *yh, *h2h, *f1h;
    __half *wqh, *wph, *w1h, *w2h;
    cudaGetSymbolAddress((void**)&h1f,   g_h1f);
    cudaGetSymbolAddress((void**)&h1h,   g_h1h);
    cudaGetSymbolAddress((void**)&qkvh,  g_qkvh);
    cudaGetSymbolAddress((void**)&qkvc,  g_qkvc);
    cudaGetSymbolAddress((void**)&qkvch, g_qkvch);
    cudaGetSymbolAddress((void**)&cls,   g_cls);
    cudaGetSymbolAddress((void**)&yh,    g_yh);
    cudaGetSymbolAddress((void**)&x2,    g_x2);
    cudaGetSymbolAddress((void**)&h2h,   g_h2h);
    cudaGetSymbolAddress((void**)&f1h,   g_f1h);
    cudaGetSymbolAddress((void**)&wqh,   g_wqh);
    cudaGetSymbolAddress((void**)&wph,   g_wph);
    cudaGetSymbolAddress((void**)&w1h,   g_w1h);
    cudaGetSymbolAddress((void**)&w2h,   g_w2h);

    const int M = MROWS;
    const int smem1 = NSTAGE * 2 * TILE_B + 128;   // 98432
    cudaFuncSetAttribute(tc_gemm<0,3>, cudaFuncAttributeMaxDynamicSharedMemorySize, smem1);
    cudaFuncSetAttribute(tc_gemm<1,0>, cudaFuncAttributeMaxDynamicSharedMemorySize, smem1);
    cudaFuncSetAttribute(tc_gemm<2,3>, cudaFuncAttributeMaxDynamicSharedMemorySize, smem1);
    const int ba_smem = 8192 + 3*16384 + 128;      // Q + 3x(K,V) = 56KB+pad
    cudaFuncSetAttribute(branch_attn_kernel, cudaFuncAttributeMaxDynamicSharedMemorySize, ba_smem);

    // 0. convert all weights to fp16 in ONE launch
    {
        int nb0 = 3*CC*CC/4/256;   // 1728
        int nb1 = CC*CC/4/256;     // 576
        int nb2 = 4*CC*CC/4/256;   // 2304
        int nb3 = nb2;
        int b1 = nb0, b2 = nb0+nb1, b3 = nb0+nb1+nb2;
        cvt4_kernel<<<b3 + nb3, 256>>>(qkv_w, proj_w, fc1_w, fc2_w,
                                       wqh, wph, w1h, w2h, b1, b2, b3);
    }

    // 1. LN1 (cls rows fp32 + fp16)
    ln_kernel<<<(M + 7)/8, 256>>>(x, ln1_w, ln1_b, h1f, h1h, M);

    // 2. qkv = h1 @ qkv_w^T  (fp16 out)
    {
        dim3 grid((3*CC)/128, MPAD/128);
        tc_gemm<0,3><<<grid, 256, smem1>>>(h1h, wqh, nullptr, nullptr,
                                           nullptr, qkvh, M, 3*CC, CC);
    }

    // 3. cls global attention
    cls_attn_kernel<<<BB*HH, 512>>>(qkvh, h1f, cls, yh);

    // 4. cls qkv
    cls_qkv_kernel<<<3*CC, 256>>>(cls, qkv_w, qkvc, qkvch);

    // 5. branch attention
    {
        dim3 grid(8, NBB, BB*HH);
        branch_attn_kernel<<<grid, 128, ba_smem>>>(qkvh, qkvch, yh);
    }

    // 6. x2 = x + y @ proj_w^T + proj_b
    {
        dim3 grid(CC/128, MPAD/128);
        tc_gemm<1,0><<<grid, 256, smem1>>>(yh, wph, proj_b, x,
                                           x2, nullptr, M, CC, CC);
    }

    // 7. LN2 (fp16 out)
    ln_kernel<<<(M + 7)/8, 256>>>(x2, ln2_w, ln2_b, nullptr, h2h, M);

    // 8. fc1 + gelu (fp16 out)
    {
        dim3 grid((4*CC)/128, MPAD/128);
        tc_gemm<2,3><<<grid, 256, smem1>>>(h2h, w1h, fc1_b, nullptr,
                                           nullptr, f1h, M, 4*CC, CC);
    }

    // 9. out = x2 + fc1g @ fc2_w^T + fc2_b
    {
        dim3 grid(CC/128, MPAD/128);
        tc_gemm<1,0><<<grid, 256, smem1>>>(f1h, w2h, fc2_b, x2,
                                           out, nullptr, M, CC, 4*CC);
    }
}

// round 11
// speedup vs baseline: 5.1635x; 1.0345x over previous
#include <cuda_runtime.h>
#include <cuda_fp16.h>
#include <math.h>
#include <stdint.h>

// ---------------- problem constants ----------------
#define BB   8
#define NN   2049
#define CC   768
#define HH   12
#define NBB  4
#define HD   64
#define SPB  512
#define MROWS (BB*NN)      // 16392
#define MPAD  16512        // 129 * 128
#define SCALE 0.125f
#define LNEPS 1e-6f
#define NSPLIT 8
#define CHUNK 257          // ceil(2049/8)

// ---------------- scratch ----------------
__device__ float g_h1f [(size_t)MROWS * CC];       // only cls rows written/read
__device__ __half g_h1h[(size_t)MPAD * CC];
__device__ __half g_qkvh[(size_t)MROWS * 3 * CC];
__device__ float g_qkvc[BB * 3 * CC];
__device__ __half g_qkvch[BB * 3 * CC];
__device__ float g_cls [BB * CC];
__device__ float g_clsp[BB * HH * NSPLIT * 80];    // partial m,l,o[64]
__device__ __half g_yh [(size_t)MPAD * CC];
__device__ float g_x2  [(size_t)MROWS * CC];
__device__ __half g_h2h[(size_t)MPAD * CC];
__device__ __half g_f1h[(size_t)MPAD * 4 * CC];
__device__ __half g_wqh[3*CC*CC];
__device__ __half g_wph[CC*CC];
__device__ __half g_w1h[4*CC*CC];
__device__ __half g_w2h[4*CC*CC];

// ---------------- helpers ----------------
__device__ __forceinline__ uint32_t smem_u32(const void* p) {
    return (uint32_t)__cvta_generic_to_shared(p);
}
__device__ __forceinline__ void cp16(uint32_t saddr, const void* g) {
    asm volatile("cp.async.cg.shared.global [%0], [%1], 16;\n" :: "r"(saddr), "l"(g));
}
__device__ __forceinline__ void cp_commit() { asm volatile("cp.async.commit_group;\n"); }
template<int NW> __device__ __forceinline__ void cp_wait() {
    asm volatile("cp.async.wait_group %0;\n" :: "n"(NW));
}
__device__ __forceinline__ void ldsm4(uint32_t addr, uint32_t& r0, uint32_t& r1,
                                      uint32_t& r2, uint32_t& r3) {
    asm volatile("ldmatrix.sync.aligned.m8n8.x4.shared.b16 {%0,%1,%2,%3}, [%4];"
                 : "=r"(r0), "=r"(r1), "=r"(r2), "=r"(r3) : "r"(addr));
}
__device__ __forceinline__ void ldsm4t(uint32_t addr, uint32_t& r0, uint32_t& r1,
                                       uint32_t& r2, uint32_t& r3) {
    asm volatile("ldmatrix.sync.aligned.m8n8.x4.trans.shared.b16 {%0,%1,%2,%3}, [%4];"
                 : "=r"(r0), "=r"(r1), "=r"(r2), "=r"(r3) : "r"(addr));
}
__device__ __forceinline__ void mma16816(float* c, const uint32_t* a, const uint32_t* b) {
    asm volatile("mma.sync.aligned.m16n8k16.row.col.f32.f16.f16.f32 "
        "{%0,%1,%2,%3}, {%4,%5,%6,%7}, {%8,%9}, {%0,%1,%2,%3};"
        : "+f"(c[0]), "+f"(c[1]), "+f"(c[2]), "+f"(c[3])
        : "r"(a[0]), "r"(a[1]), "r"(a[2]), "r"(a[3]), "r"(b[0]), "r"(b[1]));
}
__device__ __forceinline__ uint32_t pack2h(float a, float b) {
    __half2 h = __float22half2_rn(make_float2(a, b));
    return *(uint32_t*)&h;
}

// ---------------- fused fp32 -> fp16 convert for all 4 weight arrays ----------------
__global__ void __launch_bounds__(256) cvt4_kernel(
    const float* __restrict__ i0, const float* __restrict__ i1,
    const float* __restrict__ i2, const float* __restrict__ i3,
    __half* __restrict__ o0, __half* __restrict__ o1,
    __half* __restrict__ o2, __half* __restrict__ o3,
    int b1, int b2, int b3)
{
    int bi = blockIdx.x;
    const float* in; __half* oh; int base;
    if (bi < b1)      { in = i0; oh = o0; base = 0;  }
    else if (bi < b2) { in = i1; oh = o1; base = b1; }
    else if (bi < b3) { in = i2; oh = o2; base = b2; }
    else              { in = i3; oh = o3; base = b3; }
    int i = (bi - base) * 256 + threadIdx.x;
    float4 v = ((const float4*)in)[i];
    uint2 o;
    o.x = pack2h(v.x, v.y);
    o.y = pack2h(v.z, v.w);
    ((uint2*)oh)[i] = o;
}

// ---------------- LayerNorm: warp per row, fp16 out ----------------
__global__ void __launch_bounds__(256) ln_kernel(const float* __restrict__ x,
                                                 const float* __restrict__ w,
                                                 const float* __restrict__ b,
                                                 float* __restrict__ outf,
                                                 __half* __restrict__ oh,
                                                 int rows)
{
    int row = blockIdx.x * 8 + (threadIdx.x >> 5);
    if (row >= rows) return;
    int lane = threadIdx.x & 31;
    const float4* xr = (const float4*)(x + (size_t)row * CC);

    float4 v[6];
    float s = 0.0f;
    #pragma unroll
    for (int i = 0; i < 6; i++) {
        v[i] = xr[i * 32 + lane];
        s += v[i].x + v[i].y + v[i].z + v[i].w;
    }
    #pragma unroll
    for (int o = 16; o; o >>= 1) s += __shfl_xor_sync(0xffffffffu, s, o);
    float mu = s * (1.0f / CC);

    float q = 0.0f;
    #pragma unroll
    for (int i = 0; i < 6; i++) {
        v[i].x -= mu; v[i].y -= mu; v[i].z -= mu; v[i].w -= mu;
        q += v[i].x*v[i].x + v[i].y*v[i].y + v[i].z*v[i].z + v[i].w*v[i].w;
    }
    #pragma unroll
    for (int o = 16; o; o >>= 1) q += __shfl_xor_sync(0xffffffffu, q, o);
    float rs = rsqrtf(q * (1.0f / CC) + LNEPS);

    const float4* w4 = (const float4*)w;
    const float4* b4 = (const float4*)b;
    uint2* oh2 = (uint2*)(oh + (size_t)row * CC);
    bool wf = (outf != nullptr) && (row % NN) == 0;
    float4* of4 = wf ? (float4*)(outf + (size_t)row * CC) : nullptr;

    #pragma unroll
    for (int i = 0; i < 6; i++) {
        float4 wv = w4[i * 32 + lane], bv = b4[i * 32 + lane];
        float o0 = v[i].x * rs * wv.x + bv.x;
        float o1 = v[i].y * rs * wv.y + bv.y;
        float o2 = v[i].z * rs * wv.z + bv.z;
        float o3 = v[i].w * rs * wv.w + bv.w;
        oh2[i * 32 + lane] = make_uint2(pack2h(o0, o1), pack2h(o2, o3));
        if (wf) of4[i * 32 + lane] = make_float4(o0, o1, o2, o3);
    }
}

// ================= single-pass fp16 mma.sync GEMM =================
#define TILE_B   16384
#define NSTAGE   3

template<int EPI, int OUTM>
__global__ void __launch_bounds__(256, 2) tc_gemm(
    const __half* __restrict__ Ah, const __half* __restrict__ Wh,
    const float* __restrict__ bias, const float* __restrict__ res,
    float* __restrict__ Cf, __half* __restrict__ Ch,
    int M, int N, int K)
{
    constexpr uint32_t STB = 2 * TILE_B;

    extern __shared__ char dynraw[];
    uint32_t raw = smem_u32(dynraw);
    uint32_t smb = (raw + 127) & ~127u;

    const int tid = threadIdx.x;
    const int bn = blockIdx.x * 128, bm = blockIdx.y * 128;
    const int nt = K >> 6;
    const int lane = tid & 31, wid = tid >> 5;
    const int wm = (wid & 1) * 64, wn = (wid >> 1) * 32;
    const int r8 = lane & 7, sub = lane >> 3;

    const int lrow = tid >> 1;
    const int c0 = (tid & 1) * 4;

    auto load_stage = [&](int kt, int s) {
        uint32_t sb = smb + s * STB;
        size_t goff = (size_t)(kt * 64 + c0 * 8);
        const __half* gAh = Ah + (size_t)(bm + lrow) * K + goff;
        const __half* gWh = Wh + (size_t)(bn + lrow) * K + goff;
        uint32_t ro = lrow * 128;
        #pragma unroll
        for (int c = 0; c < 4; c++) {
            int chunk = c0 + c;
            uint32_t sw = ro + (uint32_t)((chunk ^ (lrow & 7)) << 4);
            cp16(sb          + sw, gAh + c*8);
            cp16(sb + TILE_B + sw, gWh + c*8);
        }
        cp_commit();
    };

    float acc[4][4][4];
    #pragma unroll
    for (int i = 0; i < 4; i++)
        #pragma unroll
        for (int j = 0; j < 4; j++)
            #pragma unroll
            for (int t = 0; t < 4; t++) acc[i][j][t] = 0.0f;

    uint32_t aRowBase[4]; int aKey[4];
    #pragma unroll
    for (int mi = 0; mi < 4; mi++) {
        int row = wm + mi*16 + ((sub & 1) << 3) + r8;
        aRowBase[mi] = row * 128;
        aKey[mi] = row & 7;
    }
    const int aChunkOff = sub >> 1;
    uint32_t bRowBase[2]; int bKey[2];
    #pragma unroll
    for (int pr = 0; pr < 2; pr++) {
        int row = wn + pr*16 + ((sub >> 1) << 3) + r8;
        bRowBase[pr] = row * 128;
        bKey[pr] = row & 7;
    }
    const int bChunkOff = sub & 1;

    load_stage(0, 0);
    load_stage(1, 1);

    for (int kt = 0; kt < nt; kt++) {
        if (kt + 1 < nt) cp_wait<1>(); else cp_wait<0>();
        __syncthreads();
        if (kt + 2 < nt) load_stage(kt + 2, (kt + 2) % NSTAGE);

        uint32_t sb = smb + (kt % NSTAGE) * STB;

        #pragma unroll
        for (int kk = 0; kk < 4; kk++) {
            uint32_t Bh[2][4];
            #pragma unroll
            for (int pr = 0; pr < 2; pr++) {
                int chunk = kk*2 + bChunkOff;
                uint32_t ad = sb + TILE_B + bRowBase[pr]
                            + (uint32_t)((chunk ^ bKey[pr]) << 4);
                ldsm4(ad, Bh[pr][0], Bh[pr][1], Bh[pr][2], Bh[pr][3]);
            }
            #pragma unroll
            for (int mi = 0; mi < 4; mi++) {
                int chunk = kk*2 + aChunkOff;
                uint32_t ad = sb + aRowBase[mi]
                            + (uint32_t)((chunk ^ aKey[mi]) << 4);
                uint32_t Af[4];
                ldsm4(ad, Af[0], Af[1], Af[2], Af[3]);
                #pragma unroll
                for (int ni = 0; ni < 4; ni++) {
                    int pr = ni >> 1, half = (ni & 1) * 2;
                    mma16816(acc[mi][ni], Af, &Bh[pr][half]);
                }
            }
        }
    }

    int r4 = lane >> 2, c2 = (lane & 3) * 2;
    #pragma unroll
    for (int mi = 0; mi < 4; mi++) {
        #pragma unroll
        for (int hh = 0; hh < 2; hh++) {
            int m = bm + wm + mi*16 + r4 + hh*8;
            if (m >= M) continue;
            #pragma unroll
            for (int ni = 0; ni < 4; ni++) {
                int n0 = bn + wn + ni*8 + c2;
                #pragma unroll
                for (int t = 0; t < 2; t++) {
                    int n = n0 + t;
                    float v = acc[mi][ni][hh*2 + t];
                    if (EPI != 0) v += bias[n];
                    size_t idx = (size_t)m * N + n;
                    if (EPI == 1) v += res[idx];
                    if (EPI == 2) v = 0.5f * v * (1.0f + erff(v * 0.7071067811865476f));
                    if (OUTM == 0) Cf[idx] = v;
                    else           Ch[idx] = __float2half_rn(v);
                }
            }
        }
    }
}

// ---------------- cls attention, split-K partials ----------------
// grid (96, NSPLIT), 256 threads. Each block: 257 keys -> partial (m, l, o[64]).
__global__ void __launch_bounds__(256) cls_attn_part(const __half* __restrict__ qkvh,
                                                     float* __restrict__ part)
{
    __shared__ float sq[64];
    __shared__ float sc[CHUNK];
    __shared__ float red[256];
    __shared__ float so[4][64];

    int bh = blockIdx.x, sp = blockIdx.y;
    int b = bh / HH, h = bh % HH;
    int tid = threadIdx.x;
    int i0 = sp * CHUNK;
    int i1 = i0 + CHUNK; if (i1 > NN) i1 = NN;
    int cnt = i1 - i0;

    const __half* qbase = qkvh + (size_t)(b * NN) * (3*CC) + h * HD;
    if (tid < 64) sq[tid] = __half2float(qbase[tid]);
    __syncthreads();

    float lmax = -1e30f;
    for (int j = tid; j < cnt; j += 256) {
        int i = i0 + j;
        const __half2* kr = (const __half2*)(qkvh + (size_t)(b * NN + i) * (3*CC) + CC + h * HD);
        float s = 0.0f;
        #pragma unroll 8
        for (int d = 0; d < 32; d++) {
            float2 kv = __half22float2(kr[d]);
            s = fmaf(sq[2*d], kv.x, s);
            s = fmaf(sq[2*d+1], kv.y, s);
        }
        s *= SCALE;
        sc[j] = s;
        lmax = fmaxf(lmax, s);
    }
    red[tid] = lmax; __syncthreads();
    for (int off = 128; off; off >>= 1) {
        if (tid < off) red[tid] = fmaxf(red[tid], red[tid + off]);
        __syncthreads();
    }
    float m = red[0];
    __syncthreads();

    float lsum = 0.0f;
    for (int j = tid; j < cnt; j += 256) {
        float e = __expf(sc[j] - m);
        sc[j] = e;
        lsum += e;
    }
    red[tid] = lsum; __syncthreads();
    for (int off = 128; off; off >>= 1) {
        if (tid < off) red[tid] += red[tid + off];
        __syncthreads();
    }
    float l = red[0];
    __syncthreads();

    int d = tid & 63, p = tid >> 6;
    float o = 0.0f;
    for (int j = p; j < cnt; j += 4)
        o = fmaf(sc[j], __half2float(qkvh[(size_t)(b * NN + i0 + j) * (3*CC) + 2*CC + h * HD + d]), o);
    so[p][d] = o;
    __syncthreads();

    float* pr = part + (size_t)(bh * NSPLIT + sp) * 80;
    if (tid == 0) { pr[0] = m; pr[1] = l; }
    if (tid < 64) pr[2 + tid] = so[0][tid] + so[1][tid] + so[2][tid] + so[3][tid];
}

// ---------------- cls attention reduce ----------------
// grid 96, 64 threads.
__global__ void __launch_bounds__(64) cls_attn_reduce(const float* __restrict__ part,
                                                      const float* __restrict__ h1,
                                                      float* __restrict__ cls,
                                                      __half* __restrict__ yh)
{
    int bh = blockIdx.x;
    int b = bh / HH, h = bh % HH;
    int d = threadIdx.x;

    const float* pr = part + (size_t)bh * NSPLIT * 80;
    float m = -1e30f;
    #pragma unroll
    for (int s = 0; s < NSPLIT; s++) m = fmaxf(m, pr[s*80]);
    float l = 0.0f, o = 0.0f;
    #pragma unroll
    for (int s = 0; s < NSPLIT; s++) {
        float w = __expf(pr[s*80] - m);
        l += w * pr[s*80 + 1];
        o += w * pr[s*80 + 2 + d];
    }
    float val = o / l;
    size_t off0 = (size_t)(b * NN) * CC + h * HD + d;
    float v = val + h1[off0];
    cls[b * CC + h * HD + d] = v;
    yh[off0] = __float2half_rn(v);
}

// ---------------- cls qkv ----------------
__global__ void __launch_bounds__(256) cls_qkv_kernel(const float* __restrict__ cls,
                                                      const float* __restrict__ qkv_w,
                                                      float* __restrict__ qkvc,
                                                      __half* __restrict__ qkvch)
{
    int j = blockIdx.x;
    int w = threadIdx.x >> 5;
    int lane = threadIdx.x & 31;
    const float* cr = cls + (size_t)w * CC;
    const float* wr = qkv_w + (size_t)j * CC;
    float s = 0.0f;
    for (int k = lane; k < CC; k += 32) s = fmaf(cr[k], wr[k], s);
    #pragma unroll
    for (int off = 16; off; off >>= 1) s += __shfl_xor_sync(0xffffffffu, s, off);
    if (lane == 0) {
        qkvc[w * (3*CC) + j] = s;
        qkvch[w * (3*CC) + j] = __float2half_rn(s);
    }
}

// ---------------- branch attention: 128-query tiles, 8 warps, 3-buffer KV ring ----
// smem: Q 16KB + 3 x 16KB KV = 64KB. grid (4, NBB, 96) = 1536 CTAs.
#define BQ   0
#define BKV  16384

__global__ void __launch_bounds__(256) branch_attn_kernel(
    const __half* __restrict__ qkvh, const __half* __restrict__ qkvch,
    __half* __restrict__ yh)
{
    extern __shared__ char dynraw[];
    uint32_t raw = smem_u32(dynraw);
    uint32_t smb = (raw + 127) & ~127u;

    const int tid = threadIdx.x;
    const int lane = tid & 31, wid = tid >> 5;       // 8 warps
    const int r8 = lane & 7, sub = lane >> 3;
    const int qt = blockIdx.x, nb = blockIdx.y;      // qt 0..3 (128 queries each)
    const int b = blockIdx.z / HH, h = blockIdx.z % HH;

    // KV loaders: 4 threads/row, 2 chunks each
    const int kr = tid >> 2;
    const int kch0 = (tid & 3) * 2;
    const uint32_t kro = kr * 128;

    auto load_kv = [&](int kt, int buf) {
        int jg = kt * 64 + kr;
        int jc = jg > 512 ? 512 : jg;
        const __half *kh_s, *vh_s;
        if (jc == 0) {
            size_t rb = (size_t)b * (3*CC) + h * HD;
            kh_s = qkvch + rb + CC;
            vh_s = qkvch + rb + 2*CC;
        } else {
            int token = nb * SPB + jc;
            size_t rb = (size_t)(b * NN + token) * (3*CC) + h * HD;
            kh_s = qkvh + rb + CC;
            vh_s = qkvh + rb + 2*CC;
        }
        uint32_t bk = smb + BKV + buf * 16384;
        uint32_t bv = bk + 8192;
        #pragma unroll
        for (int c = 0; c < 2; c++) {
            int chunk = kch0 + c;
            uint32_t sw = kro + (uint32_t)((chunk ^ (kr & 7)) << 4);
            cp16(bk + sw, kh_s + chunk*8);
            cp16(bv + sw, vh_s + chunk*8);
        }
        cp_commit();
    };

    // ---- load Q tile (128 rows, 2 threads/row, 4 chunks) ----
    {
        int qrow = tid >> 1;
        int ch0 = (tid & 1) * 4;
        int token = 1 + nb * SPB + qt * 128 + qrow;
        const __half* gh = qkvh + (size_t)(b * NN + token) * (3*CC) + h * HD;
        uint32_t ro = qrow * 128;
        #pragma unroll
        for (int c = 0; c < 4; c++) {
            int chunk = ch0 + c;
            uint32_t sw = ro + (uint32_t)((chunk ^ (qrow & 7)) << 4);
            cp16(smb + BQ + sw, gh + chunk*8);
        }
        cp_commit();
    }
    load_kv(0, 0);
    load_kv(1, 1);

    float m0 = -1e30f, m1 = -1e30f, l0 = 0.0f, l1 = 0.0f;
    float oreg[8][4];
    #pragma unroll
    for (int i = 0; i < 8; i++)
        #pragma unroll
        for (int t = 0; t < 4; t++) oreg[i][t] = 0.0f;

    for (int kt = 0; kt < 9; kt++) {
        if (kt < 8) cp_wait<1>(); else cp_wait<0>();
        __syncthreads();
        if (kt + 2 < 9) load_kv(kt + 2, (kt + 2) % 3);

        uint32_t bk = smb + BKV + (kt % 3) * 16384;
        uint32_t bv = bk + 8192;

        // ---- S = Q K^T ----
        float sreg[8][4];
        #pragma unroll
        for (int i = 0; i < 8; i++)
            #pragma unroll
            for (int t = 0; t < 4; t++) sreg[i][t] = 0.0f;

        #pragma unroll
        for (int kk = 0; kk < 4; kk++) {
            int arow = wid*16 + ((sub & 1) << 3) + r8;
            uint32_t aad = smb + BQ + arow*128
                         + (uint32_t)(((kk*2 + (sub >> 1)) ^ (arow & 7)) << 4);
            uint32_t qh[4];
            ldsm4(aad, qh[0], qh[1], qh[2], qh[3]);
            #pragma unroll
            for (int pr = 0; pr < 4; pr++) {
                int brow = pr*16 + ((sub >> 1) << 3) + r8;
                uint32_t bad = bk + brow*128
                             + (uint32_t)(((kk*2 + (sub & 1)) ^ (brow & 7)) << 4);
                uint32_t kh[4];
                ldsm4(bad, kh[0], kh[1], kh[2], kh[3]);
                mma16816(sreg[pr*2    ], qh, &kh[0]);
                mma16816(sreg[pr*2 + 1], qh, &kh[2]);
            }
        }

        // ---- scale + mask ----
        #pragma unroll
        for (int nt = 0; nt < 8; nt++)
            #pragma unroll
            for (int t = 0; t < 4; t++) {
                float v = sreg[nt][t] * SCALE;
                int gcol = kt*64 + nt*8 + (lane & 3)*2 + (t & 1);
                if (gcol > 512) v = -1e30f;
                sreg[nt][t] = v;
            }

        // ---- online softmax ----
        float mt0 = -1e30f, mt1 = -1e30f;
        #pragma unroll
        for (int nt = 0; nt < 8; nt++) {
            mt0 = fmaxf(mt0, fmaxf(sreg[nt][0], sreg[nt][1]));
            mt1 = fmaxf(mt1, fmaxf(sreg[nt][2], sreg[nt][3]));
        }
        mt0 = fmaxf(mt0, __shfl_xor_sync(0xffffffffu, mt0, 1));
        mt0 = fmaxf(mt0, __shfl_xor_sync(0xffffffffu, mt0, 2));
        mt1 = fmaxf(mt1, __shfl_xor_sync(0xffffffffu, mt1, 1));
        mt1 = fmaxf(mt1, __shfl_xor_sync(0xffffffffu, mt1, 2));
        float mn0 = fmaxf(m0, mt0), mn1 = fmaxf(m1, mt1);
        float a0 = __expf(m0 - mn0), a1 = __expf(m1 - mn1);
        m0 = mn0; m1 = mn1;
        float rs0 = 0.0f, rs1 = 0.0f;
        #pragma unroll
        for (int nt = 0; nt < 8; nt++) {
            sreg[nt][0] = __expf(sreg[nt][0] - mn0);
            sreg[nt][1] = __expf(sreg[nt][1] - mn0);
            sreg[nt][2] = __expf(sreg[nt][2] - mn1);
            sreg[nt][3] = __expf(sreg[nt][3] - mn1);
            rs0 += sreg[nt][0] + sreg[nt][1];
            rs1 += sreg[nt][2] + sreg[nt][3];
        }
        rs0 += __shfl_xor_sync(0xffffffffu, rs0, 1);
        rs0 += __shfl_xor_sync(0xffffffffu, rs0, 2);
        rs1 += __shfl_xor_sync(0xffffffffu, rs1, 1);
        rs1 += __shfl_xor_sync(0xffffffffu, rs1, 2);
        l0 = l0 * a0 + rs0;
        l1 = l1 * a1 + rs1;
        #pragma unroll
        for (int dt = 0; dt < 8; dt++) {
            oreg[dt][0] *= a0; oreg[dt][1] *= a0;
            oreg[dt][2] *= a1; oreg[dt][3] *= a1;
        }

        // ---- pack P ----
        uint32_t ph[4][4];
        #pragma unroll
        for (int kc = 0; kc < 4; kc++) {
            ph[kc][0] = pack2h(sreg[2*kc][0],   sreg[2*kc][1]);
            ph[kc][1] = pack2h(sreg[2*kc][2],   sreg[2*kc][3]);
            ph[kc][2] = pack2h(sreg[2*kc+1][0], sreg[2*kc+1][1]);
            ph[kc][3] = pack2h(sreg[2*kc+1][2], sreg[2*kc+1][3]);
        }

        // ---- O += P V ----
        #pragma unroll
        for (int kc = 0; kc < 4; kc++) {
            #pragma unroll
            for (int dg = 0; dg < 4; dg++) {
                int vrow = kc*16 + ((sub & 1) << 3) + r8;
                uint32_t vad = bv + vrow*128
                             + (uint32_t)(((dg*2 + (sub >> 1)) ^ (vrow & 7)) << 4);
                uint32_t vh[4];
                ldsm4t(vad, vh[0], vh[1], vh[2], vh[3]);
                mma16816(oreg[dg*2    ], ph[kc], &vh[0]);
                mma16816(oreg[dg*2 + 1], ph[kc], &vh[2]);
            }
        }
    }

    // ---- write out (scrambled reshape) ----
    float inv0 = 1.0f / l0, inv1 = 1.0f / l1;
    int r4 = lane >> 2, c2 = (lane & 3) * 2;
    #pragma unroll
    for (int dt = 0; dt < 8; dt++) {
        #pragma unroll
        for (int t = 0; t < 4; t++) {
            int rh = t >> 1;
            int sp = qt*128 + wid*16 + r4 + rh*8;
            int dp = dt*8 + c2 + (t & 1);
            float v = oreg[dt][t] * (rh ? inv1 : inv0);
            int linear = h * (SPB * HD) + sp * HD + dp;
            int s_ = linear / CC;
            int c = linear - s_ * CC;
            int token = 1 + nb * SPB + s_;
            yh[(size_t)(b * NN + token) * CC + c] = __float2half_rn(v);
        }
    }
}

// ---------------- launch ----------------
extern "C" void kernel_launch(void* const* d_in, const int* in_sizes, int n_in,
                              void* d_out, int out_size)
{
    const float* x      = (const float*)d_in[0];
    const float* ln1_w  = (const float*)d_in[1];
    const float* ln1_b  = (const float*)d_in[2];
    const float* qkv_w  = (const float*)d_in[3];
    const float* proj_w = (const float*)d_in[4];
    const float* proj_b = (const float*)d_in[5];
    const float* ln2_w  = (const float*)d_in[6];
    const float* ln2_b  = (const float*)d_in[7];
    const float* fc1_w  = (const float*)d_in[8];
    const float* fc1_b  = (const float*)d_in[9];
    const float* fc2_w  = (const float*)d_in[10];
    const float* fc2_b  = (const float*)d_in[11];
    float* out = (float*)d_out;

    float *h1f, *qkvc, *cls, *clsp, *x2;
    __half *h1h, *qkvh, *qkvch, *yh, *h2h, *f1h;
    __half *wqh, *wph, *w1h, *w2h;
    cudaGetSymbolAddress((void**)&h1f,   g_h1f);
    cudaGetSymbolAddress((void**)&h1h,   g_h1h);
    cudaGetSymbolAddress((void**)&qkvh,  g_qkvh);
    cudaGetSymbolAddress((void**)&qkvc,  g_qkvc);
    cudaGetSymbolAddress((void**)&qkvch, g_qkvch);
    cudaGetSymbolAddress((void**)&cls,   g_cls);
    cudaGetSymbolAddress((void**)&clsp,  g_clsp);
    cudaGetSymbolAddress((void**)&yh,    g_yh);
    cudaGetSymbolAddress((void**)&x2,    g_x2);
    cudaGetSymbolAddress((void**)&h2h,   g_h2h);
    cudaGetSymbolAddress((void**)&f1h,   g_f1h);
    cudaGetSymbolAddress((void**)&wqh,   g_wqh);
    cudaGetSymbolAddress((void**)&wph,   g_wph);
    cudaGetSymbolAddress((void**)&w1h,   g_w1h);
    cudaGetSymbolAddress((void**)&w2h,   g_w2h);

    const int M = MROWS;
    const int smem1 = NSTAGE * 2 * TILE_B + 128;   // 98432
    cudaFuncSetAttribute(tc_gemm<0,3>, cudaFuncAttributeMaxDynamicSharedMemorySize, smem1);
    cudaFuncSetAttribute(tc_gemm<1,0>, cudaFuncAttributeMaxDynamicSharedMemorySize, smem1);
    cudaFuncSetAttribute(tc_gemm<2,3>, cudaFuncAttributeMaxDynamicSharedMemorySize, smem1);
    const int ba_smem = 16384 + 3*16384 + 128;     // Q(128) + 3x(K,V) = 64KB+pad
    cudaFuncSetAttribute(branch_attn_kernel, cudaFuncAttributeMaxDynamicSharedMemorySize, ba_smem);

    // 0. convert all weights to fp16 in ONE launch
    {
        int nb0 = 3*CC*CC/4/256;   // 1728
        int nb1 = CC*CC/4/256;     // 576
        int nb2 = 4*CC*CC/4/256;   // 2304
        int nb3 = nb2;
        int b1 = nb0, b2 = nb0+nb1, b3 = nb0+nb1+nb2;
        cvt4_kernel<<<b3 + nb3, 256>>>(qkv_w, proj_w, fc1_w, fc2_w,
                                       wqh, wph, w1h, w2h, b1, b2, b3);
    }

    // 1. LN1 (cls rows fp32 + fp16)
    ln_kernel<<<(M + 7)/8, 256>>>(x, ln1_w, ln1_b, h1f, h1h, M);

    // 2. qkv = h1 @ qkv_w^T  (fp16 out)
    {
        dim3 grid((3*CC)/128, MPAD/128);
        tc_gemm<0,3><<<grid, 256, smem1>>>(h1h, wqh, nullptr, nullptr,
                                           nullptr, qkvh, M, 3*CC, CC);
    }

    // 3. cls global attention (split-K partials + reduce)
    {
        dim3 grid(BB*HH, NSPLIT);
        cls_attn_part<<<grid, 256>>>(qkvh, clsp);
        cls_attn_reduce<<<BB*HH, 64>>>(clsp, h1f, cls, yh);
    }

    // 4. cls qkv
    cls_qkv_kernel<<<3*CC, 256>>>(cls, qkv_w, qkvc, qkvch);

    // 5. branch attention (128-query tiles)
    {
        dim3 grid(4, NBB, BB*HH);
        branch_attn_kernel<<<grid, 256, ba_smem>>>(qkvh, qkvch, yh);
    }

    // 6. x2 = x + y @ proj_w^T + proj_b
    {
        dim3 grid(CC/128, MPAD/128);
        tc_gemm<1,0><<<grid, 256, smem1>>>(yh, wph, proj_b, x,
                                           x2, nullptr, M, CC, CC);
    }

    // 7. LN2 (fp16 out)
    ln_kernel<<<(M + 7)/8, 256>>>(x2, ln2_w, ln2_b, nullptr, h2h, M);

    // 8. fc1 + gelu (fp16 out)
    {
        dim3 grid((4*CC)/128, MPAD/128);
        tc_gemm<2,3><<<grid, 256, smem1>>>(h2h, w1h, fc1_b, nullptr,
                                           nullptr, f1h, M, 4*CC, CC);
    }

    // 9. out = x2 + fc1g @ fc2_w^T + fc2_b
    {
        dim3 grid(CC/128, MPAD/128);
        tc_gemm<1,0><<<grid, 256, smem1>>>(f1h, w2h, fc2_b, x2,
                                           out, nullptr, M, CC, 4*CC);
    }
}

// round 12
// speedup vs baseline: 5.2507x; 1.0169x over previous
#include <cuda_runtime.h>
#include <cuda_fp16.h>
#include <math.h>
#include <stdint.h>

// ---------------- problem constants ----------------
#define BB   8
#define NN   2049
#define CC   768
#define HH   12
#define NBB  4
#define HD   64
#define SPB  512
#define MROWS (BB*NN)      // 16392
#define MPAD  16512        // 129 * 128
#define SCALE 0.125f
#define LNEPS 1e-6f
#define NSPLIT 8
#define CHUNK 257          // ceil(2049/8)

// ---------------- scratch ----------------
__device__ float g_h1f [(size_t)MROWS * CC];       // only cls rows written/read
__device__ __half g_h1h[(size_t)MPAD * CC];
__device__ __half g_qkvh[(size_t)MROWS * 3 * CC];
__device__ float g_qkvc[BB * 3 * CC];
__device__ __half g_qkvch[BB * 3 * CC];
__device__ float g_cls [BB * CC];
__device__ float g_clsp[BB * HH * NSPLIT * 80];    // partial m,l,o[64]
__device__ __half g_yh [(size_t)MPAD * CC];
__device__ float g_x2  [(size_t)MROWS * CC];
__device__ __half g_h2h[(size_t)MPAD * CC];
__device__ __half g_f1h[(size_t)MPAD * 4 * CC];
__device__ __half g_wqh[3*CC*CC];
__device__ __half g_wph[CC*CC];
__device__ __half g_w1h[4*CC*CC];
__device__ __half g_w2h[4*CC*CC];

// ---------------- helpers ----------------
__device__ __forceinline__ uint32_t smem_u32(const void* p) {
    return (uint32_t)__cvta_generic_to_shared(p);
}
__device__ __forceinline__ void cp16(uint32_t saddr, const void* g) {
    asm volatile("cp.async.cg.shared.global [%0], [%1], 16;\n" :: "r"(saddr), "l"(g));
}
__device__ __forceinline__ void cp_commit() { asm volatile("cp.async.commit_group;\n"); }
template<int NW> __device__ __forceinline__ void cp_wait() {
    asm volatile("cp.async.wait_group %0;\n" :: "n"(NW));
}
__device__ __forceinline__ void ldsm4(uint32_t addr, uint32_t& r0, uint32_t& r1,
                                      uint32_t& r2, uint32_t& r3) {
    asm volatile("ldmatrix.sync.aligned.m8n8.x4.shared.b16 {%0,%1,%2,%3}, [%4];"
                 : "=r"(r0), "=r"(r1), "=r"(r2), "=r"(r3) : "r"(addr));
}
__device__ __forceinline__ void ldsm4t(uint32_t addr, uint32_t& r0, uint32_t& r1,
                                       uint32_t& r2, uint32_t& r3) {
    asm volatile("ldmatrix.sync.aligned.m8n8.x4.trans.shared.b16 {%0,%1,%2,%3}, [%4];"
                 : "=r"(r0), "=r"(r1), "=r"(r2), "=r"(r3) : "r"(addr));
}
__device__ __forceinline__ void mma16816(float* c, const uint32_t* a, const uint32_t* b) {
    asm volatile("mma.sync.aligned.m16n8k16.row.col.f32.f16.f16.f32 "
        "{%0,%1,%2,%3}, {%4,%5,%6,%7}, {%8,%9}, {%0,%1,%2,%3};"
        : "+f"(c[0]), "+f"(c[1]), "+f"(c[2]), "+f"(c[3])
        : "r"(a[0]), "r"(a[1]), "r"(a[2]), "r"(a[3]), "r"(b[0]), "r"(b[1]));
}
__device__ __forceinline__ uint32_t pack2h(float a, float b) {
    __half2 h = __float22half2_rn(make_float2(a, b));
    return *(uint32_t*)&h;
}

// ---------------- fused fp32 -> fp16 convert for all 4 weight arrays ----------------
__global__ void __launch_bounds__(256) cvt4_kernel(
    const float* __restrict__ i0, const float* __restrict__ i1,
    const float* __restrict__ i2, const float* __restrict__ i3,
    __half* __restrict__ o0, __half* __restrict__ o1,
    __half* __restrict__ o2, __half* __restrict__ o3,
    int b1, int b2, int b3)
{
    int bi = blockIdx.x;
    const float* in; __half* oh; int base;
    if (bi < b1)      { in = i0; oh = o0; base = 0;  }
    else if (bi < b2) { in = i1; oh = o1; base = b1; }
    else if (bi < b3) { in = i2; oh = o2; base = b2; }
    else              { in = i3; oh = o3; base = b3; }
    int i = (bi - base) * 256 + threadIdx.x;
    float4 v = ((const float4*)in)[i];
    uint2 o;
    o.x = pack2h(v.x, v.y);
    o.y = pack2h(v.z, v.w);
    ((uint2*)oh)[i] = o;
}

// ---------------- LayerNorm: warp per row, fp16 out ----------------
__global__ void __launch_bounds__(256) ln_kernel(const float* __restrict__ x,
                                                 const float* __restrict__ w,
                                                 const float* __restrict__ b,
                                                 float* __restrict__ outf,
                                                 __half* __restrict__ oh,
                                                 int rows)
{
    int row = blockIdx.x * 8 + (threadIdx.x >> 5);
    if (row >= rows) return;
    int lane = threadIdx.x & 31;
    const float4* xr = (const float4*)(x + (size_t)row * CC);

    float4 v[6];
    float s = 0.0f;
    #pragma unroll
    for (int i = 0; i < 6; i++) {
        v[i] = xr[i * 32 + lane];
        s += v[i].x + v[i].y + v[i].z + v[i].w;
    }
    #pragma unroll
    for (int o = 16; o; o >>= 1) s += __shfl_xor_sync(0xffffffffu, s, o);
    float mu = s * (1.0f / CC);

    float q = 0.0f;
    #pragma unroll
    for (int i = 0; i < 6; i++) {
        v[i].x -= mu; v[i].y -= mu; v[i].z -= mu; v[i].w -= mu;
        q += v[i].x*v[i].x + v[i].y*v[i].y + v[i].z*v[i].z + v[i].w*v[i].w;
    }
    #pragma unroll
    for (int o = 16; o; o >>= 1) q += __shfl_xor_sync(0xffffffffu, q, o);
    float rs = rsqrtf(q * (1.0f / CC) + LNEPS);

    const float4* w4 = (const float4*)w;
    const float4* b4 = (const float4*)b;
    uint2* oh2 = (uint2*)(oh + (size_t)row * CC);
    bool wf = (outf != nullptr) && (row % NN) == 0;
    float4* of4 = wf ? (float4*)(outf + (size_t)row * CC) : nullptr;

    #pragma unroll
    for (int i = 0; i < 6; i++) {
        float4 wv = w4[i * 32 + lane], bv = b4[i * 32 + lane];
        float o0 = v[i].x * rs * wv.x + bv.x;
        float o1 = v[i].y * rs * wv.y + bv.y;
        float o2 = v[i].z * rs * wv.z + bv.z;
        float o3 = v[i].w * rs * wv.w + bv.w;
        oh2[i * 32 + lane] = make_uint2(pack2h(o0, o1), pack2h(o2, o3));
        if (wf) of4[i * 32 + lane] = make_float4(o0, o1, o2, o3);
    }
}

// ================= single-pass fp16 mma.sync GEMM =================
#define TILE_B   16384
#define NSTAGE   3

template<int EPI, int OUTM>
__global__ void __launch_bounds__(256, 2) tc_gemm(
    const __half* __restrict__ Ah, const __half* __restrict__ Wh,
    const float* __restrict__ bias, const float* __restrict__ res,
    float* __restrict__ Cf, __half* __restrict__ Ch,
    int M, int N, int K)
{
    constexpr uint32_t STB = 2 * TILE_B;

    extern __shared__ char dynraw[];
    uint32_t raw = smem_u32(dynraw);
    uint32_t smb = (raw + 127) & ~127u;

    const int tid = threadIdx.x;
    const int bn = blockIdx.x * 128, bm = blockIdx.y * 128;
    const int nt = K >> 6;
    const int lane = tid & 31, wid = tid >> 5;
    const int wm = (wid & 1) * 64, wn = (wid >> 1) * 32;
    const int r8 = lane & 7, sub = lane >> 3;

    const int lrow = tid >> 1;
    const int c0 = (tid & 1) * 4;

    auto load_stage = [&](int kt, int s) {
        uint32_t sb = smb + s * STB;
        size_t goff = (size_t)(kt * 64 + c0 * 8);
        const __half* gAh = Ah + (size_t)(bm + lrow) * K + goff;
        const __half* gWh = Wh + (size_t)(bn + lrow) * K + goff;
        uint32_t ro = lrow * 128;
        #pragma unroll
        for (int c = 0; c < 4; c++) {
            int chunk = c0 + c;
            uint32_t sw = ro + (uint32_t)((chunk ^ (lrow & 7)) << 4);
            cp16(sb          + sw, gAh + c*8);
            cp16(sb + TILE_B + sw, gWh + c*8);
        }
        cp_commit();
    };

    float acc[4][4][4];
    #pragma unroll
    for (int i = 0; i < 4; i++)
        #pragma unroll
        for (int j = 0; j < 4; j++)
            #pragma unroll
            for (int t = 0; t < 4; t++) acc[i][j][t] = 0.0f;

    uint32_t aRowBase[4]; int aKey[4];
    #pragma unroll
    for (int mi = 0; mi < 4; mi++) {
        int row = wm + mi*16 + ((sub & 1) << 3) + r8;
        aRowBase[mi] = row * 128;
        aKey[mi] = row & 7;
    }
    const int aChunkOff = sub >> 1;
    uint32_t bRowBase[2]; int bKey[2];
    #pragma unroll
    for (int pr = 0; pr < 2; pr++) {
        int row = wn + pr*16 + ((sub >> 1) << 3) + r8;
        bRowBase[pr] = row * 128;
        bKey[pr] = row & 7;
    }
    const int bChunkOff = sub & 1;

    load_stage(0, 0);
    load_stage(1, 1);

    for (int kt = 0; kt < nt; kt++) {
        if (kt + 1 < nt) cp_wait<1>(); else cp_wait<0>();
        __syncthreads();
        if (kt + 2 < nt) load_stage(kt + 2, (kt + 2) % NSTAGE);

        uint32_t sb = smb + (kt % NSTAGE) * STB;

        #pragma unroll
        for (int kk = 0; kk < 4; kk++) {
            uint32_t Bh[2][4];
            #pragma unroll
            for (int pr = 0; pr < 2; pr++) {
                int chunk = kk*2 + bChunkOff;
                uint32_t ad = sb + TILE_B + bRowBase[pr]
                            + (uint32_t)((chunk ^ bKey[pr]) << 4);
                ldsm4(ad, Bh[pr][0], Bh[pr][1], Bh[pr][2], Bh[pr][3]);
            }
            #pragma unroll
            for (int mi = 0; mi < 4; mi++) {
                int chunk = kk*2 + aChunkOff;
                uint32_t ad = sb + aRowBase[mi]
                            + (uint32_t)((chunk ^ aKey[mi]) << 4);
                uint32_t Af[4];
                ldsm4(ad, Af[0], Af[1], Af[2], Af[3]);
                #pragma unroll
                for (int ni = 0; ni < 4; ni++) {
                    int pr = ni >> 1, half = (ni & 1) * 2;
                    mma16816(acc[mi][ni], Af, &Bh[pr][half]);
                }
            }
        }
    }

    int r4 = lane >> 2, c2 = (lane & 3) * 2;
    #pragma unroll
    for (int mi = 0; mi < 4; mi++) {
        #pragma unroll
        for (int hh = 0; hh < 2; hh++) {
            int m = bm + wm + mi*16 + r4 + hh*8;
            if (m >= M) continue;
            #pragma unroll
            for (int ni = 0; ni < 4; ni++) {
                int n0 = bn + wn + ni*8 + c2;
                #pragma unroll
                for (int t = 0; t < 2; t++) {
                    int n = n0 + t;
                    float v = acc[mi][ni][hh*2 + t];
                    if (EPI != 0) v += bias[n];
                    size_t idx = (size_t)m * N + n;
                    if (EPI == 1) v += res[idx];
                    if (EPI == 2) v = 0.5f * v * (1.0f + erff(v * 0.7071067811865476f));
                    if (OUTM == 0) Cf[idx] = v;
                    else           Ch[idx] = __float2half_rn(v);
                }
            }
        }
    }
}

// ---------------- cls attention, split-K partials (coalesced QK) ----------------
// grid (96, NSPLIT), 256 threads. Warp covers 4 keys x 8 lanes (16B each).
__global__ void __launch_bounds__(256) cls_attn_part(const __half* __restrict__ qkvh,
                                                     float* __restrict__ part)
{
    __shared__ float sq[64];
    __shared__ float sc[CHUNK];
    __shared__ float red[256];
    __shared__ float so[4][64];

    int bh = blockIdx.x, sp = blockIdx.y;
    int b = bh / HH, h = bh % HH;
    int tid = threadIdx.x;
    int lane = tid & 31, wid = tid >> 5;
    int i0 = sp * CHUNK;
    int i1 = i0 + CHUNK; if (i1 > NN) i1 = NN;
    int cnt = i1 - i0;

    const __half* qbase = qkvh + (size_t)(b * NN) * (3*CC) + h * HD;
    if (tid < 64) sq[tid] = __half2float(qbase[tid]);
    __syncthreads();

    // ---- scores: warp handles 4 keys; 8 lanes/key each load uint4 (16B) ----
    const int g = lane >> 3;          // key slot within warp (0..3)
    const int s8 = lane & 7;          // 16B chunk (0..7)
    float qf[8];
    #pragma unroll
    for (int i = 0; i < 8; i++) qf[i] = sq[s8 * 8 + i];

    float lmax = -1e30f;
    for (int base = 0; base < cnt; base += 32) {
        int j = base + wid * 4 + g;
        float dot = 0.0f;
        if (j < cnt) {
            const uint4* kr = (const uint4*)(qkvh + (size_t)(b * NN + i0 + j) * (3*CC) + CC + h * HD);
            uint4 kv = kr[s8];
            __half2 h0 = *(__half2*)&kv.x, h1v = *(__half2*)&kv.y;
            __half2 h2 = *(__half2*)&kv.z, h3 = *(__half2*)&kv.w;
            float2 f0 = __half22float2(h0), f1 = __half22float2(h1v);
            float2 f2 = __half22float2(h2), f3 = __half22float2(h3);
            dot = qf[0]*f0.x + qf[1]*f0.y + qf[2]*f1.x + qf[3]*f1.y
                + qf[4]*f2.x + qf[5]*f2.y + qf[6]*f3.x + qf[7]*f3.y;
        }
        dot += __shfl_xor_sync(0xffffffffu, dot, 1);
        dot += __shfl_xor_sync(0xffffffffu, dot, 2);
        dot += __shfl_xor_sync(0xffffffffu, dot, 4);
        if (s8 == 0 && j < cnt) {
            float sv = dot * SCALE;
            sc[j] = sv;
            lmax = fmaxf(lmax, sv);
        }
    }
    red[tid] = lmax; __syncthreads();
    for (int off = 128; off; off >>= 1) {
        if (tid < off) red[tid] = fmaxf(red[tid], red[tid + off]);
        __syncthreads();
    }
    float m = red[0];
    __syncthreads();

    float lsum = 0.0f;
    for (int j = tid; j < cnt; j += 256) {
        float e = __expf(sc[j] - m);
        sc[j] = e;
        lsum += e;
    }
    red[tid] = lsum; __syncthreads();
    for (int off = 128; off; off >>= 1) {
        if (tid < off) red[tid] += red[tid + off];
        __syncthreads();
    }
    float l = red[0];
    __syncthreads();

    int d = tid & 63, p = tid >> 6;
    float o = 0.0f;
    for (int j = p; j < cnt; j += 4)
        o = fmaf(sc[j], __half2float(qkvh[(size_t)(b * NN + i0 + j) * (3*CC) + 2*CC + h * HD + d]), o);
    so[p][d] = o;
    __syncthreads();

    float* pr = part + (size_t)(bh * NSPLIT + sp) * 80;
    if (tid == 0) { pr[0] = m; pr[1] = l; }
    if (tid < 64) pr[2 + tid] = so[0][tid] + so[1][tid] + so[2][tid] + so[3][tid];
}

// ---------------- cls attention reduce ----------------
__global__ void __launch_bounds__(64) cls_attn_reduce(const float* __restrict__ part,
                                                      const float* __restrict__ h1,
                                                      float* __restrict__ cls,
                                                      __half* __restrict__ yh)
{
    int bh = blockIdx.x;
    int b = bh / HH, h = bh % HH;
    int d = threadIdx.x;

    const float* pr = part + (size_t)bh * NSPLIT * 80;
    float m = -1e30f;
    #pragma unroll
    for (int s = 0; s < NSPLIT; s++) m = fmaxf(m, pr[s*80]);
    float l = 0.0f, o = 0.0f;
    #pragma unroll
    for (int s = 0; s < NSPLIT; s++) {
        float w = __expf(pr[s*80] - m);
        l += w * pr[s*80 + 1];
        o += w * pr[s*80 + 2 + d];
    }
    float val = o / l;
    size_t off0 = (size_t)(b * NN) * CC + h * HD + d;
    float v = val + h1[off0];
    cls[b * CC + h * HD + d] = v;
    yh[off0] = __float2half_rn(v);
}

// ---------------- cls qkv ----------------
__global__ void __launch_bounds__(256) cls_qkv_kernel(const float* __restrict__ cls,
                                                      const float* __restrict__ qkv_w,
                                                      float* __restrict__ qkvc,
                                                      __half* __restrict__ qkvch)
{
    int j = blockIdx.x;
    int w = threadIdx.x >> 5;
    int lane = threadIdx.x & 31;
    const float* cr = cls + (size_t)w * CC;
    const float* wr = qkv_w + (size_t)j * CC;
    float s = 0.0f;
    for (int k = lane; k < CC; k += 32) s = fmaf(cr[k], wr[k], s);
    #pragma unroll
    for (int off = 16; off; off >>= 1) s += __shfl_xor_sync(0xffffffffu, s, off);
    if (lane == 0) {
        qkvc[w * (3*CC) + j] = s;
        qkvch[w * (3*CC) + j] = __float2half_rn(s);
    }
}

// ---------------- branch attention: 128-query tiles, 8 warps, 3-buffer KV ring ----
#define BQ   0
#define BKV  16384

__global__ void __launch_bounds__(256) branch_attn_kernel(
    const __half* __restrict__ qkvh, const __half* __restrict__ qkvch,
    __half* __restrict__ yh)
{
    extern __shared__ char dynraw[];
    uint32_t raw = smem_u32(dynraw);
    uint32_t smb = (raw + 127) & ~127u;

    const int tid = threadIdx.x;
    const int lane = tid & 31, wid = tid >> 5;
    const int r8 = lane & 7, sub = lane >> 3;
    const int qt = blockIdx.x, nb = blockIdx.y;
    const int b = blockIdx.z / HH, h = blockIdx.z % HH;

    const int kr = tid >> 2;
    const int kch0 = (tid & 3) * 2;
    const uint32_t kro = kr * 128;

    auto load_kv = [&](int kt, int buf) {
        int jg = kt * 64 + kr;
        int jc = jg > 512 ? 512 : jg;
        const __half *kh_s, *vh_s;
        if (jc == 0) {
            size_t rb = (size_t)b * (3*CC) + h * HD;
            kh_s = qkvch + rb + CC;
            vh_s = qkvch + rb + 2*CC;
        } else {
            int token = nb * SPB + jc;
            size_t rb = (size_t)(b * NN + token) * (3*CC) + h * HD;
            kh_s = qkvh + rb + CC;
            vh_s = qkvh + rb + 2*CC;
        }
        uint32_t bk = smb + BKV + buf * 16384;
        uint32_t bv = bk + 8192;
        #pragma unroll
        for (int c = 0; c < 2; c++) {
            int chunk = kch0 + c;
            uint32_t sw = kro + (uint32_t)((chunk ^ (kr & 7)) << 4);
            cp16(bk + sw, kh_s + chunk*8);
            cp16(bv + sw, vh_s + chunk*8);
        }
        cp_commit();
    };

    {
        int qrow = tid >> 1;
        int ch0 = (tid & 1) * 4;
        int token = 1 + nb * SPB + qt * 128 + qrow;
        const __half* gh = qkvh + (size_t)(b * NN + token) * (3*CC) + h * HD;
        uint32_t ro = qrow * 128;
        #pragma unroll
        for (int c = 0; c < 4; c++) {
            int chunk = ch0 + c;
            uint32_t sw = ro + (uint32_t)((chunk ^ (qrow & 7)) << 4);
            cp16(smb + BQ + sw, gh + chunk*8);
        }
        cp_commit();
    }
    load_kv(0, 0);
    load_kv(1, 1);

    float m0 = -1e30f, m1 = -1e30f, l0 = 0.0f, l1 = 0.0f;
    float oreg[8][4];
    #pragma unroll
    for (int i = 0; i < 8; i++)
        #pragma unroll
        for (int t = 0; t < 4; t++) oreg[i][t] = 0.0f;

    for (int kt = 0; kt < 9; kt++) {
        if (kt < 8) cp_wait<1>(); else cp_wait<0>();
        __syncthreads();
        if (kt + 2 < 9) load_kv(kt + 2, (kt + 2) % 3);

        uint32_t bk = smb + BKV + (kt % 3) * 16384;
        uint32_t bv = bk + 8192;

        float sreg[8][4];
        #pragma unroll
        for (int i = 0; i < 8; i++)
            #pragma unroll
            for (int t = 0; t < 4; t++) sreg[i][t] = 0.0f;

        #pragma unroll
        for (int kk = 0; kk < 4; kk++) {
            int arow = wid*16 + ((sub & 1) << 3) + r8;
            uint32_t aad = smb + BQ + arow*128
                         + (uint32_t)(((kk*2 + (sub >> 1)) ^ (arow & 7)) << 4);
            uint32_t qh[4];
            ldsm4(aad, qh[0], qh[1], qh[2], qh[3]);
            #pragma unroll
            for (int pr = 0; pr < 4; pr++) {
                int brow = pr*16 + ((sub >> 1) << 3) + r8;
                uint32_t bad = bk + brow*128
                             + (uint32_t)(((kk*2 + (sub & 1)) ^ (brow & 7)) << 4);
                uint32_t kh[4];
                ldsm4(bad, kh[0], kh[1], kh[2], kh[3]);
                mma16816(sreg[pr*2    ], qh, &kh[0]);
                mma16816(sreg[pr*2 + 1], qh, &kh[2]);
            }
        }

        #pragma unroll
        for (int nt = 0; nt < 8; nt++)
            #pragma unroll
            for (int t = 0; t < 4; t++) {
                float v = sreg[nt][t] * SCALE;
                int gcol = kt*64 + nt*8 + (lane & 3)*2 + (t & 1);
                if (gcol > 512) v = -1e30f;
                sreg[nt][t] = v;
            }

        float mt0 = -1e30f, mt1 = -1e30f;
        #pragma unroll
        for (int nt = 0; nt < 8; nt++) {
            mt0 = fmaxf(mt0, fmaxf(sreg[nt][0], sreg[nt][1]));
            mt1 = fmaxf(mt1, fmaxf(sreg[nt][2], sreg[nt][3]));
        }
        mt0 = fmaxf(mt0, __shfl_xor_sync(0xffffffffu, mt0, 1));
        mt0 = fmaxf(mt0, __shfl_xor_sync(0xffffffffu, mt0, 2));
        mt1 = fmaxf(mt1, __shfl_xor_sync(0xffffffffu, mt1, 1));
        mt1 = fmaxf(mt1, __shfl_xor_sync(0xffffffffu, mt1, 2));
        float mn0 = fmaxf(m0, mt0), mn1 = fmaxf(m1, mt1);
        float a0 = __expf(m0 - mn0), a1 = __expf(m1 - mn1);
        m0 = mn0; m1 = mn1;
        float rs0 = 0.0f, rs1 = 0.0f;
        #pragma unroll
        for (int nt = 0; nt < 8; nt++) {
            sreg[nt][0] = __expf(sreg[nt][0] - mn0);
            sreg[nt][1] = __expf(sreg[nt][1] - mn0);
            sreg[nt][2] = __expf(sreg[nt][2] - mn1);
            sreg[nt][3] = __expf(sreg[nt][3] - mn1);
            rs0 += sreg[nt][0] + sreg[nt][1];
            rs1 += sreg[nt][2] + sreg[nt][3];
        }
        rs0 += __shfl_xor_sync(0xffffffffu, rs0, 1);
        rs0 += __shfl_xor_sync(0xffffffffu, rs0, 2);
        rs1 += __shfl_xor_sync(0xffffffffu, rs1, 1);
        rs1 += __shfl_xor_sync(0xffffffffu, rs1, 2);
        l0 = l0 * a0 + rs0;
        l1 = l1 * a1 + rs1;
        #pragma unroll
        for (int dt = 0; dt < 8; dt++) {
            oreg[dt][0] *= a0; oreg[dt][1] *= a0;
            oreg[dt][2] *= a1; oreg[dt][3] *= a1;
        }

        uint32_t ph[4][4];
        #pragma unroll
        for (int kc = 0; kc < 4; kc++) {
            ph[kc][0] = pack2h(sreg[2*kc][0],   sreg[2*kc][1]);
            ph[kc][1] = pack2h(sreg[2*kc][2],   sreg[2*kc][3]);
            ph[kc][2] = pack2h(sreg[2*kc+1][0], sreg[2*kc+1][1]);
            ph[kc][3] = pack2h(sreg[2*kc+1][2], sreg[2*kc+1][3]);
        }

        #pragma unroll
        for (int kc = 0; kc < 4; kc++) {
            #pragma unroll
            for (int dg = 0; dg < 4; dg++) {
                int vrow = kc*16 + ((sub & 1) << 3) + r8;
                uint32_t vad = bv + vrow*128
                             + (uint32_t)(((dg*2 + (sub >> 1)) ^ (vrow & 7)) << 4);
                uint32_t vh[4];
                ldsm4t(vad, vh[0], vh[1], vh[2], vh[3]);
                mma16816(oreg[dg*2    ], ph[kc], &vh[0]);
                mma16816(oreg[dg*2 + 1], ph[kc], &vh[2]);
            }
        }
    }

    float inv0 = 1.0f / l0, inv1 = 1.0f / l1;
    int r4 = lane >> 2, c2 = (lane & 3) * 2;
    #pragma unroll
    for (int dt = 0; dt < 8; dt++) {
        #pragma unroll
        for (int t = 0; t < 4; t++) {
            int rh = t >> 1;
            int sp = qt*128 + wid*16 + r4 + rh*8;
            int dp = dt*8 + c2 + (t & 1);
            float v = oreg[dt][t] * (rh ? inv1 : inv0);
            int linear = h * (SPB * HD) + sp * HD + dp;
            int s_ = linear / CC;
            int c = linear - s_ * CC;
            int token = 1 + nb * SPB + s_;
            yh[(size_t)(b * NN + token) * CC + c] = __float2half_rn(v);
        }
    }
}

// ---------------- launch ----------------
extern "C" void kernel_launch(void* const* d_in, const int* in_sizes, int n_in,
                              void* d_out, int out_size)
{
    const float* x      = (const float*)d_in[0];
    const float* ln1_w  = (const float*)d_in[1];
    const float* ln1_b  = (const float*)d_in[2];
    const float* qkv_w  = (const float*)d_in[3];
    const float* proj_w = (const float*)d_in[4];
    const float* proj_b = (const float*)d_in[5];
    const float* ln2_w  = (const float*)d_in[6];
    const float* ln2_b  = (const float*)d_in[7];
    const float* fc1_w  = (const float*)d_in[8];
    const float* fc1_b  = (const float*)d_in[9];
    const float* fc2_w  = (const float*)d_in[10];
    const float* fc2_b  = (const float*)d_in[11];
    float* out = (float*)d_out;

    float *h1f, *qkvc, *cls, *clsp, *x2;
    __half *h1h, *qkvh, *qkvch, *yh, *h2h, *f1h;
    __half *wqh, *wph, *w1h, *w2h;
    cudaGetSymbolAddress((void**)&h1f,   g_h1f);
    cudaGetSymbolAddress((void**)&h1h,   g_h1h);
    cudaGetSymbolAddress((void**)&qkvh,  g_qkvh);
    cudaGetSymbolAddress((void**)&qkvc,  g_qkvc);
    cudaGetSymbolAddress((void**)&qkvch, g_qkvch);
    cudaGetSymbolAddress((void**)&cls,   g_cls);
    cudaGetSymbolAddress((void**)&clsp,  g_clsp);
    cudaGetSymbolAddress((void**)&yh,    g_yh);
    cudaGetSymbolAddress((void**)&x2,    g_x2);
    cudaGetSymbolAddress((void**)&h2h,   g_h2h);
    cudaGetSymbolAddress((void**)&f1h,   g_f1h);
    cudaGetSymbolAddress((void**)&wqh,   g_wqh);
    cudaGetSymbolAddress((void**)&wph,   g_wph);
    cudaGetSymbolAddress((void**)&w1h,   g_w1h);
    cudaGetSymbolAddress((void**)&w2h,   g_w2h);

    const int M = MROWS;
    const int smem1 = NSTAGE * 2 * TILE_B + 128;   // 98432
    cudaFuncSetAttribute(tc_gemm<0,3>, cudaFuncAttributeMaxDynamicSharedMemorySize, smem1);
    cudaFuncSetAttribute(tc_gemm<1,0>, cudaFuncAttributeMaxDynamicSharedMemorySize, smem1);
    cudaFuncSetAttribute(tc_gemm<2,3>, cudaFuncAttributeMaxDynamicSharedMemorySize, smem1);
    const int ba_smem = 16384 + 3*16384 + 128;
    cudaFuncSetAttribute(branch_attn_kernel, cudaFuncAttributeMaxDynamicSharedMemorySize, ba_smem);

    // 0. convert all weights to fp16 in ONE launch
    {
        int nb0 = 3*CC*CC/4/256;
        int nb1 = CC*CC/4/256;
        int nb2 = 4*CC*CC/4/256;
        int nb3 = nb2;
        int b1 = nb0, b2 = nb0+nb1, b3 = nb0+nb1+nb2;
        cvt4_kernel<<<b3 + nb3, 256>>>(qkv_w, proj_w, fc1_w, fc2_w,
                                       wqh, wph, w1h, w2h, b1, b2, b3);
    }

    // 1. LN1 (cls rows fp32 + fp16)
    ln_kernel<<<(M + 7)/8, 256>>>(x, ln1_w, ln1_b, h1f, h1h, M);

    // 2. qkv = h1 @ qkv_w^T  (fp16 out)
    {
        dim3 grid((3*CC)/128, MPAD/128);
        tc_gemm<0,3><<<grid, 256, smem1>>>(h1h, wqh, nullptr, nullptr,
                                           nullptr, qkvh, M, 3*CC, CC);
    }

    // 3. cls global attention (split-K partials + reduce)
    {
        dim3 grid(BB*HH, NSPLIT);
        cls_attn_part<<<grid, 256>>>(qkvh, clsp);
        cls_attn_reduce<<<BB*HH, 64>>>(clsp, h1f, cls, yh);
    }

    // 4. cls qkv
    cls_qkv_kernel<<<3*CC, 256>>>(cls, qkv_w, qkvc, qkvch);

    // 5. branch attention (128-query tiles)
    {
        dim3 grid(4, NBB, BB*HH);
        branch_attn_kernel<<<grid, 256, ba_smem>>>(qkvh, qkvch, yh);
    }

    // 6. x2 = x + y @ proj_w^T + proj_b
    {
        dim3 grid(CC/128, MPAD/128);
        tc_gemm<1,0><<<grid, 256, smem1>>>(yh, wph, proj_b, x,
                                           x2, nullptr, M, CC, CC);
    }

    // 7. LN2 (fp16 out)
    ln_kernel<<<(M + 7)/8, 256>>>(x2, ln2_w, ln2_b, nullptr, h2h, M);

    // 8. fc1 + gelu (fp16 out)
    {
        dim3 grid((4*CC)/128, MPAD/128);
        tc_gemm<2,3><<<grid, 256, smem1>>>(h2h, w1h, fc1_b, nullptr,
                                           nullptr, f1h, M, 4*CC, CC);
    }

    // 9. out = x2 + fc1g @ fc2_w^T + fc2_b
    {
        dim3 grid(CC/128, MPAD/128);
        tc_gemm<1,0><<<grid, 256, smem1>>>(f1h, w2h, fc2_b, x2,
                                           out, nullptr, M, CC, 4*CC);
    }
}

// round 13
// speedup vs baseline: 5.2637x; 1.0025x over previous
#include <cuda_runtime.h>
#include <cuda_fp16.h>
#include <math.h>
#include <stdint.h>

// ---------------- problem constants ----------------
#define BB   8
#define NN   2049
#define CC   768
#define HH   12
#define NBB  4
#define HD   64
#define SPB  512
#define MROWS (BB*NN)      // 16392
#define MPAD  16512        // 129 * 128
#define SCALE 0.125f
#define SCALE2 0.18033688011112042f   // SCALE * log2(e)
#define LNEPS 1e-6f
#define NSPLIT 16
#define CHUNK 129          // ceil(2049/16)

// ---------------- scratch ----------------
__device__ float g_h1f [(size_t)MROWS * CC];       // only cls rows written/read
__device__ __half g_h1h[(size_t)MPAD * CC];
__device__ __half g_qkvh[(size_t)MROWS * 3 * CC];
__device__ float g_qkvc[BB * 3 * CC];
__device__ __half g_qkvch[BB * 3 * CC];
__device__ float g_cls [BB * CC];
__device__ float g_clsp[BB * HH * NSPLIT * 80];    // partial m,l,o[64]
__device__ __half g_yh [(size_t)MPAD * CC];
__device__ float g_x2  [(size_t)MROWS * CC];
__device__ __half g_h2h[(size_t)MPAD * CC];
__device__ __half g_f1h[(size_t)MPAD * 4 * CC];
__device__ __half g_wqh[3*CC*CC];
__device__ __half g_wph[CC*CC];
__device__ __half g_w1h[4*CC*CC];
__device__ __half g_w2h[4*CC*CC];

// ---------------- helpers ----------------
__device__ __forceinline__ uint32_t smem_u32(const void* p) {
    return (uint32_t)__cvta_generic_to_shared(p);
}
__device__ __forceinline__ void cp16(uint32_t saddr, const void* g) {
    asm volatile("cp.async.cg.shared.global [%0], [%1], 16;\n" :: "r"(saddr), "l"(g));
}
__device__ __forceinline__ void cp_commit() { asm volatile("cp.async.commit_group;\n"); }
template<int NW> __device__ __forceinline__ void cp_wait() {
    asm volatile("cp.async.wait_group %0;\n" :: "n"(NW));
}
__device__ __forceinline__ void ldsm4(uint32_t addr, uint32_t& r0, uint32_t& r1,
                                      uint32_t& r2, uint32_t& r3) {
    asm volatile("ldmatrix.sync.aligned.m8n8.x4.shared.b16 {%0,%1,%2,%3}, [%4];"
                 : "=r"(r0), "=r"(r1), "=r"(r2), "=r"(r3) : "r"(addr));
}
__device__ __forceinline__ void ldsm4t(uint32_t addr, uint32_t& r0, uint32_t& r1,
                                       uint32_t& r2, uint32_t& r3) {
    asm volatile("ldmatrix.sync.aligned.m8n8.x4.trans.shared.b16 {%0,%1,%2,%3}, [%4];"
                 : "=r"(r0), "=r"(r1), "=r"(r2), "=r"(r3) : "r"(addr));
}
__device__ __forceinline__ void mma16816(float* c, const uint32_t* a, const uint32_t* b) {
    asm volatile("mma.sync.aligned.m16n8k16.row.col.f32.f16.f16.f32 "
        "{%0,%1,%2,%3}, {%4,%5,%6,%7}, {%8,%9}, {%0,%1,%2,%3};"
        : "+f"(c[0]), "+f"(c[1]), "+f"(c[2]), "+f"(c[3])
        : "r"(a[0]), "r"(a[1]), "r"(a[2]), "r"(a[3]), "r"(b[0]), "r"(b[1]));
}
__device__ __forceinline__ uint32_t pack2h(float a, float b) {
    __half2 h = __float22half2_rn(make_float2(a, b));
    return *(uint32_t*)&h;
}

// ---------------- LN row body (warp-collective) ----------------
__device__ __forceinline__ void ln_row(const float* __restrict__ x,
                                       const float* __restrict__ w,
                                       const float* __restrict__ b,
                                       float* __restrict__ outf,
                                       __half* __restrict__ oh,
                                       int row, int lane)
{
    const float4* xr = (const float4*)(x + (size_t)row * CC);

    float4 v[6];
    float s = 0.0f;
    #pragma unroll
    for (int i = 0; i < 6; i++) {
        v[i] = xr[i * 32 + lane];
        s += v[i].x + v[i].y + v[i].z + v[i].w;
    }
    #pragma unroll
    for (int o = 16; o; o >>= 1) s += __shfl_xor_sync(0xffffffffu, s, o);
    float mu = s * (1.0f / CC);

    float q = 0.0f;
    #pragma unroll
    for (int i = 0; i < 6; i++) {
        v[i].x -= mu; v[i].y -= mu; v[i].z -= mu; v[i].w -= mu;
        q += v[i].x*v[i].x + v[i].y*v[i].y + v[i].z*v[i].z + v[i].w*v[i].w;
    }
    #pragma unroll
    for (int o = 16; o; o >>= 1) q += __shfl_xor_sync(0xffffffffu, q, o);
    float rs = rsqrtf(q * (1.0f / CC) + LNEPS);

    const float4* w4 = (const float4*)w;
    const float4* b4 = (const float4*)b;
    uint2* oh2 = (uint2*)(oh + (size_t)row * CC);
    bool wf = (outf != nullptr) && (row % NN) == 0;
    float4* of4 = wf ? (float4*)(outf + (size_t)row * CC) : nullptr;

    #pragma unroll
    for (int i = 0; i < 6; i++) {
        float4 wv = w4[i * 32 + lane], bv = b4[i * 32 + lane];
        float o0 = v[i].x * rs * wv.x + bv.x;
        float o1 = v[i].y * rs * wv.y + bv.y;
        float o2 = v[i].z * rs * wv.z + bv.z;
        float o3 = v[i].w * rs * wv.w + bv.w;
        oh2[i * 32 + lane] = make_uint2(pack2h(o0, o1), pack2h(o2, o3));
        if (wf) of4[i * 32 + lane] = make_float4(o0, o1, o2, o3);
    }
}

// ---------------- prologue: LN1 blocks + weight-convert blocks in ONE launch ---
__global__ void __launch_bounds__(256) prologue_kernel(
    const float* __restrict__ x, const float* __restrict__ ln1_w,
    const float* __restrict__ ln1_b, float* __restrict__ h1f,
    __half* __restrict__ h1h, int ln_blocks,
    const float* __restrict__ i0, const float* __restrict__ i1,
    const float* __restrict__ i2, const float* __restrict__ i3,
    __half* __restrict__ o0, __half* __restrict__ o1,
    __half* __restrict__ o2, __half* __restrict__ o3,
    int c1, int c2, int c3)
{
    int bi = blockIdx.x;
    if (bi < ln_blocks) {
        int row = bi * 8 + (threadIdx.x >> 5);
        if (row < MROWS)
            ln_row(x, ln1_w, ln1_b, h1f, h1h, row, threadIdx.x & 31);
    } else {
        int cb = bi - ln_blocks;
        const float* in; __half* oh; int base;
        if (cb < c1)      { in = i0; oh = o0; base = 0;  }
        else if (cb < c2) { in = i1; oh = o1; base = c1; }
        else if (cb < c3) { in = i2; oh = o2; base = c2; }
        else              { in = i3; oh = o3; base = c3; }
        int i = (cb - base) * 256 + threadIdx.x;
        float4 v = ((const float4*)in)[i];
        uint2 o;
        o.x = pack2h(v.x, v.y);
        o.y = pack2h(v.z, v.w);
        ((uint2*)oh)[i] = o;
    }
}

// ---------------- LN2 (standalone) ----------------
__global__ void __launch_bounds__(256) ln_kernel(const float* __restrict__ x,
                                                 const float* __restrict__ w,
                                                 const float* __restrict__ b,
                                                 __half* __restrict__ oh,
                                                 int rows)
{
    int row = blockIdx.x * 8 + (threadIdx.x >> 5);
    if (row >= rows) return;
    ln_row(x, w, b, nullptr, oh, row, threadIdx.x & 31);
}

// ================= single-pass fp16 mma.sync GEMM =================
#define TILE_B   16384
#define NSTAGE   3

template<int EPI, int OUTM>
__global__ void __launch_bounds__(256, 2) tc_gemm(
    const __half* __restrict__ Ah, const __half* __restrict__ Wh,
    const float* __restrict__ bias, const float* __restrict__ res,
    float* __restrict__ Cf, __half* __restrict__ Ch,
    int M, int N, int K)
{
    constexpr uint32_t STB = 2 * TILE_B;

    extern __shared__ char dynraw[];
    uint32_t raw = smem_u32(dynraw);
    uint32_t smb = (raw + 127) & ~127u;

    const int tid = threadIdx.x;
    const int bn = blockIdx.x * 128, bm = blockIdx.y * 128;
    const int nt = K >> 6;
    const int lane = tid & 31, wid = tid >> 5;
    const int wm = (wid & 1) * 64, wn = (wid >> 1) * 32;
    const int r8 = lane & 7, sub = lane >> 3;

    const int lrow = tid >> 1;
    const int c0 = (tid & 1) * 4;

    auto load_stage = [&](int kt, int s) {
        uint32_t sb = smb + s * STB;
        size_t goff = (size_t)(kt * 64 + c0 * 8);
        const __half* gAh = Ah + (size_t)(bm + lrow) * K + goff;
        const __half* gWh = Wh + (size_t)(bn + lrow) * K + goff;
        uint32_t ro = lrow * 128;
        #pragma unroll
        for (int c = 0; c < 4; c++) {
            int chunk = c0 + c;
            uint32_t sw = ro + (uint32_t)((chunk ^ (lrow & 7)) << 4);
            cp16(sb          + sw, gAh + c*8);
            cp16(sb + TILE_B + sw, gWh + c*8);
        }
        cp_commit();
    };

    float acc[4][4][4];
    #pragma unroll
    for (int i = 0; i < 4; i++)
        #pragma unroll
        for (int j = 0; j < 4; j++)
            #pragma unroll
            for (int t = 0; t < 4; t++) acc[i][j][t] = 0.0f;

    uint32_t aRowBase[4]; int aKey[4];
    #pragma unroll
    for (int mi = 0; mi < 4; mi++) {
        int row = wm + mi*16 + ((sub & 1) << 3) + r8;
        aRowBase[mi] = row * 128;
        aKey[mi] = row & 7;
    }
    const int aChunkOff = sub >> 1;
    uint32_t bRowBase[2]; int bKey[2];
    #pragma unroll
    for (int pr = 0; pr < 2; pr++) {
        int row = wn + pr*16 + ((sub >> 1) << 3) + r8;
        bRowBase[pr] = row * 128;
        bKey[pr] = row & 7;
    }
    const int bChunkOff = sub & 1;

    load_stage(0, 0);
    load_stage(1, 1);

    for (int kt = 0; kt < nt; kt++) {
        if (kt + 1 < nt) cp_wait<1>(); else cp_wait<0>();
        __syncthreads();
        if (kt + 2 < nt) load_stage(kt + 2, (kt + 2) % NSTAGE);

        uint32_t sb = smb + (kt % NSTAGE) * STB;

        #pragma unroll
        for (int kk = 0; kk < 4; kk++) {
            uint32_t Bh[2][4];
            #pragma unroll
            for (int pr = 0; pr < 2; pr++) {
                int chunk = kk*2 + bChunkOff;
                uint32_t ad = sb + TILE_B + bRowBase[pr]
                            + (uint32_t)((chunk ^ bKey[pr]) << 4);
                ldsm4(ad, Bh[pr][0], Bh[pr][1], Bh[pr][2], Bh[pr][3]);
            }
            #pragma unroll
            for (int mi = 0; mi < 4; mi++) {
                int chunk = kk*2 + aChunkOff;
                uint32_t ad = sb + aRowBase[mi]
                            + (uint32_t)((chunk ^ aKey[mi]) << 4);
                uint32_t Af[4];
                ldsm4(ad, Af[0], Af[1], Af[2], Af[3]);
                #pragma unroll
                for (int ni = 0; ni < 4; ni++) {
                    int pr = ni >> 1, half = (ni & 1) * 2;
                    mma16816(acc[mi][ni], Af, &Bh[pr][half]);
                }
            }
        }
    }

    int r4 = lane >> 2, c2 = (lane & 3) * 2;
    #pragma unroll
    for (int mi = 0; mi < 4; mi++) {
        #pragma unroll
        for (int hh = 0; hh < 2; hh++) {
            int m = bm + wm + mi*16 + r4 + hh*8;
            if (m >= M) continue;
            #pragma unroll
            for (int ni = 0; ni < 4; ni++) {
                int n0 = bn + wn + ni*8 + c2;
                #pragma unroll
                for (int t = 0; t < 2; t++) {
                    int n = n0 + t;
                    float v = acc[mi][ni][hh*2 + t];
                    if (EPI != 0) v += bias[n];
                    size_t idx = (size_t)m * N + n;
                    if (EPI == 1) v += res[idx];
                    if (EPI == 2) v = 0.5f * v * (1.0f + erff(v * 0.7071067811865476f));
                    if (OUTM == 0) Cf[idx] = v;
                    else           Ch[idx] = __float2half_rn(v);
                }
            }
        }
    }
}

// ---------------- cls attention, split-K partials (coalesced QK, exp2 domain) ---
__global__ void __launch_bounds__(256) cls_attn_part(const __half* __restrict__ qkvh,
                                                     float* __restrict__ part)
{
    __shared__ float sq[64];
    __shared__ float sc[CHUNK];
    __shared__ float red[256];
    __shared__ float so[4][64];

    int bh = blockIdx.x, sp = blockIdx.y;
    int b = bh / HH, h = bh % HH;
    int tid = threadIdx.x;
    int lane = tid & 31, wid = tid >> 5;
    int i0 = sp * CHUNK;
    int i1 = i0 + CHUNK; if (i1 > NN) i1 = NN;
    int cnt = i1 - i0;

    const __half* qbase = qkvh + (size_t)(b * NN) * (3*CC) + h * HD;
    if (tid < 64) sq[tid] = __half2float(qbase[tid]);
    __syncthreads();

    const int g = lane >> 3;
    const int s8 = lane & 7;
    float qf[8];
    #pragma unroll
    for (int i = 0; i < 8; i++) qf[i] = sq[s8 * 8 + i];

    float lmax = -1e30f;
    for (int base = 0; base < cnt; base += 32) {
        int j = base + wid * 4 + g;
        float dot = 0.0f;
        if (j < cnt) {
            const uint4* kr = (const uint4*)(qkvh + (size_t)(b * NN + i0 + j) * (3*CC) + CC + h * HD);
            uint4 kv = kr[s8];
            __half2 h0 = *(__half2*)&kv.x, h1v = *(__half2*)&kv.y;
            __half2 h2 = *(__half2*)&kv.z, h3 = *(__half2*)&kv.w;
            float2 f0 = __half22float2(h0), f1 = __half22float2(h1v);
            float2 f2 = __half22float2(h2), f3 = __half22float2(h3);
            dot = qf[0]*f0.x + qf[1]*f0.y + qf[2]*f1.x + qf[3]*f1.y
                + qf[4]*f2.x + qf[5]*f2.y + qf[6]*f3.x + qf[7]*f3.y;
        }
        dot += __shfl_xor_sync(0xffffffffu, dot, 1);
        dot += __shfl_xor_sync(0xffffffffu, dot, 2);
        dot += __shfl_xor_sync(0xffffffffu, dot, 4);
        if (s8 == 0 && j < cnt) {
            float sv = dot * SCALE2;          // log2 domain
            sc[j] = sv;
            lmax = fmaxf(lmax, sv);
        }
    }
    red[tid] = lmax; __syncthreads();
    for (int off = 128; off; off >>= 1) {
        if (tid < off) red[tid] = fmaxf(red[tid], red[tid + off]);
        __syncthreads();
    }
    float m = red[0];
    __syncthreads();

    float lsum = 0.0f;
    for (int j = tid; j < cnt; j += 256) {
        float e = exp2f(sc[j] - m);
        sc[j] = e;
        lsum += e;
    }
    red[tid] = lsum; __syncthreads();
    for (int off = 128; off; off >>= 1) {
        if (tid < off) red[tid] += red[tid + off];
        __syncthreads();
    }
    float l = red[0];
    __syncthreads();

    int d = tid & 63, p = tid >> 6;
    float o = 0.0f;
    for (int j = p; j < cnt; j += 4)
        o = fmaf(sc[j], __half2float(qkvh[(size_t)(b * NN + i0 + j) * (3*CC) + 2*CC + h * HD + d]), o);
    so[p][d] = o;
    __syncthreads();

    float* pr = part + (size_t)(bh * NSPLIT + sp) * 80;
    if (tid == 0) { pr[0] = m; pr[1] = l; }
    if (tid < 64) pr[2 + tid] = so[0][tid] + so[1][tid] + so[2][tid] + so[3][tid];
}

// ---------------- cls attention reduce (exp2 domain) ----------------
__global__ void __launch_bounds__(64) cls_attn_reduce(const float* __restrict__ part,
                                                      const float* __restrict__ h1,
                                                      float* __restrict__ cls,
                                                      __half* __restrict__ yh)
{
    int bh = blockIdx.x;
    int b = bh / HH, h = bh % HH;
    int d = threadIdx.x;

    const float* pr = part + (size_t)bh * NSPLIT * 80;
    float m = -1e30f;
    #pragma unroll
    for (int s = 0; s < NSPLIT; s++) m = fmaxf(m, pr[s*80]);
    float l = 0.0f, o = 0.0f;
    #pragma unroll
    for (int s = 0; s < NSPLIT; s++) {
        float w = exp2f(pr[s*80] - m);
        l += w * pr[s*80 + 1];
        o += w * pr[s*80 + 2 + d];
    }
    float val = o / l;
    size_t off0 = (size_t)(b * NN) * CC + h * HD + d;
    float v = val + h1[off0];
    cls[b * CC + h * HD + d] = v;
    yh[off0] = __float2half_rn(v);
}

// ---------------- cls qkv ----------------
__global__ void __launch_bounds__(256) cls_qkv_kernel(const float* __restrict__ cls,
                                                      const float* __restrict__ qkv_w,
                                                      float* __restrict__ qkvc,
                                                      __half* __restrict__ qkvch)
{
    int j = blockIdx.x;
    int w = threadIdx.x >> 5;
    int lane = threadIdx.x & 31;
    const float* cr = cls + (size_t)w * CC;
    const float* wr = qkv_w + (size_t)j * CC;
    float s = 0.0f;
    for (int k = lane; k < CC; k += 32) s = fmaf(cr[k], wr[k], s);
    #pragma unroll
    for (int off = 16; off; off >>= 1) s += __shfl_xor_sync(0xffffffffu, s, off);
    if (lane == 0) {
        qkvc[w * (3*CC) + j] = s;
        qkvch[w * (3*CC) + j] = __float2half_rn(s);
    }
}

// ---------------- branch attention: 128-query tiles, 8 warps, 3-buffer KV ring ----
#define BQ   0
#define BKV  16384

__global__ void __launch_bounds__(256) branch_attn_kernel(
    const __half* __restrict__ qkvh, const __half* __restrict__ qkvch,
    __half* __restrict__ yh)
{
    extern __shared__ char dynraw[];
    uint32_t raw = smem_u32(dynraw);
    uint32_t smb = (raw + 127) & ~127u;

    const int tid = threadIdx.x;
    const int lane = tid & 31, wid = tid >> 5;
    const int r8 = lane & 7, sub = lane >> 3;
    const int qt = blockIdx.x, nb = blockIdx.y;
    const int b = blockIdx.z / HH, h = blockIdx.z % HH;

    const int kr = tid >> 2;
    const int kch0 = (tid & 3) * 2;
    const uint32_t kro = kr * 128;

    auto load_kv = [&](int kt, int buf) {
        int jg = kt * 64 + kr;
        int jc = jg > 512 ? 512 : jg;
        const __half *kh_s, *vh_s;
        if (jc == 0) {
            size_t rb = (size_t)b * (3*CC) + h * HD;
            kh_s = qkvch + rb + CC;
            vh_s = qkvch + rb + 2*CC;
        } else {
            int token = nb * SPB + jc;
            size_t rb = (size_t)(b * NN + token) * (3*CC) + h * HD;
            kh_s = qkvh + rb + CC;
            vh_s = qkvh + rb + 2*CC;
        }
        uint32_t bk = smb + BKV + buf * 16384;
        uint32_t bv = bk + 8192;
        #pragma unroll
        for (int c = 0; c < 2; c++) {
            int chunk = kch0 + c;
            uint32_t sw = kro + (uint32_t)((chunk ^ (kr & 7)) << 4);
            cp16(bk + sw, kh_s + chunk*8);
            cp16(bv + sw, vh_s + chunk*8);
        }
        cp_commit();
    };

    {
        int qrow = tid >> 1;
        int ch0 = (tid & 1) * 4;
        int token = 1 + nb * SPB + qt * 128 + qrow;
        const __half* gh = qkvh + (size_t)(b * NN + token) * (3*CC) + h * HD;
        uint32_t ro = qrow * 128;
        #pragma unroll
        for (int c = 0; c < 4; c++) {
            int chunk = ch0 + c;
            uint32_t sw = ro + (uint32_t)((chunk ^ (qrow & 7)) << 4);
            cp16(smb + BQ + sw, gh + chunk*8);
        }
        cp_commit();
    }
    load_kv(0, 0);
    load_kv(1, 1);

    float m0 = -1e30f, m1 = -1e30f, l0 = 0.0f, l1 = 0.0f;
    float oreg[8][4];
    #pragma unroll
    for (int i = 0; i < 8; i++)
        #pragma unroll
        for (int t = 0; t < 4; t++) oreg[i][t] = 0.0f;

    for (int kt = 0; kt < 9; kt++) {
        if (kt < 8) cp_wait<1>(); else cp_wait<0>();
        __syncthreads();
        if (kt + 2 < 9) load_kv(kt + 2, (kt + 2) % 3);

        uint32_t bk = smb + BKV + (kt % 3) * 16384;
        uint32_t bv = bk + 8192;

        float sreg[8][4];
        #pragma unroll
        for (int i = 0; i < 8; i++)
            #pragma unroll
            for (int t = 0; t < 4; t++) sreg[i][t] = 0.0f;

        #pragma unroll
        for (int kk = 0; kk < 4; kk++) {
            int arow = wid*16 + ((sub & 1) << 3) + r8;
            uint32_t aad = smb + BQ + arow*128
                         + (uint32_t)(((kk*2 + (sub >> 1)) ^ (arow & 7)) << 4);
            uint32_t qh[4];
            ldsm4(aad, qh[0], qh[1], qh[2], qh[3]);
            #pragma unroll
            for (int pr = 0; pr < 4; pr++) {
                int brow = pr*16 + ((sub >> 1) << 3) + r8;
                uint32_t bad = bk + brow*128
                             + (uint32_t)(((kk*2 + (sub & 1)) ^ (brow & 7)) << 4);
                uint32_t kh[4];
                ldsm4(bad, kh[0], kh[1], kh[2], kh[3]);
                mma16816(sreg[pr*2    ], qh, &kh[0]);
                mma16816(sreg[pr*2 + 1], qh, &kh[2]);
            }
        }

        // ---- scale (log2 domain) + mask ----
        #pragma unroll
        for (int nt = 0; nt < 8; nt++)
            #pragma unroll
            for (int t = 0; t < 4; t++) {
                float v = sreg[nt][t] * SCALE2;
                int gcol = kt*64 + nt*8 + (lane & 3)*2 + (t & 1);
                if (gcol > 512) v = -1e30f;
                sreg[nt][t] = v;
            }

        float mt0 = -1e30f, mt1 = -1e30f;
        #pragma unroll
        for (int nt = 0; nt < 8; nt++) {
            mt0 = fmaxf(mt0, fmaxf(sreg[nt][0], sreg[nt][1]));
            mt1 = fmaxf(mt1, fmaxf(sreg[nt][2], sreg[nt][3]));
        }
        mt0 = fmaxf(mt0, __shfl_xor_sync(0xffffffffu, mt0, 1));
        mt0 = fmaxf(mt0, __shfl_xor_sync(0xffffffffu, mt0, 2));
        mt1 = fmaxf(mt1, __shfl_xor_sync(0xffffffffu, mt1, 1));
        mt1 = fmaxf(mt1, __shfl_xor_sync(0xffffffffu, mt1, 2));
        float mn0 = fmaxf(m0, mt0), mn1 = fmaxf(m1, mt1);
        float a0 = exp2f(m0 - mn0), a1 = exp2f(m1 - mn1);
        m0 = mn0; m1 = mn1;
        float rs0 = 0.0f, rs1 = 0.0f;
        #pragma unroll
        for (int nt = 0; nt < 8; nt++) {
            sreg[nt][0] = exp2f(sreg[nt][0] - mn0);
            sreg[nt][1] = exp2f(sreg[nt][1] - mn0);
            sreg[nt][2] = exp2f(sreg[nt][2] - mn1);
            sreg[nt][3] = exp2f(sreg[nt][3] - mn1);
            rs0 += sreg[nt][0] + sreg[nt][1];
            rs1 += sreg[nt][2] + sreg[nt][3];
        }
        rs0 += __shfl_xor_sync(0xffffffffu, rs0, 1);
        rs0 += __shfl_xor_sync(0xffffffffu, rs0, 2);
        rs1 += __shfl_xor_sync(0xffffffffu, rs1, 1);
        rs1 += __shfl_xor_sync(0xffffffffu, rs1, 2);
        l0 = l0 * a0 + rs0;
        l1 = l1 * a1 + rs1;
        #pragma unroll
        for (int dt = 0; dt < 8; dt++) {
            oreg[dt][0] *= a0; oreg[dt][1] *= a0;
            oreg[dt][2] *= a1; oreg[dt][3] *= a1;
        }

        uint32_t ph[4][4];
        #pragma unroll
        for (int kc = 0; kc < 4; kc++) {
            ph[kc][0] = pack2h(sreg[2*kc][0],   sreg[2*kc][1]);
            ph[kc][1] = pack2h(sreg[2*kc][2],   sreg[2*kc][3]);
            ph[kc][2] = pack2h(sreg[2*kc+1][0], sreg[2*kc+1][1]);
            ph[kc][3] = pack2h(sreg[2*kc+1][2], sreg[2*kc+1][3]);
        }

        #pragma unroll
        for (int kc = 0; kc < 4; kc++) {
            #pragma unroll
            for (int dg = 0; dg < 4; dg++) {
                int vrow = kc*16 + ((sub & 1) << 3) + r8;
                uint32_t vad = bv + vrow*128
                             + (uint32_t)(((dg*2 + (sub >> 1)) ^ (vrow & 7)) << 4);
                uint32_t vh[4];
                ldsm4t(vad, vh[0], vh[1], vh[2], vh[3]);
                mma16816(oreg[dg*2    ], ph[kc], &vh[0]);
                mma16816(oreg[dg*2 + 1], ph[kc], &vh[2]);
            }
        }
    }

    float inv0 = 1.0f / l0, inv1 = 1.0f / l1;
    int r4 = lane >> 2, c2 = (lane & 3) * 2;
    #pragma unroll
    for (int dt = 0; dt < 8; dt++) {
        #pragma unroll
        for (int t = 0; t < 4; t++) {
            int rh = t >> 1;
            int sp = qt*128 + wid*16 + r4 + rh*8;
            int dp = dt*8 + c2 + (t & 1);
            float v = oreg[dt][t] * (rh ? inv1 : inv0);
            int linear = h * (SPB * HD) + sp * HD + dp;
            int s_ = linear / CC;
            int c = linear - s_ * CC;
            int token = 1 + nb * SPB + s_;
            yh[(size_t)(b * NN + token) * CC + c] = __float2half_rn(v);
        }
    }
}

// ---------------- launch ----------------
extern "C" void kernel_launch(void* const* d_in, const int* in_sizes, int n_in,
                              void* d_out, int out_size)
{
    const float* x      = (const float*)d_in[0];
    const float* ln1_w  = (const float*)d_in[1];
    const float* ln1_b  = (const float*)d_in[2];
    const float* qkv_w  = (const float*)d_in[3];
    const float* proj_w = (const float*)d_in[4];
    const float* proj_b = (const float*)d_in[5];
    const float* ln2_w  = (const float*)d_in[6];
    const float* ln2_b  = (const float*)d_in[7];
    const float* fc1_w  = (const float*)d_in[8];
    const float* fc1_b  = (const float*)d_in[9];
    const float* fc2_w  = (const float*)d_in[10];
    const float* fc2_b  = (const float*)d_in[11];
    float* out = (float*)d_out;

    float *h1f, *qkvc, *cls, *clsp, *x2;
    __half *h1h, *qkvh, *qkvch, *yh, *h2h, *f1h;
    __half *wqh, *wph, *w1h, *w2h;
    cudaGetSymbolAddress((void**)&h1f,   g_h1f);
    cudaGetSymbolAddress((void**)&h1h,   g_h1h);
    cudaGetSymbolAddress((void**)&qkvh,  g_qkvh);
    cudaGetSymbolAddress((void**)&qkvc,  g_qkvc);
    cudaGetSymbolAddress((void**)&qkvch, g_qkvch);
    cudaGetSymbolAddress((void**)&cls,   g_cls);
    cudaGetSymbolAddress((void**)&clsp,  g_clsp);
    cudaGetSymbolAddress((void**)&yh,    g_yh);
    cudaGetSymbolAddress((void**)&x2,    g_x2);
    cudaGetSymbolAddress((void**)&h2h,   g_h2h);
    cudaGetSymbolAddress((void**)&f1h,   g_f1h);
    cudaGetSymbolAddress((void**)&wqh,   g_wqh);
    cudaGetSymbolAddress((void**)&wph,   g_wph);
    cudaGetSymbolAddress((void**)&w1h,   g_w1h);
    cudaGetSymbolAddress((void**)&w2h,   g_w2h);

    const int M = MROWS;
    const int smem1 = NSTAGE * 2 * TILE_B + 128;   // 98432
    cudaFuncSetAttribute(tc_gemm<0,3>, cudaFuncAttributeMaxDynamicSharedMemorySize, smem1);
    cudaFuncSetAttribute(tc_gemm<1,0>, cudaFuncAttributeMaxDynamicSharedMemorySize, smem1);
    cudaFuncSetAttribute(tc_gemm<2,3>, cudaFuncAttributeMaxDynamicSharedMemorySize, smem1);
    const int ba_smem = 16384 + 3*16384 + 128;
    cudaFuncSetAttribute(branch_attn_kernel, cudaFuncAttributeMaxDynamicSharedMemorySize, ba_smem);

    // 0+1. prologue: LN1 blocks + all weight converts, ONE launch
    {
        int ln_blocks = (M + 7) / 8;               // 2049
        int nb0 = 3*CC*CC/4/256;                   // 1728
        int nb1 = CC*CC/4/256;                     // 576
        int nb2 = 4*CC*CC/4/256;                   // 2304
        int nb3 = nb2;
        int c1 = nb0, c2 = nb0+nb1, c3 = nb0+nb1+nb2;
        prologue_kernel<<<ln_blocks + c3 + nb3, 256>>>(
            x, ln1_w, ln1_b, h1f, h1h, ln_blocks,
            qkv_w, proj_w, fc1_w, fc2_w, wqh, wph, w1h, w2h, c1, c2, c3);
    }

    // 2. qkv = h1 @ qkv_w^T  (fp16 out)
    {
        dim3 grid((3*CC)/128, MPAD/128);
        tc_gemm<0,3><<<grid, 256, smem1>>>(h1h, wqh, nullptr, nullptr,
                                           nullptr, qkvh, M, 3*CC, CC);
    }

    // 3. cls global attention (split-K partials + reduce)
    {
        dim3 grid(BB*HH, NSPLIT);
        cls_attn_part<<<grid, 256>>>(qkvh, clsp);
        cls_attn_reduce<<<BB*HH, 64>>>(clsp, h1f, cls, yh);
    }

    // 4. cls qkv
    cls_qkv_kernel<<<3*CC, 256>>>(cls, qkv_w, qkvc, qkvch);

    // 5. branch attention (128-query tiles)
    {
        dim3 grid(4, NBB, BB*HH);
        branch_attn_kernel<<<grid, 256, ba_smem>>>(qkvh, qkvch, yh);
    }

    // 6. x2 = x + y @ proj_w^T + proj_b
    {
        dim3 grid(CC/128, MPAD/128);
        tc_gemm<1,0><<<grid, 256, smem1>>>(yh, wph, proj_b, x,
                                           x2, nullptr, M, CC, CC);
    }

    // 7. LN2 (fp16 out)
    ln_kernel<<<(M + 7)/8, 256>>>(x2, ln2_w, ln2_b, h2h, M);

    // 8. fc1 + gelu (fp16 out)
    {
        dim3 grid((4*CC)/128, MPAD/128);
        tc_gemm<2,3><<<grid, 256, smem1>>>(h2h, w1h, fc1_b, nullptr,
                                           nullptr, f1h, M, 4*CC, CC);
    }

    // 9. out = x2 + fc1g @ fc2_w^T + fc2_b
    {
        dim3 grid(CC/128, MPAD/128);
        tc_gemm<1,0><<<grid, 256, smem1>>>(f1h, w2h, fc2_b, x2,
                                           out, nullptr, M, CC, 4*CC);
    }
}

// round 14
// speedup vs baseline: 6.0559x; 1.1505x over previous
#include <cuda_runtime.h>
#include <cuda_fp16.h>
#include <math.h>
#include <stdint.h>

// ---------------- problem constants ----------------
#define BB   8
#define NN   2049
#define CC   768
#define HH   12
#define NBB  4
#define HD   64
#define SPB  512
#define MROWS (BB*NN)      // 16392
#define MPAD  16512        // 129 * 128
#define SCALE 0.125f
#define SCALE2 0.18033688011112042f   // SCALE * log2(e)
#define LNEPS 1e-6f
#define NSPLIT 16
#define CHUNK 129          // ceil(2049/16)

// ---------------- scratch ----------------
__device__ float g_h1f [(size_t)MROWS * CC];       // only cls rows written/read
__device__ __half g_h1h[(size_t)MPAD * CC];
__device__ __half g_qkvh[(size_t)MROWS * 3 * CC];
__device__ __half g_qkvch[BB * 3 * CC];
__device__ float g_cls [BB * CC];
__device__ float g_clsp[BB * HH * NSPLIT * 80];    // partial m,l,o[64]
__device__ __half g_yh [(size_t)MPAD * CC];
__device__ float g_x2  [(size_t)MROWS * CC];
__device__ __half g_h2h[(size_t)MPAD * CC];
__device__ __half g_f1h[(size_t)MPAD * 4 * CC];
__device__ __half g_wqh[3*CC*CC];
__device__ __half g_wph[CC*CC];
__device__ __half g_w1h[4*CC*CC];
__device__ __half g_w2h[4*CC*CC];

// ---------------- helpers ----------------
__device__ __forceinline__ uint32_t smem_u32(const void* p) {
    return (uint32_t)__cvta_generic_to_shared(p);
}
__device__ __forceinline__ void cp16(uint32_t saddr, const void* g) {
    asm volatile("cp.async.cg.shared.global [%0], [%1], 16;\n" :: "r"(saddr), "l"(g));
}
__device__ __forceinline__ void cp_commit() { asm volatile("cp.async.commit_group;\n"); }
template<int NW> __device__ __forceinline__ void cp_wait() {
    asm volatile("cp.async.wait_group %0;\n" :: "n"(NW));
}
__device__ __forceinline__ void ldsm4(uint32_t addr, uint32_t& r0, uint32_t& r1,
                                      uint32_t& r2, uint32_t& r3) {
    asm volatile("ldmatrix.sync.aligned.m8n8.x4.shared.b16 {%0,%1,%2,%3}, [%4];"
                 : "=r"(r0), "=r"(r1), "=r"(r2), "=r"(r3) : "r"(addr));
}
__device__ __forceinline__ void ldsm4t(uint32_t addr, uint32_t& r0, uint32_t& r1,
                                       uint32_t& r2, uint32_t& r3) {
    asm volatile("ldmatrix.sync.aligned.m8n8.x4.trans.shared.b16 {%0,%1,%2,%3}, [%4];"
                 : "=r"(r0), "=r"(r1), "=r"(r2), "=r"(r3) : "r"(addr));
}
__device__ __forceinline__ void mma16816(float* c, const uint32_t* a, const uint32_t* b) {
    asm volatile("mma.sync.aligned.m16n8k16.row.col.f32.f16.f16.f32 "
        "{%0,%1,%2,%3}, {%4,%5,%6,%7}, {%8,%9}, {%0,%1,%2,%3};"
        : "+f"(c[0]), "+f"(c[1]), "+f"(c[2]), "+f"(c[3])
        : "r"(a[0]), "r"(a[1]), "r"(a[2]), "r"(a[3]), "r"(b[0]), "r"(b[1]));
}
__device__ __forceinline__ uint32_t pack2h(float a, float b) {
    __half2 h = __float22half2_rn(make_float2(a, b));
    return *(uint32_t*)&h;
}

// ---------------- LN row body (warp-collective) ----------------
__device__ __forceinline__ void ln_row(const float* __restrict__ x,
                                       const float* __restrict__ w,
                                       const float* __restrict__ b,
                                       float* __restrict__ outf,
                                       __half* __restrict__ oh,
                                       int row, int lane)
{
    const float4* xr = (const float4*)(x + (size_t)row * CC);

    float4 v[6];
    float s = 0.0f;
    #pragma unroll
    for (int i = 0; i < 6; i++) {
        v[i] = xr[i * 32 + lane];
        s += v[i].x + v[i].y + v[i].z + v[i].w;
    }
    #pragma unroll
    for (int o = 16; o; o >>= 1) s += __shfl_xor_sync(0xffffffffu, s, o);
    float mu = s * (1.0f / CC);

    float q = 0.0f;
    #pragma unroll
    for (int i = 0; i < 6; i++) {
        v[i].x -= mu; v[i].y -= mu; v[i].z -= mu; v[i].w -= mu;
        q += v[i].x*v[i].x + v[i].y*v[i].y + v[i].z*v[i].z + v[i].w*v[i].w;
    }
    #pragma unroll
    for (int o = 16; o; o >>= 1) q += __shfl_xor_sync(0xffffffffu, q, o);
    float rs = rsqrtf(q * (1.0f / CC) + LNEPS);

    const float4* w4 = (const float4*)w;
    const float4* b4 = (const float4*)b;
    uint2* oh2 = (uint2*)(oh + (size_t)row * CC);
    bool wf = (outf != nullptr) && (row % NN) == 0;
    float4* of4 = wf ? (float4*)(outf + (size_t)row * CC) : nullptr;

    #pragma unroll
    for (int i = 0; i < 6; i++) {
        float4 wv = w4[i * 32 + lane], bv = b4[i * 32 + lane];
        float o0 = v[i].x * rs * wv.x + bv.x;
        float o1 = v[i].y * rs * wv.y + bv.y;
        float o2 = v[i].z * rs * wv.z + bv.z;
        float o3 = v[i].w * rs * wv.w + bv.w;
        oh2[i * 32 + lane] = make_uint2(pack2h(o0, o1), pack2h(o2, o3));
        if (wf) of4[i * 32 + lane] = make_float4(o0, o1, o2, o3);
    }
}

// ---------------- prologue: LN1 blocks + weight-convert blocks in ONE launch ---
__global__ void __launch_bounds__(256) prologue_kernel(
    const float* __restrict__ x, const float* __restrict__ ln1_w,
    const float* __restrict__ ln1_b, float* __restrict__ h1f,
    __half* __restrict__ h1h, int ln_blocks,
    const float* __restrict__ i0, const float* __restrict__ i1,
    const float* __restrict__ i2, const float* __restrict__ i3,
    __half* __restrict__ o0, __half* __restrict__ o1,
    __half* __restrict__ o2, __half* __restrict__ o3,
    int c1, int c2, int c3)
{
    int bi = blockIdx.x;
    if (bi < ln_blocks) {
        int row = bi * 8 + (threadIdx.x >> 5);
        if (row < MROWS)
            ln_row(x, ln1_w, ln1_b, h1f, h1h, row, threadIdx.x & 31);
    } else {
        int cb = bi - ln_blocks;
        const float* in; __half* oh; int base;
        if (cb < c1)      { in = i0; oh = o0; base = 0;  }
        else if (cb < c2) { in = i1; oh = o1; base = c1; }
        else if (cb < c3) { in = i2; oh = o2; base = c2; }
        else              { in = i3; oh = o3; base = c3; }
        int i = (cb - base) * 256 + threadIdx.x;
        float4 v = ((const float4*)in)[i];
        uint2 o;
        o.x = pack2h(v.x, v.y);
        o.y = pack2h(v.z, v.w);
        ((uint2*)oh)[i] = o;
    }
}

// ---------------- LN2 (standalone) ----------------
__global__ void __launch_bounds__(256) ln_kernel(const float* __restrict__ x,
                                                 const float* __restrict__ w,
                                                 const float* __restrict__ b,
                                                 __half* __restrict__ oh,
                                                 int rows)
{
    int row = blockIdx.x * 8 + (threadIdx.x >> 5);
    if (row >= rows) return;
    ln_row(x, w, b, nullptr, oh, row, threadIdx.x & 31);
}

// ================= single-pass fp16 mma.sync GEMM =================
#define TILE_B   16384
#define NSTAGE   3

template<int EPI, int OUTM>
__global__ void __launch_bounds__(256, 2) tc_gemm(
    const __half* __restrict__ Ah, const __half* __restrict__ Wh,
    const float* __restrict__ bias, const float* __restrict__ res,
    float* __restrict__ Cf, __half* __restrict__ Ch,
    int M, int N, int K)
{
    constexpr uint32_t STB = 2 * TILE_B;

    extern __shared__ char dynraw[];
    uint32_t raw = smem_u32(dynraw);
    uint32_t smb = (raw + 127) & ~127u;

    const int tid = threadIdx.x;
    const int bn = blockIdx.x * 128, bm = blockIdx.y * 128;
    const int nt = K >> 6;
    const int lane = tid & 31, wid = tid >> 5;
    const int wm = (wid & 1) * 64, wn = (wid >> 1) * 32;
    const int r8 = lane & 7, sub = lane >> 3;

    const int lrow = tid >> 1;
    const int c0 = (tid & 1) * 4;

    auto load_stage = [&](int kt, int s) {
        uint32_t sb = smb + s * STB;
        size_t goff = (size_t)(kt * 64 + c0 * 8);
        const __half* gAh = Ah + (size_t)(bm + lrow) * K + goff;
        const __half* gWh = Wh + (size_t)(bn + lrow) * K + goff;
        uint32_t ro = lrow * 128;
        #pragma unroll
        for (int c = 0; c < 4; c++) {
            int chunk = c0 + c;
            uint32_t sw = ro + (uint32_t)((chunk ^ (lrow & 7)) << 4);
            cp16(sb          + sw, gAh + c*8);
            cp16(sb + TILE_B + sw, gWh + c*8);
        }
        cp_commit();
    };

    float acc[4][4][4];
    #pragma unroll
    for (int i = 0; i < 4; i++)
        #pragma unroll
        for (int j = 0; j < 4; j++)
            #pragma unroll
            for (int t = 0; t < 4; t++) acc[i][j][t] = 0.0f;

    uint32_t aRowBase[4]; int aKey[4];
    #pragma unroll
    for (int mi = 0; mi < 4; mi++) {
        int row = wm + mi*16 + ((sub & 1) << 3) + r8;
        aRowBase[mi] = row * 128;
        aKey[mi] = row & 7;
    }
    const int aChunkOff = sub >> 1;
    uint32_t bRowBase[2]; int bKey[2];
    #pragma unroll
    for (int pr = 0; pr < 2; pr++) {
        int row = wn + pr*16 + ((sub >> 1) << 3) + r8;
        bRowBase[pr] = row * 128;
        bKey[pr] = row & 7;
    }
    const int bChunkOff = sub & 1;

    load_stage(0, 0);
    load_stage(1, 1);

    for (int kt = 0; kt < nt; kt++) {
        if (kt + 1 < nt) cp_wait<1>(); else cp_wait<0>();
        __syncthreads();
        if (kt + 2 < nt) load_stage(kt + 2, (kt + 2) % NSTAGE);

        uint32_t sb = smb + (kt % NSTAGE) * STB;

        #pragma unroll
        for (int kk = 0; kk < 4; kk++) {
            uint32_t Bh[2][4];
            #pragma unroll
            for (int pr = 0; pr < 2; pr++) {
                int chunk = kk*2 + bChunkOff;
                uint32_t ad = sb + TILE_B + bRowBase[pr]
                            + (uint32_t)((chunk ^ bKey[pr]) << 4);
                ldsm4(ad, Bh[pr][0], Bh[pr][1], Bh[pr][2], Bh[pr][3]);
            }
            #pragma unroll
            for (int mi = 0; mi < 4; mi++) {
                int chunk = kk*2 + aChunkOff;
                uint32_t ad = sb + aRowBase[mi]
                            + (uint32_t)((chunk ^ aKey[mi]) << 4);
                uint32_t Af[4];
                ldsm4(ad, Af[0], Af[1], Af[2], Af[3]);
                #pragma unroll
                for (int ni = 0; ni < 4; ni++) {
                    int pr = ni >> 1, half = (ni & 1) * 2;
                    mma16816(acc[mi][ni], Af, &Bh[pr][half]);
                }
            }
        }
    }

    // ---- epilogue: vectorized (float2 / half2) ----
    int r4 = lane >> 2, c2 = (lane & 3) * 2;
    #pragma unroll
    for (int mi = 0; mi < 4; mi++) {
        #pragma unroll
        for (int hh = 0; hh < 2; hh++) {
            int m = bm + wm + mi*16 + r4 + hh*8;
            if (m >= M) continue;
            #pragma unroll
            for (int ni = 0; ni < 4; ni++) {
                int n0 = bn + wn + ni*8 + c2;
                float v0 = acc[mi][ni][hh*2 + 0];
                float v1 = acc[mi][ni][hh*2 + 1];
                size_t idx = (size_t)m * N + n0;
                if (EPI != 0) {
                    float2 bb = *(const float2*)&bias[n0];
                    v0 += bb.x; v1 += bb.y;
                }
                if (EPI == 1) {
                    float2 rr = *(const float2*)&res[idx];
                    v0 += rr.x; v1 += rr.y;
                }
                if (EPI == 2) {
                    v0 = 0.5f * v0 * (1.0f + erff(v0 * 0.7071067811865476f));
                    v1 = 0.5f * v1 * (1.0f + erff(v1 * 0.7071067811865476f));
                }
                if (OUTM == 0) *(float2*)&Cf[idx] = make_float2(v0, v1);
                else           *(uint32_t*)&Ch[idx] = pack2h(v0, v1);
            }
        }
    }
}

// ---------------- cls attention, split-K partials (coalesced QK, exp2 domain) ---
__global__ void __launch_bounds__(256) cls_attn_part(const __half* __restrict__ qkvh,
                                                     float* __restrict__ part)
{
    __shared__ float sq[64];
    __shared__ float sc[CHUNK];
    __shared__ float red[256];
    __shared__ float so[4][64];

    int bh = blockIdx.x, sp = blockIdx.y;
    int b = bh / HH, h = bh % HH;
    int tid = threadIdx.x;
    int lane = tid & 31, wid = tid >> 5;
    int i0 = sp * CHUNK;
    int i1 = i0 + CHUNK; if (i1 > NN) i1 = NN;
    int cnt = i1 - i0;

    const __half* qbase = qkvh + (size_t)(b * NN) * (3*CC) + h * HD;
    if (tid < 64) sq[tid] = __half2float(qbase[tid]);
    __syncthreads();

    const int g = lane >> 3;
    const int s8 = lane & 7;
    float qf[8];
    #pragma unroll
    for (int i = 0; i < 8; i++) qf[i] = sq[s8 * 8 + i];

    float lmax = -1e30f;
    for (int base = 0; base < cnt; base += 32) {
        int j = base + wid * 4 + g;
        float dot = 0.0f;
        if (j < cnt) {
            const uint4* kr = (const uint4*)(qkvh + (size_t)(b * NN + i0 + j) * (3*CC) + CC + h * HD);
            uint4 kv = kr[s8];
            __half2 h0 = *(__half2*)&kv.x, h1v = *(__half2*)&kv.y;
            __half2 h2 = *(__half2*)&kv.z, h3 = *(__half2*)&kv.w;
            float2 f0 = __half22float2(h0), f1 = __half22float2(h1v);
            float2 f2 = __half22float2(h2), f3 = __half22float2(h3);
            dot = qf[0]*f0.x + qf[1]*f0.y + qf[2]*f1.x + qf[3]*f1.y
                + qf[4]*f2.x + qf[5]*f2.y + qf[6]*f3.x + qf[7]*f3.y;
        }
        dot += __shfl_xor_sync(0xffffffffu, dot, 1);
        dot += __shfl_xor_sync(0xffffffffu, dot, 2);
        dot += __shfl_xor_sync(0xffffffffu, dot, 4);
        if (s8 == 0 && j < cnt) {
            float sv = dot * SCALE2;
            sc[j] = sv;
            lmax = fmaxf(lmax, sv);
        }
    }
    red[tid] = lmax; __syncthreads();
    for (int off = 128; off; off >>= 1) {
        if (tid < off) red[tid] = fmaxf(red[tid], red[tid + off]);
        __syncthreads();
    }
    float m = red[0];
    __syncthreads();

    float lsum = 0.0f;
    for (int j = tid; j < cnt; j += 256) {
        float e = exp2f(sc[j] - m);
        sc[j] = e;
        lsum += e;
    }
    red[tid] = lsum; __syncthreads();
    for (int off = 128; off; off >>= 1) {
        if (tid < off) red[tid] += red[tid + off];
        __syncthreads();
    }
    float l = red[0];
    __syncthreads();

    int d = tid & 63, p = tid >> 6;
    float o = 0.0f;
    for (int j = p; j < cnt; j += 4)
        o = fmaf(sc[j], __half2float(qkvh[(size_t)(b * NN + i0 + j) * (3*CC) + 2*CC + h * HD + d]), o);
    so[p][d] = o;
    __syncthreads();

    float* pr = part + (size_t)(bh * NSPLIT + sp) * 80;
    if (tid == 0) { pr[0] = m; pr[1] = l; }
    if (tid < 64) pr[2 + tid] = so[0][tid] + so[1][tid] + so[2][tid] + so[3][tid];
}

// ---------------- cls attention reduce (exp2 domain) ----------------
__global__ void __launch_bounds__(64) cls_attn_reduce(const float* __restrict__ part,
                                                      const float* __restrict__ h1,
                                                      float* __restrict__ cls,
                                                      __half* __restrict__ yh)
{
    int bh = blockIdx.x;
    int b = bh / HH, h = bh % HH;
    int d = threadIdx.x;

    const float* pr = part + (size_t)bh * NSPLIT * 80;
    float m = -1e30f;
    #pragma unroll
    for (int s = 0; s < NSPLIT; s++) m = fmaxf(m, pr[s*80]);
    float l = 0.0f, o = 0.0f;
    #pragma unroll
    for (int s = 0; s < NSPLIT; s++) {
        float w = exp2f(pr[s*80] - m);
        l += w * pr[s*80 + 1];
        o += w * pr[s*80 + 2 + d];
    }
    float val = o / l;
    size_t off0 = (size_t)(b * NN) * CC + h * HD + d;
    float v = val + h1[off0];
    cls[b * CC + h * HD + d] = v;
    yh[off0] = __float2half_rn(v);
}

// ---------------- cls qkv (fp16 weights, vectorized) ----------------
__global__ void __launch_bounds__(256) cls_qkv_kernel(const float* __restrict__ cls,
                                                      const __half* __restrict__ wqh,
                                                      __half* __restrict__ qkvch)
{
    int j = blockIdx.x;
    int w = threadIdx.x >> 5;
    int lane = threadIdx.x & 31;
    const float2* cr = (const float2*)(cls + (size_t)w * CC);
    const __half2* wr = (const __half2*)(wqh + (size_t)j * CC);
    float s = 0.0f;
    #pragma unroll 4
    for (int k = lane; k < CC/2; k += 32) {
        float2 c = cr[k];
        float2 wv = __half22float2(wr[k]);
        s = fmaf(c.x, wv.x, s);
        s = fmaf(c.y, wv.y, s);
    }
    #pragma unroll
    for (int off = 16; off; off >>= 1) s += __shfl_xor_sync(0xffffffffu, s, off);
    if (lane == 0) qkvch[w * (3*CC) + j] = __float2half_rn(s);
}

// ---------------- branch attention: 128-query tiles, 8 warps, 3-buffer KV ring ----
#define BQ   0
#define BKV  16384

__global__ void __launch_bounds__(256) branch_attn_kernel(
    const __half* __restrict__ qkvh, const __half* __restrict__ qkvch,
    __half* __restrict__ yh)
{
    extern __shared__ char dynraw[];
    uint32_t raw = smem_u32(dynraw);
    uint32_t smb = (raw + 127) & ~127u;

    const int tid = threadIdx.x;
    const int lane = tid & 31, wid = tid >> 5;
    const int r8 = lane & 7, sub = lane >> 3;
    const int qt = blockIdx.x, nb = blockIdx.y;
    const int b = blockIdx.z / HH, h = blockIdx.z % HH;

    const int kr = tid >> 2;
    const int kch0 = (tid & 3) * 2;
    const uint32_t kro = kr * 128;

    auto load_kv = [&](int kt, int buf) {
        int jg = kt * 64 + kr;
        int jc = jg > 512 ? 512 : jg;
        const __half *kh_s, *vh_s;
        if (jc == 0) {
            size_t rb = (size_t)b * (3*CC) + h * HD;
            kh_s = qkvch + rb + CC;
            vh_s = qkvch + rb + 2*CC;
        } else {
            int token = nb * SPB + jc;
            size_t rb = (size_t)(b * NN + token) * (3*CC) + h * HD;
            kh_s = qkvh + rb + CC;
            vh_s = qkvh + rb + 2*CC;
        }
        uint32_t bk = smb + BKV + buf * 16384;
        uint32_t bv = bk + 8192;
        #pragma unroll
        for (int c = 0; c < 2; c++) {
            int chunk = kch0 + c;
            uint32_t sw = kro + (uint32_t)((chunk ^ (kr & 7)) << 4);
            cp16(bk + sw, kh_s + chunk*8);
            cp16(bv + sw, vh_s + chunk*8);
        }
        cp_commit();
    };

    {
        int qrow = tid >> 1;
        int ch0 = (tid & 1) * 4;
        int token = 1 + nb * SPB + qt * 128 + qrow;
        const __half* gh = qkvh + (size_t)(b * NN + token) * (3*CC) + h * HD;
        uint32_t ro = qrow * 128;
        #pragma unroll
        for (int c = 0; c < 4; c++) {
            int chunk = ch0 + c;
            uint32_t sw = ro + (uint32_t)((chunk ^ (qrow & 7)) << 4);
            cp16(smb + BQ + sw, gh + chunk*8);
        }
        cp_commit();
    }
    load_kv(0, 0);
    load_kv(1, 1);

    float m0 = -1e30f, m1 = -1e30f, l0 = 0.0f, l1 = 0.0f;
    float oreg[8][4];
    #pragma unroll
    for (int i = 0; i < 8; i++)
        #pragma unroll
        for (int t = 0; t < 4; t++) oreg[i][t] = 0.0f;

    for (int kt = 0; kt < 9; kt++) {
        if (kt < 8) cp_wait<1>(); else cp_wait<0>();
        __syncthreads();
        if (kt + 2 < 9) load_kv(kt + 2, (kt + 2) % 3);

        uint32_t bk = smb + BKV + (kt % 3) * 16384;
        uint32_t bv = bk + 8192;

        float sreg[8][4];
        #pragma unroll
        for (int i = 0; i < 8; i++)
            #pragma unroll
            for (int t = 0; t < 4; t++) sreg[i][t] = 0.0f;

        #pragma unroll
        for (int kk = 0; kk < 4; kk++) {
            int arow = wid*16 + ((sub & 1) << 3) + r8;
            uint32_t aad = smb + BQ + arow*128
                         + (uint32_t)(((kk*2 + (sub >> 1)) ^ (arow & 7)) << 4);
            uint32_t qh[4];
            ldsm4(aad, qh[0], qh[1], qh[2], qh[3]);
            #pragma unroll
            for (int pr = 0; pr < 4; pr++) {
                int brow = pr*16 + ((sub >> 1) << 3) + r8;
                uint32_t bad = bk + brow*128
                             + (uint32_t)(((kk*2 + (sub & 1)) ^ (brow & 7)) << 4);
                uint32_t kh[4];
                ldsm4(bad, kh[0], kh[1], kh[2], kh[3]);
                mma16816(sreg[pr*2    ], qh, &kh[0]);
                mma16816(sreg[pr*2 + 1], qh, &kh[2]);
            }
        }

        #pragma unroll
        for (int nt = 0; nt < 8; nt++)
            #pragma unroll
            for (int t = 0; t < 4; t++) {
                float v = sreg[nt][t] * SCALE2;
                int gcol = kt*64 + nt*8 + (lane & 3)*2 + (t & 1);
                if (gcol > 512) v = -1e30f;
                sreg[nt][t] = v;
            }

        float mt0 = -1e30f, mt1 = -1e30f;
        #pragma unroll
        for (int nt = 0; nt < 8; nt++) {
            mt0 = fmaxf(mt0, fmaxf(sreg[nt][0], sreg[nt][1]));
            mt1 = fmaxf(mt1, fmaxf(sreg[nt][2], sreg[nt][3]));
        }
        mt0 = fmaxf(mt0, __shfl_xor_sync(0xffffffffu, mt0, 1));
        mt0 = fmaxf(mt0, __shfl_xor_sync(0xffffffffu, mt0, 2));
        mt1 = fmaxf(mt1, __shfl_xor_sync(0xffffffffu, mt1, 1));
        mt1 = fmaxf(mt1, __shfl_xor_sync(0xffffffffu, mt1, 2));
        float mn0 = fmaxf(m0, mt0), mn1 = fmaxf(m1, mt1);
        float a0 = exp2f(m0 - mn0), a1 = exp2f(m1 - mn1);
        m0 = mn0; m1 = mn1;
        float rs0 = 0.0f, rs1 = 0.0f;
        #pragma unroll
        for (int nt = 0; nt < 8; nt++) {
            sreg[nt][0] = exp2f(sreg[nt][0] - mn0);
            sreg[nt][1] = exp2f(sreg[nt][1] - mn0);
            sreg[nt][2] = exp2f(sreg[nt][2] - mn1);
            sreg[nt][3] = exp2f(sreg[nt][3] - mn1);
            rs0 += sreg[nt][0] + sreg[nt][1];
            rs1 += sreg[nt][2] + sreg[nt][3];
        }
        rs0 += __shfl_xor_sync(0xffffffffu, rs0, 1);
        rs0 += __shfl_xor_sync(0xffffffffu, rs0, 2);
        rs1 += __shfl_xor_sync(0xffffffffu, rs1, 1);
        rs1 += __shfl_xor_sync(0xffffffffu, rs1, 2);
        l0 = l0 * a0 + rs0;
        l1 = l1 * a1 + rs1;
        #pragma unroll
        for (int dt = 0; dt < 8; dt++) {
            oreg[dt][0] *= a0; oreg[dt][1] *= a0;
            oreg[dt][2] *= a1; oreg[dt][3] *= a1;
        }

        uint32_t ph[4][4];
        #pragma unroll
        for (int kc = 0; kc < 4; kc++) {
            ph[kc][0] = pack2h(sreg[2*kc][0],   sreg[2*kc][1]);
            ph[kc][1] = pack2h(sreg[2*kc][2],   sreg[2*kc][3]);
            ph[kc][2] = pack2h(sreg[2*kc+1][0], sreg[2*kc+1][1]);
            ph[kc][3] = pack2h(sreg[2*kc+1][2], sreg[2*kc+1][3]);
        }

        #pragma unroll
        for (int kc = 0; kc < 4; kc++) {
            #pragma unroll
            for (int dg = 0; dg < 4; dg++) {
                int vrow = kc*16 + ((sub & 1) << 3) + r8;
                uint32_t vad = bv + vrow*128
                             + (uint32_t)(((dg*2 + (sub >> 1)) ^ (vrow & 7)) << 4);
                uint32_t vh[4];
                ldsm4t(vad, vh[0], vh[1], vh[2], vh[3]);
                mma16816(oreg[dg*2    ], ph[kc], &vh[0]);
                mma16816(oreg[dg*2 + 1], ph[kc], &vh[2]);
            }
        }
    }

    float inv0 = 1.0f / l0, inv1 = 1.0f / l1;
    int r4 = lane >> 2, c2 = (lane & 3) * 2;
    #pragma unroll
    for (int dt = 0; dt < 8; dt++) {
        #pragma unroll
        for (int t = 0; t < 4; t++) {
            int rh = t >> 1;
            int sp = qt*128 + wid*16 + r4 + rh*8;
            int dp = dt*8 + c2 + (t & 1);
            float v = oreg[dt][t] * (rh ? inv1 : inv0);
            int linear = h * (SPB * HD) + sp * HD + dp;
            int s_ = linear / CC;
            int c = linear - s_ * CC;
            int token = 1 + nb * SPB + s_;
            yh[(size_t)(b * NN + token) * CC + c] = __float2half_rn(v);
        }
    }
}

// ---------------- launch ----------------
extern "C" void kernel_launch(void* const* d_in, const int* in_sizes, int n_in,
                              void* d_out, int out_size)
{
    const float* x      = (const float*)d_in[0];
    const float* ln1_w  = (const float*)d_in[1];
    const float* ln1_b  = (const float*)d_in[2];
    const float* qkv_w  = (const float*)d_in[3];
    const float* proj_w = (const float*)d_in[4];
    const float* proj_b = (const float*)d_in[5];
    const float* ln2_w  = (const float*)d_in[6];
    const float* ln2_b  = (const float*)d_in[7];
    const float* fc1_w  = (const float*)d_in[8];
    const float* fc1_b  = (const float*)d_in[9];
    const float* fc2_w  = (const float*)d_in[10];
    const float* fc2_b  = (const float*)d_in[11];
    float* out = (float*)d_out;

    float *h1f, *cls, *clsp, *x2;
    __half *h1h, *qkvh, *qkvch, *yh, *h2h, *f1h;
    __half *wqh, *wph, *w1h, *w2h;
    cudaGetSymbolAddress((void**)&h1f,   g_h1f);
    cudaGetSymbolAddress((void**)&h1h,   g_h1h);
    cudaGetSymbolAddress((void**)&qkvh,  g_qkvh);
    cudaGetSymbolAddress((void**)&qkvch, g_qkvch);
    cudaGetSymbolAddress((void**)&cls,   g_cls);
    cudaGetSymbolAddress((void**)&clsp,  g_clsp);
    cudaGetSymbolAddress((void**)&yh,    g_yh);
    cudaGetSymbolAddress((void**)&x2,    g_x2);
    cudaGetSymbolAddress((void**)&h2h,   g_h2h);
    cudaGetSymbolAddress((void**)&f1h,   g_f1h);
    cudaGetSymbolAddress((void**)&wqh,   g_wqh);
    cudaGetSymbolAddress((void**)&wph,   g_wph);
    cudaGetSymbolAddress((void**)&w1h,   g_w1h);
    cudaGetSymbolAddress((void**)&w2h,   g_w2h);

    const int M = MROWS;
    const int smem1 = NSTAGE * 2 * TILE_B + 128;   // 98432
    cudaFuncSetAttribute(tc_gemm<0,3>, cudaFuncAttributeMaxDynamicSharedMemorySize, smem1);
    cudaFuncSetAttribute(tc_gemm<1,0>, cudaFuncAttributeMaxDynamicSharedMemorySize, smem1);
    cudaFuncSetAttribute(tc_gemm<2,3>, cudaFuncAttributeMaxDynamicSharedMemorySize, smem1);
    const int ba_smem = 16384 + 3*16384 + 128;
    cudaFuncSetAttribute(branch_attn_kernel, cudaFuncAttributeMaxDynamicSharedMemorySize, ba_smem);

    // 0+1. prologue: LN1 blocks + all weight converts, ONE launch
    {
        int ln_blocks = (M + 7) / 8;               // 2049
        int nb0 = 3*CC*CC/4/256;                   // 1728
        int nb1 = CC*CC/4/256;                     // 576
        int nb2 = 4*CC*CC/4/256;                   // 2304
        int nb3 = nb2;
        int c1 = nb0, c2 = nb0+nb1, c3 = nb0+nb1+nb2;
        prologue_kernel<<<ln_blocks + c3 + nb3, 256>>>(
            x, ln1_w, ln1_b, h1f, h1h, ln_blocks,
            qkv_w, proj_w, fc1_w, fc2_w, wqh, wph, w1h, w2h, c1, c2, c3);
    }

    // 2. qkv = h1 @ qkv_w^T  (fp16 out)
    {
        dim3 grid((3*CC)/128, MPAD/128);
        tc_gemm<0,3><<<grid, 256, smem1>>>(h1h, wqh, nullptr, nullptr,
                                           nullptr, qkvh, M, 3*CC, CC);
    }

    // 3. cls global attention (split-K partials + reduce)
    {
        dim3 grid(BB*HH, NSPLIT);
        cls_attn_part<<<grid, 256>>>(qkvh, clsp);
        cls_attn_reduce<<<BB*HH, 64>>>(clsp, h1f, cls, yh);
    }

    // 4. cls qkv (fp16 weights)
    cls_qkv_kernel<<<3*CC, 256>>>(cls, wqh, qkvch);

    // 5. branch attention (128-query tiles)
    {
        dim3 grid(4, NBB, BB*HH);
        branch_attn_kernel<<<grid, 256, ba_smem>>>(qkvh, qkvch, yh);
    }

    // 6. x2 = x + y @ proj_w^T + proj_b
    {
        dim3 grid(CC/128, MPAD/128);
        tc_gemm<1,0><<<grid, 256, smem1>>>(yh, wph, proj_b, x,
                                           x2, nullptr, M, CC, CC);
    }

    // 7. LN2 (fp16 out)
    ln_kernel<<<(M + 7)/8, 256>>>(x2, ln2_w, ln2_b, h2h, M);

    // 8. fc1 + gelu (fp16 out)
    {
        dim3 grid((4*CC)/128, MPAD/128);
        tc_gemm<2,3><<<grid, 256, smem1>>>(h2h, w1h, fc1_b, nullptr,
                                           nullptr, f1h, M, 4*CC, CC);
    }

    // 9. out = x2 + fc1g @ fc2_w^T + fc2_b
    {
        dim3 grid(CC/128, MPAD/128);
        tc_gemm<1,0><<<grid, 256, smem1>>>(f1h, w2h, fc2_b, x2,
                                           out, nullptr, M, CC, 4*CC);
    }
}